// round 8
// baseline (speedup 1.0000x reference)
#include <cuda_runtime.h>
#include <cuda_bf16.h>
#include <math.h>
#include <cstdint>

#define NB 1024
#define ND 256
#define NR 16384
#define NW 64
#define NSPLIT 32
#define EPSF 1e-16f
#define KCAT 768

// ---------------- scratch (no allocations allowed) ----------------
__device__ float g_sim[(size_t)NB * NR];   // beta*sim logits, then a (in place)
__device__ float g_pl [(size_t)NB * NR];   // p logits (raw fp32)
__device__ float g_v  [NB * NW];
__device__ float g_vn [NB];
__device__ float g_beta[NB];
__device__ float g_gamma[NB];
__device__ float g_mn [NR];
__device__ float g_part[(size_t)NSPLIT * NB * NW];
__device__ float g_add[(size_t)NR * NW];
__device__ float g_er [NR];
__device__ float g_pmx [NB];
__device__ float g_pinv[NB];
__device__ __nv_bfloat16 g_xcat[(size_t)NB * KCAT];   // [x_hi | x_lo | x_hi]
__device__ __nv_bfloat16 g_wcat[(size_t)NR * KCAT];   // [W_hi | W_hi | W_lo] (transposed)
__device__ __nv_bfloat16 g_vh  [NB * NW];
__device__ __nv_bfloat16 g_memh[NR * NW];
__device__ __nv_bfloat16 g_m2h[(size_t)NW * NR];      // mem2^T hi  [w][r]
__device__ __nv_bfloat16 g_m2l[(size_t)NW * NR];      // mem2^T lo  [w][r]

__device__ __forceinline__ float softplus_f(float z) {
    return z > 0.f ? z + log1pf(expf(-z)) : log1pf(expf(z));
}
__device__ __forceinline__ uint32_t smem_u32(const void* p) {
    uint32_t a;
    asm("{ .reg .u64 t; cvta.to.shared.u64 t, %1; cvt.u32.u64 %0, t; }" : "=r"(a) : "l"(p));
    return a;
}
__device__ __forceinline__ void ldsm_x4(uint32_t& r0, uint32_t& r1, uint32_t& r2, uint32_t& r3,
                                        uint32_t addr) {
    asm volatile("ldmatrix.sync.aligned.m8n8.x4.shared.b16 {%0, %1, %2, %3}, [%4];"
                 : "=r"(r0), "=r"(r1), "=r"(r2), "=r"(r3) : "r"(addr));
}
__device__ __forceinline__ void ldsm_x4t(uint32_t& r0, uint32_t& r1, uint32_t& r2, uint32_t& r3,
                                         uint32_t addr) {
    asm volatile("ldmatrix.sync.aligned.m8n8.x4.trans.shared.b16 {%0, %1, %2, %3}, [%4];"
                 : "=r"(r0), "=r"(r1), "=r"(r2), "=r"(r3) : "r"(addr));
}
__device__ __forceinline__ void mma16816(float* d, const uint32_t* a, const uint32_t* b) {
    asm volatile(
        "mma.sync.aligned.m16n8k16.row.col.f32.bf16.bf16.f32 "
        "{%0, %1, %2, %3}, {%4, %5, %6, %7}, {%8, %9}, {%0, %1, %2, %3};"
        : "+f"(d[0]), "+f"(d[1]), "+f"(d[2]), "+f"(d[3])
        : "r"(a[0]), "r"(a[1]), "r"(a[2]), "r"(a[3]), "r"(b[0]), "r"(b[1]));
}
__device__ __forceinline__ void cp_async16(uint32_t saddr, const void* g) {
    asm volatile("cp.async.cg.shared.global [%0], [%1], 16;" :: "r"(saddr), "l"(g));
}
#define CP_COMMIT() asm volatile("cp.async.commit_group;" ::: "memory")
#define CP_WAIT(n)  asm volatile("cp.async.wait_group %0;" :: "n"(n) : "memory")

// block reductions for 1024 threads (32 warps)
__device__ __forceinline__ float blk_max(float v, float* red) {
    int lane = threadIdx.x & 31, w = threadIdx.x >> 5;
    #pragma unroll
    for (int o = 16; o; o >>= 1) v = fmaxf(v, __shfl_xor_sync(0xffffffffu, v, o));
    if (!lane) red[w] = v;
    __syncthreads();
    if (w == 0) {
        v = red[lane];
        #pragma unroll
        for (int o = 16; o; o >>= 1) v = fmaxf(v, __shfl_xor_sync(0xffffffffu, v, o));
        if (!lane) red[0] = v;
    }
    __syncthreads();
    v = red[0];
    __syncthreads();
    return v;
}
__device__ __forceinline__ float blk_sum(float v, float* red) {
    int lane = threadIdx.x & 31, w = threadIdx.x >> 5;
    #pragma unroll
    for (int o = 16; o; o >>= 1) v += __shfl_xor_sync(0xffffffffu, v, o);
    if (!lane) red[w] = v;
    __syncthreads();
    if (w == 0) {
        v = red[lane];
        #pragma unroll
        for (int o = 16; o; o >>= 1) v += __shfl_xor_sync(0xffffffffu, v, o);
        if (!lane) red[0] = v;
    }
    __syncthreads();
    v = red[0];
    __syncthreads();
    return v;
}

// ---------------- K1: controller heads ----------------
__global__ void heads_kernel(const float* __restrict__ x,
                             const float* __restrict__ Wv, const float* __restrict__ bv,
                             const float* __restrict__ Wb, const float* __restrict__ bb,
                             const float* __restrict__ Wg, const float* __restrict__ bg) {
    int b = blockIdx.x, t = threadIdx.x;        // 64 threads
    __shared__ float xs[ND];
    __shared__ float red[64];
    for (int i = t; i < ND; i += 64) xs[i] = x[b * ND + i];
    __syncthreads();

    float acc = 0.f;
    #pragma unroll 8
    for (int d = 0; d < ND; ++d) acc = fmaf(xs[d], Wv[d * NW + t], acc);
    float pb = 0.f, pg = 0.f;
    for (int d = t; d < ND; d += 64) {
        pb = fmaf(xs[d], Wb[d], pb);
        pg = fmaf(xs[d], Wg[d], pg);
    }
    float v = acc + bv[t];
    g_v[b * NW + t] = v;
    g_vh[b * NW + t] = __float2bfloat16(v);

    red[t] = v * v; __syncthreads();
    for (int s = 32; s > 0; s >>= 1) { if (t < s) red[t] += red[t + s]; __syncthreads(); }
    if (t == 0) g_vn[b] = sqrtf(red[0]);
    __syncthreads();

    red[t] = pb; __syncthreads();
    for (int s = 32; s > 0; s >>= 1) { if (t < s) red[t] += red[t + s]; __syncthreads(); }
    if (t == 0) g_beta[b] = softplus_f(red[0] + bb[0]);
    __syncthreads();

    red[t] = pg; __syncthreads();
    for (int s = 32; s > 0; s >>= 1) { if (t < s) red[t] += red[t + s]; __syncthreads(); }
    if (t == 0) g_gamma[b] = 1.f + softplus_f(red[0] + bg[0]);
}

// ---------------- K0: memory row norms ----------------
__global__ void mn_kernel(const float* __restrict__ mem) {
    int r = blockIdx.x * blockDim.x + threadIdx.x;
    if (r >= NR) return;
    const float4* m4 = (const float4*)(mem + (size_t)r * NW);
    float s = 0.f;
    #pragma unroll
    for (int i = 0; i < NW / 4; ++i) {
        float4 t4 = m4[i];
        s += t4.x * t4.x + t4.y * t4.y + t4.z * t4.z + t4.w * t4.w;
    }
    g_mn[r] = sqrtf(s);
}

// ---------------- prep: mem -> bf16 ----------------
__global__ void memh_kernel(const float* __restrict__ mem) {
    int i = blockIdx.x * 256 + threadIdx.x;
    float4 f = *(const float4*)&mem[(size_t)i * 4];
    __nv_bfloat162 h0 = __float22bfloat162_rn(make_float2(f.x, f.y));
    __nv_bfloat162 h1 = __float22bfloat162_rn(make_float2(f.z, f.w));
    *(__nv_bfloat162*)&g_memh[(size_t)i * 4]     = h0;
    *(__nv_bfloat162*)&g_memh[(size_t)i * 4 + 2] = h1;
}

// ---------------- K2: sim via HMMA bf16 ----------------
#define SLS 72
__global__ void __launch_bounds__(256, 2)
sim_tc_kernel() {
    __shared__ __nv_bfloat16 As[128][SLS];
    __shared__ __nv_bfloat16 Bs[128][SLS];
    int tid = threadIdx.x;
    int lane = tid & 31, wid = tid >> 5;
    int n0 = blockIdx.x * 128;    // r
    int b0 = blockIdx.y * 128;    // b
    int wm0 = (wid & 1) * 64;
    int wn0 = (wid >> 1) * 32;

    #pragma unroll
    for (int i = 0; i < 4; ++i) {
        int q = tid + i * 256;
        int row = q >> 3, seg = (q & 7) * 8;
        *(uint4*)&As[row][seg] = *(const uint4*)&g_vh[(size_t)(b0 + row) * NW + seg];
        *(uint4*)&Bs[row][seg] = *(const uint4*)&g_memh[(size_t)(n0 + row) * NW + seg];
    }
    __syncthreads();

    float d[4][4][4] = {};
    uint32_t as_base = smem_u32(&As[0][0]);
    uint32_t bs_base = smem_u32(&Bs[0][0]);
    int a_row = wm0 + (lane & 15);
    int a_kof = (lane >> 4) * 8;
    int b_rof = ((lane >> 4) * 8) + (lane & 7);
    int b_kof = ((lane >> 3) & 1) * 8;

    #pragma unroll
    for (int ks = 0; ks < 4; ++ks) {
        int k0 = ks * 16;
        uint32_t a[4][4];
        #pragma unroll
        for (int mi = 0; mi < 4; ++mi) {
            uint32_t addr = as_base + ((a_row + mi * 16) * SLS + k0 + a_kof) * 2;
            ldsm_x4(a[mi][0], a[mi][1], a[mi][2], a[mi][3], addr);
        }
        uint32_t bfr[2][4];
        #pragma unroll
        for (int nj = 0; nj < 2; ++nj) {
            uint32_t addr = bs_base + ((wn0 + nj * 16 + b_rof) * SLS + k0 + b_kof) * 2;
            ldsm_x4(bfr[nj][0], bfr[nj][1], bfr[nj][2], bfr[nj][3], addr);
        }
        #pragma unroll
        for (int mi = 0; mi < 4; ++mi)
            #pragma unroll
            for (int ni = 0; ni < 4; ++ni)
                mma16816(d[mi][ni], a[mi], &bfr[ni >> 1][(ni & 1) * 2]);
    }

    int gr = lane >> 2, gc = (lane & 3) * 2;
    #pragma unroll
    for (int mi = 0; mi < 4; ++mi) {
        int bi0 = b0 + wm0 + mi * 16 + gr;
        float s0 = g_beta[bi0] , n0v = g_vn[bi0];
        float s1 = g_beta[bi0 + 8], n1v = g_vn[bi0 + 8];
        #pragma unroll
        for (int ni = 0; ni < 4; ++ni) {
            int c = n0 + wn0 + ni * 8 + gc;
            float m0 = g_mn[c], m1 = g_mn[c + 1];
            *(float2*)&g_sim[(size_t)bi0 * NR + c] = make_float2(
                s0 * d[mi][ni][0] / (n0v * m0 + EPSF),
                s0 * d[mi][ni][1] / (n0v * m1 + EPSF));
            *(float2*)&g_sim[(size_t)(bi0 + 8) * NR + c] = make_float2(
                s1 * d[mi][ni][2] / (n1v * m0 + EPSF),
                s1 * d[mi][ni][3] / (n1v * m1 + EPSF));
        }
    }
}

// ---------------- K3: softmax -> conv(K=3) -> pow(gamma) -> renorm (float4) ---------
__global__ void wa_kernel(const float* __restrict__ conv_k, const float* __restrict__ conv_b) {
    extern __shared__ float ws[];
    __shared__ float red[32];
    int b = blockIdx.x, t = threadIdx.x;   // 1024 threads
    float* row = g_sim + (size_t)b * NR;

    float4 loc[4];
    float mx = -1e30f;
    #pragma unroll
    for (int i = 0; i < 4; ++i) {
        loc[i] = *(const float4*)&row[i * 4096 + t * 4];
        mx = fmaxf(mx, fmaxf(fmaxf(loc[i].x, loc[i].y), fmaxf(loc[i].z, loc[i].w)));
    }
    mx = blk_max(mx, red);

    float sum = 0.f;
    #pragma unroll
    for (int i = 0; i < 4; ++i) {
        float4 e;
        e.x = __expf(loc[i].x - mx); e.y = __expf(loc[i].y - mx);
        e.z = __expf(loc[i].z - mx); e.w = __expf(loc[i].w - mx);
        *(float4*)&ws[i * 4096 + t * 4] = e;
        sum += e.x + e.y + e.z + e.w;
    }
    sum = blk_sum(sum, red);
    float inv = 1.f / sum;

    float c0 = conv_k[0], c1 = conv_k[1], c2 = conv_k[2], cb = conv_b[0];
    float gam = g_gamma[b];
    float la[16];
    float asum = 0.f;
    #pragma unroll
    for (int i = 0; i < 4; ++i) {
        int base = i * 4096 + t * 4;
        #pragma unroll
        for (int c = 0; c < 4; ++c) {
            int r = base + c;
            float wl = (r > 0)      ? ws[r - 1] : 0.f;
            float wr = (r < NR - 1) ? ws[r + 1] : 0.f;
            float wc = fmaf(wl, c0, fmaf(ws[r], c1, wr * c2)) * inv + cb;
            float a = __powf(wc, gam);
            la[i * 4 + c] = a; asum += a;
        }
    }
    asum = blk_sum(asum, red);
    float invd = 1.f / (asum + (float)NR * EPSF);

    #pragma unroll
    for (int i = 0; i < 4; ++i) {
        float4 o;
        o.x = la[i * 4 + 0] * invd; o.y = la[i * 4 + 1] * invd;
        o.z = la[i * 4 + 2] * invd; o.w = la[i * 4 + 3] * invd;
        *(float4*)&row[i * 4096 + t * 4] = o;
    }
}

// ---------------- K4a: add/erase via HMMA bf16 (ldmatrix.trans) ----------------
#define ATS 72
__global__ void __launch_bounds__(128, 4)
add_tc_kernel() {
    __shared__ __nv_bfloat16 As[128][ATS];   // [b-local][r-local 64]
    __shared__ __nv_bfloat16 Vs[128][ATS];   // [b-local][w 64]
    int tid = threadIdx.x, lane = tid & 31, wid = tid >> 5;   // 4 warps
    int r0 = blockIdx.x * 64;
    float acc[8][4] = {};
    float acce[4] = {};
    uint32_t onesf[2] = {0x3F803F80u, 0x3F803F80u};
    uint32_t asb = smem_u32(&As[0][0]), vsb = smem_u32(&Vs[0][0]);
    int m0 = wid * 16;
    int lrow = (lane & 7) + ((lane & 16) >> 1);
    int lcol = lane & 8;

    for (int kb = 0; kb < NB; kb += 128) {
        #pragma unroll
        for (int i = 0; i < 16; ++i) {
            int q = tid + i * 128;
            int kk = q >> 4, c = (q & 15) * 4;
            float4 f = *(const float4*)&g_sim[(size_t)(kb + kk) * NR + r0 + c];
            *(__nv_bfloat162*)&As[kk][c]     = __float22bfloat162_rn(make_float2(f.x, f.y));
            *(__nv_bfloat162*)&As[kk][c + 2] = __float22bfloat162_rn(make_float2(f.z, f.w));
        }
        #pragma unroll
        for (int i = 0; i < 8; ++i) {
            int q = tid + i * 128;
            int kk = q >> 3, c = (q & 7) * 8;
            *(uint4*)&Vs[kk][c] = *(const uint4*)&g_vh[(kb + kk) * NW + c];
        }
        __syncthreads();

        #pragma unroll
        for (int ks = 0; ks < 8; ++ks) {
            int k0 = ks * 16;
            uint32_t a[4];
            ldsm_x4t(a[0], a[1], a[2], a[3],
                     asb + ((k0 + lrow) * ATS + m0 + lcol) * 2);
            uint32_t bfr[4][4];
            #pragma unroll
            for (int nj = 0; nj < 4; ++nj)
                ldsm_x4t(bfr[nj][0], bfr[nj][1], bfr[nj][2], bfr[nj][3],
                         vsb + ((k0 + lrow) * ATS + nj * 16 + lcol) * 2);
            #pragma unroll
            for (int nj = 0; nj < 4; ++nj) {
                uint32_t f1[2] = {bfr[nj][0], bfr[nj][2]};
                uint32_t f2[2] = {bfr[nj][1], bfr[nj][3]};
                mma16816(acc[nj * 2],     a, f1);
                mma16816(acc[nj * 2 + 1], a, f2);
            }
            mma16816(acce, a, onesf);
        }
        __syncthreads();
    }

    int gr = lane >> 2, gc = (lane & 3) * 2;
    int r = r0 + m0 + gr;
    #pragma unroll
    for (int nj = 0; nj < 8; ++nj) {
        int w = nj * 8 + gc;
        *(float2*)&g_add[(size_t)r * NW + w]       = make_float2(acc[nj][0], acc[nj][1]);
        *(float2*)&g_add[(size_t)(r + 8) * NW + w] = make_float2(acc[nj][2], acc[nj][3]);
    }
    if ((lane & 3) == 0) { g_er[r] = acce[0]; g_er[r + 8] = acce[2]; }
}

// ---------------- K4b: mem2 = mem*(1-er/B) + add/B, transpose + bf16 hi/lo ----------
__global__ void mem2t_kernel(const float* __restrict__ mem) {
    __shared__ float t[64][65];
    __shared__ float ev[64];
    int r0 = blockIdx.x * 64;
    int tid = threadIdx.x;
    const float invB = 1.f / (float)NB;

    if (tid < 64) ev[tid] = 1.f - g_er[r0 + tid] * invB;
    __syncthreads();

    #pragma unroll
    for (int i = 0; i < 16; ++i) {
        int q = tid + i * 256;
        int r = q >> 6, w = q & 63;
        t[r][w] = mem[(size_t)(r0 + r) * NW + w] * ev[r] + g_add[(size_t)(r0 + r) * NW + w] * invB;
    }
    __syncthreads();

    #pragma unroll
    for (int i = 0; i < 16; ++i) {
        int q = tid + i * 256;
        int w = q >> 6, r = q & 63;
        float f = t[r][w];
        __nv_bfloat16 h = __float2bfloat16(f);
        __nv_bfloat16 l = __float2bfloat16(f - __bfloat162float(h));
        g_m2h[(size_t)w * NR + r0 + r] = h;
        g_m2l[(size_t)w * NR + r0 + r] = l;
    }
}

// ---------------- prep: xcat = [x_hi | x_lo | x_hi] ----------------
__global__ void xcat_kernel(const float* __restrict__ x) {
    int i = blockIdx.x * 256 + threadIdx.x;
    int b = i >> 8, k = i & 255;
    float f = x[i];
    __nv_bfloat16 h = __float2bfloat16(f);
    __nv_bfloat16 l = __float2bfloat16(f - __bfloat162float(h));
    g_xcat[(size_t)b * KCAT + k]       = h;
    g_xcat[(size_t)b * KCAT + 256 + k] = l;
    g_xcat[(size_t)b * KCAT + 512 + k] = h;
}

// ---------------- prep: wcat ----------------
__global__ void wcat_kernel(const float* __restrict__ Wp) {
    __shared__ float t[32][33];
    int n0 = blockIdx.x * 32, k0 = blockIdx.y * 32;
    int tx = threadIdx.x, ty = threadIdx.y;   // (32, 8)
    #pragma unroll
    for (int i = 0; i < 4; ++i)
        t[ty + 8 * i][tx] = Wp[(size_t)(k0 + ty + 8 * i) * NR + n0 + tx];
    __syncthreads();
    #pragma unroll
    for (int i = 0; i < 4; ++i) {
        int row = ty + 8 * i;
        float f = t[tx][row];
        __nv_bfloat16 h = __float2bfloat16(f);
        __nv_bfloat16 l = __float2bfloat16(f - __bfloat162float(h));
        size_t base = (size_t)(n0 + row) * KCAT + k0 + tx;
        g_wcat[base]       = h;
        g_wcat[base + 256] = h;
        g_wcat[base + 512] = l;
    }
}

// ---------------- K5: p logits, 128x128 CTA tile, 256 thr, 2 CTA/SM, cp.async ---------
#define PLS 40
#define PLK (KCAT / 32)

__global__ void __launch_bounds__(256, 2)
pl_mma_kernel(const float* __restrict__ bp) {
    __shared__ __nv_bfloat16 As[2][128][PLS];
    __shared__ __nv_bfloat16 Bs[2][128][PLS];
    int tid = threadIdx.x;
    int lane = tid & 31, wid = tid >> 5;          // 8 warps
    int n0 = blockIdx.x * 128;
    int b0 = blockIdx.y * 128;
    int wm0 = (wid & 3) * 32;
    int wn0 = (wid >> 2) * 64;

    uint32_t asb = smem_u32(&As[0][0][0]);
    uint32_t bsb = smem_u32(&Bs[0][0][0]);
    const uint32_t bufB = 128 * PLS * 2;

    // load slots: 2 uint4 per thread per matrix
    int row0 = tid >> 2, seg0 = (tid & 3) * 8;
    int row1 = (tid + 256) >> 2, seg1 = (tid & 3) * 8;

    uint32_t a_sa0 = asb + (row0 * PLS + seg0) * 2;
    uint32_t a_sa1 = asb + (row1 * PLS + seg1) * 2;
    uint32_t b_sa0 = bsb + (row0 * PLS + seg0) * 2;
    uint32_t b_sa1 = bsb + (row1 * PLS + seg1) * 2;
    const __nv_bfloat16* a_g0 = &g_xcat[(size_t)(b0 + row0) * KCAT + seg0];
    const __nv_bfloat16* a_g1 = &g_xcat[(size_t)(b0 + row1) * KCAT + seg1];
    const __nv_bfloat16* b_g0 = &g_wcat[(size_t)(n0 + row0) * KCAT + seg0];
    const __nv_bfloat16* b_g1 = &g_wcat[(size_t)(n0 + row1) * KCAT + seg1];

    // prologue: chunk 0 -> stage 0
    cp_async16(a_sa0, a_g0);
    cp_async16(a_sa1, a_g1);
    cp_async16(b_sa0, b_g0);
    cp_async16(b_sa1, b_g1);
    CP_COMMIT();

    float acc[2][8][4] = {};
    int a_row = wm0 + (lane & 15);
    int a_kof = (lane >> 4) * 8;
    int b_rof = ((lane >> 4) * 8) + (lane & 7);
    int b_kof = ((lane >> 3) & 1) * 8;

    for (int kc = 0; kc < PLK; ++kc) {
        int cur = kc & 1;
        if (kc + 1 < PLK) {
            int nxt = cur ^ 1;
            int ko = (kc + 1) * 32;
            cp_async16(a_sa0 + nxt * bufB, a_g0 + ko);
            cp_async16(a_sa1 + nxt * bufB, a_g1 + ko);
            cp_async16(b_sa0 + nxt * bufB, b_g0 + ko);
            cp_async16(b_sa1 + nxt * bufB, b_g1 + ko);
            CP_COMMIT();
            CP_WAIT(1);
        } else {
            CP_WAIT(0);
        }
        __syncthreads();

        uint32_t abase = asb + cur * bufB;
        uint32_t bbase = bsb + cur * bufB;
        #pragma unroll
        for (int ks = 0; ks < 2; ++ks) {
            int k0 = ks * 16;
            uint32_t a[2][4];
            #pragma unroll
            for (int mi = 0; mi < 2; ++mi) {
                uint32_t addr = abase + ((a_row + mi * 16) * PLS + k0 + a_kof) * 2;
                ldsm_x4(a[mi][0], a[mi][1], a[mi][2], a[mi][3], addr);
            }
            uint32_t bfr[4][4];
            #pragma unroll
            for (int nj = 0; nj < 4; ++nj) {
                uint32_t addr = bbase + ((wn0 + nj * 16 + b_rof) * PLS + k0 + b_kof) * 2;
                ldsm_x4(bfr[nj][0], bfr[nj][1], bfr[nj][2], bfr[nj][3], addr);
            }
            #pragma unroll
            for (int mi = 0; mi < 2; ++mi)
                #pragma unroll
                for (int nj = 0; nj < 4; ++nj) {
                    mma16816(acc[mi][nj * 2],     a[mi], &bfr[nj][0]);
                    mma16816(acc[mi][nj * 2 + 1], a[mi], &bfr[nj][2]);
                }
        }
        __syncthreads();
    }

    int gr = lane >> 2, gc = (lane & 3) * 2;
    #pragma unroll
    for (int mi = 0; mi < 2; ++mi) {
        int r1 = b0 + wm0 + mi * 16 + gr;
        #pragma unroll
        for (int j = 0; j < 8; ++j) {
            int c = n0 + wn0 + j * 8 + gc;
            float bpx = bp[c], bpy = bp[c + 1];
            *(float2*)&g_pl[(size_t)r1 * NR + c] =
                make_float2(acc[mi][j][0] + bpx, acc[mi][j][1] + bpy);
            *(float2*)&g_pl[(size_t)(r1 + 8) * NR + c] =
                make_float2(acc[mi][j][2] + bpx, acc[mi][j][3] + bpy);
        }
    }
}

// ---------------- K6: per-row softmax stats for p (float4) ----------------
__global__ void __launch_bounds__(1024, 2)
pstats_kernel() {
    __shared__ float red[32];
    int b = blockIdx.x, t = threadIdx.x;
    const float* row = g_pl + (size_t)b * NR;

    float4 loc[4];
    float mx = -1e30f;
    #pragma unroll
    for (int i = 0; i < 4; ++i) {
        loc[i] = *(const float4*)&row[i * 4096 + t * 4];
        mx = fmaxf(mx, fmaxf(fmaxf(loc[i].x, loc[i].y), fmaxf(loc[i].z, loc[i].w)));
    }
    mx = blk_max(mx, red);

    float sum = 0.f;
    #pragma unroll
    for (int i = 0; i < 4; ++i)
        sum += __expf(loc[i].x - mx) + __expf(loc[i].y - mx)
             + __expf(loc[i].z - mx) + __expf(loc[i].w - mx);
    sum = blk_sum(sum, red);

    if (t == 0) { g_pmx[b] = mx; g_pinv[b] = 1.f / sum; }
}

// ---------------- K7: out = softmax(pl) @ mem2 via HMMA hi/lo split ----------------
#define OLS 72
#define O_EH 0
#define O_EL (128 * OLS)
#define O_MH (256 * OLS)
#define O_ML (320 * OLS)
#define O_SMEM (384 * OLS * 2)

__global__ void __launch_bounds__(256, 2)
out_tc_kernel() {
    extern __shared__ __nv_bfloat16 osm[];
    __nv_bfloat16* EH = osm + O_EH;
    __nv_bfloat16* EL = osm + O_EL;
    __nv_bfloat16* MH = osm + O_MH;
    __nv_bfloat16* ML = osm + O_ML;
    int tid = threadIdx.x;
    int lane = tid & 31, wid = tid >> 5;
    int split = blockIdx.x;
    int b0 = blockIdx.y * 128;
    int kbase = split * (NR / NSPLIT);

    int la = tid >> 4, lb = tid & 15;
    float mxv[8], invv[8];
    #pragma unroll
    for (int i = 0; i < 8; ++i) {
        mxv[i]  = g_pmx[b0 + la + 16 * i];
        invv[i] = g_pinv[b0 + la + 16 * i];
    }
    int m_row0 = tid >> 3, m_seg0 = (tid & 7) * 8;
    int m_row1 = (tid + 256) >> 3, m_seg1 = (tid & 7) * 8;

    uint32_t ehb = smem_u32(EH), elb = smem_u32(EL);
    uint32_t mhb = smem_u32(MH), mlb = smem_u32(ML);

    float acc[8][4] = {};
    int a_row = wid * 16 + (lane & 15);
    int a_kof = (lane >> 4) * 8;
    int b_rof = ((lane >> 4) * 8) + (lane & 7);
    int b_kof = ((lane >> 3) & 1) * 8;

    for (int kg = kbase; kg < kbase + NR / NSPLIT; kg += 64) {
        #pragma unroll
        for (int i = 0; i < 8; ++i) {
            int row = la + 16 * i;
            float4 l4 = *(const float4*)&g_pl[(size_t)(b0 + row) * NR + kg + lb * 4];
            float e0 = __expf(l4.x - mxv[i]) * invv[i];
            float e1 = __expf(l4.y - mxv[i]) * invv[i];
            float e2 = __expf(l4.z - mxv[i]) * invv[i];
            float e3 = __expf(l4.w - mxv[i]) * invv[i];
            __nv_bfloat16 h0 = __float2bfloat16(e0), h1 = __float2bfloat16(e1);
            __nv_bfloat16 h2 = __float2bfloat16(e2), h3 = __float2bfloat16(e3);
            __nv_bfloat16 l0 = __float2bfloat16(e0 - __bfloat162float(h0));
            __nv_bfloat16 l1 = __float2bfloat16(e1 - __bfloat162float(h1));
            __nv_bfloat16 l2 = __float2bfloat16(e2 - __bfloat162float(h2));
            __nv_bfloat16 l3 = __float2bfloat16(e3 - __bfloat162float(h3));
            __nv_bfloat16* eh = &EH[row * OLS + lb * 4];
            __nv_bfloat16* el = &EL[row * OLS + lb * 4];
            eh[0] = h0; eh[1] = h1; eh[2] = h2; eh[3] = h3;
            el[0] = l0; el[1] = l1; el[2] = l2; el[3] = l3;
        }
        *(uint4*)&MH[m_row0 * OLS + m_seg0] = *(const uint4*)&g_m2h[(size_t)m_row0 * NR + kg + m_seg0];
        *(uint4*)&MH[m_row1 * OLS + m_seg1] = *(const uint4*)&g_m2h[(size_t)m_row1 * NR + kg + m_seg1];
        *(uint4*)&ML[m_row0 * OLS + m_seg0] = *(const uint4*)&g_m2l[(size_t)m_row0 * NR + kg + m_seg0];
        *(uint4*)&ML[m_row1 * OLS + m_seg1] = *(const uint4*)&g_m2l[(size_t)m_row1 * NR + kg + m_seg1];
        __syncthreads();

        #pragma unroll
        for (int ks = 0; ks < 4; ++ks) {
            int k0 = ks * 16;
            uint32_t ah[4], al[4];
            {
                uint32_t addr = ehb + (a_row * OLS + k0 + a_kof) * 2;
                ldsm_x4(ah[0], ah[1], ah[2], ah[3], addr);
                addr = elb + (a_row * OLS + k0 + a_kof) * 2;
                ldsm_x4(al[0], al[1], al[2], al[3], addr);
            }
            uint32_t bh[4][4], bl[4][4];
            #pragma unroll
            for (int g = 0; g < 4; ++g) {
                uint32_t addr = mhb + ((g * 16 + b_rof) * OLS + k0 + b_kof) * 2;
                ldsm_x4(bh[g][0], bh[g][1], bh[g][2], bh[g][3], addr);
                addr = mlb + ((g * 16 + b_rof) * OLS + k0 + b_kof) * 2;
                ldsm_x4(bl[g][0], bl[g][1], bl[g][2], bl[g][3], addr);
            }
            #pragma unroll
            for (int g = 0; g < 4; ++g) {
                mma16816(acc[g * 2],     ah, &bh[g][0]);
                mma16816(acc[g * 2 + 1], ah, &bh[g][2]);
                mma16816(acc[g * 2],     al, &bh[g][0]);
                mma16816(acc[g * 2 + 1], al, &bh[g][2]);
                mma16816(acc[g * 2],     ah, &bl[g][0]);
                mma16816(acc[g * 2 + 1], ah, &bl[g][2]);
            }
        }
        __syncthreads();
    }

    int gr = lane >> 2, gc = (lane & 3) * 2;
    int r1 = b0 + wid * 16 + gr;
    #pragma unroll
    for (int j = 0; j < 8; ++j) {
        int c = j * 8 + gc;
        *(float2*)&g_part[(size_t)split * (NB * NW) + (size_t)r1 * NW + c] =
            make_float2(acc[j][0], acc[j][1]);
        *(float2*)&g_part[(size_t)split * (NB * NW) + (size_t)(r1 + 8) * NW + c] =
            make_float2(acc[j][2], acc[j][3]);
    }
}

__global__ void out_reduce(float* __restrict__ out) {
    int i = blockIdx.x * blockDim.x + threadIdx.x;
    float s = 0.f;
    #pragma unroll
    for (int p = 0; p < NSPLIT; ++p) s += g_part[(size_t)p * (NB * NW) + i];
    out[i] = s;
}

// ---------------- launch ----------------
extern "C" void kernel_launch(void* const* d_in, const int* in_sizes, int n_in,
                              void* d_out, int out_size) {
    const float* x   = (const float*)d_in[0];
    const float* Wv  = (const float*)d_in[1];
    const float* bv  = (const float*)d_in[2];
    const float* Wb  = (const float*)d_in[3];
    const float* bb  = (const float*)d_in[4];
    const float* Wg  = (const float*)d_in[5];
    const float* bg  = (const float*)d_in[6];
    const float* Wp  = (const float*)d_in[7];
    const float* bp  = (const float*)d_in[8];
    const float* ck  = (const float*)d_in[9];
    const float* cbv = (const float*)d_in[10];
    const float* mem = (const float*)d_in[11];
    float* out = (float*)d_out;
    (void)in_sizes; (void)n_in; (void)out_size;

    cudaFuncSetAttribute(wa_kernel, cudaFuncAttributeMaxDynamicSharedMemorySize, NR * 4);
    cudaFuncSetAttribute(out_tc_kernel, cudaFuncAttributeMaxDynamicSharedMemorySize, O_SMEM);

    // order chosen so pl_mma_kernel is launch index 3 (ncu capture slot)
    xcat_kernel<<<NB * ND / 256, 256>>>(x);
    wcat_kernel<<<dim3(NR / 32, ND / 32), dim3(32, 8)>>>(Wp);
    heads_kernel<<<NB, 64>>>(x, Wv, bv, Wb, bb, Wg, bg);
    pl_mma_kernel<<<dim3(NR / 128, NB / 128), 256>>>(bp);
    mn_kernel<<<NR / 256, 256>>>(mem);
    memh_kernel<<<NR * NW / 4 / 256, 256>>>(mem);
    sim_tc_kernel<<<dim3(NR / 128, NB / 128), 256>>>();
    wa_kernel<<<NB, 1024, NR * 4>>>(ck, cbv);
    add_tc_kernel<<<NR / 64, 128>>>();
    mem2t_kernel<<<NR / 64, 256>>>(mem);
    pstats_kernel<<<NB, 1024>>>();
    out_tc_kernel<<<dim3(NSPLIT, NB / 128), 256, O_SMEM>>>();
    out_reduce<<<NB * NW / 256, 256>>>(out);
}

// round 9
// speedup vs baseline: 1.0002x; 1.0002x over previous
#include <cuda_runtime.h>
#include <cuda_bf16.h>
#include <math.h>
#include <cstdint>

#define NB 1024
#define ND 256
#define NR 16384
#define NW 64
#define NSPLIT 32
#define EPSF 1e-16f
#define KCAT 768

// ---------------- scratch (no allocations allowed) ----------------
__device__ float g_sim[(size_t)NB * NR];   // beta*sim logits, then a (in place)
__device__ float g_pl [(size_t)NB * NR];   // p logits (raw fp32)
__device__ float g_v  [NB * NW];
__device__ float g_vn [NB];
__device__ float g_beta[NB];
__device__ float g_gamma[NB];
__device__ float g_mn [NR];
__device__ float g_part[(size_t)NSPLIT * NB * NW];
__device__ float g_add[(size_t)NR * NW];
__device__ float g_er [NR];
__device__ float g_pmx [NB];
__device__ float g_pinv[NB];
__device__ __nv_bfloat16 g_xcat[(size_t)NB * KCAT];   // [x_hi | x_lo | x_hi]
__device__ __nv_bfloat16 g_wcat[(size_t)NR * KCAT];   // [W_hi | W_hi | W_lo] (transposed)
__device__ __nv_bfloat16 g_vh  [NB * NW];
__device__ __nv_bfloat16 g_memh[NR * NW];
__device__ __nv_bfloat16 g_m2h[(size_t)NW * NR];      // mem2^T hi  [w][r]
__device__ __nv_bfloat16 g_m2l[(size_t)NW * NR];      // mem2^T lo  [w][r]

__device__ __forceinline__ float softplus_f(float z) {
    return z > 0.f ? z + log1pf(expf(-z)) : log1pf(expf(z));
}
__device__ __forceinline__ uint32_t smem_u32(const void* p) {
    uint32_t a;
    asm("{ .reg .u64 t; cvta.to.shared.u64 t, %1; cvt.u32.u64 %0, t; }" : "=r"(a) : "l"(p));
    return a;
}
__device__ __forceinline__ void ldsm_x4(uint32_t& r0, uint32_t& r1, uint32_t& r2, uint32_t& r3,
                                        uint32_t addr) {
    asm volatile("ldmatrix.sync.aligned.m8n8.x4.shared.b16 {%0, %1, %2, %3}, [%4];"
                 : "=r"(r0), "=r"(r1), "=r"(r2), "=r"(r3) : "r"(addr));
}
__device__ __forceinline__ void ldsm_x4t(uint32_t& r0, uint32_t& r1, uint32_t& r2, uint32_t& r3,
                                         uint32_t addr) {
    asm volatile("ldmatrix.sync.aligned.m8n8.x4.trans.shared.b16 {%0, %1, %2, %3}, [%4];"
                 : "=r"(r0), "=r"(r1), "=r"(r2), "=r"(r3) : "r"(addr));
}
__device__ __forceinline__ void mma16816(float* d, const uint32_t* a, const uint32_t* b) {
    asm volatile(
        "mma.sync.aligned.m16n8k16.row.col.f32.bf16.bf16.f32 "
        "{%0, %1, %2, %3}, {%4, %5, %6, %7}, {%8, %9}, {%0, %1, %2, %3};"
        : "+f"(d[0]), "+f"(d[1]), "+f"(d[2]), "+f"(d[3])
        : "r"(a[0]), "r"(a[1]), "r"(a[2]), "r"(a[3]), "r"(b[0]), "r"(b[1]));
}
__device__ __forceinline__ void cp_async16(uint32_t saddr, const void* g) {
    asm volatile("cp.async.cg.shared.global [%0], [%1], 16;" :: "r"(saddr), "l"(g));
}
#define CP_COMMIT() asm volatile("cp.async.commit_group;" ::: "memory")
#define CP_WAIT(n)  asm volatile("cp.async.wait_group %0;" :: "n"(n) : "memory")

// block reductions for 1024 threads (32 warps)
__device__ __forceinline__ float blk_max(float v, float* red) {
    int lane = threadIdx.x & 31, w = threadIdx.x >> 5;
    #pragma unroll
    for (int o = 16; o; o >>= 1) v = fmaxf(v, __shfl_xor_sync(0xffffffffu, v, o));
    if (!lane) red[w] = v;
    __syncthreads();
    if (w == 0) {
        v = red[lane];
        #pragma unroll
        for (int o = 16; o; o >>= 1) v = fmaxf(v, __shfl_xor_sync(0xffffffffu, v, o));
        if (!lane) red[0] = v;
    }
    __syncthreads();
    v = red[0];
    __syncthreads();
    return v;
}
__device__ __forceinline__ float blk_sum(float v, float* red) {
    int lane = threadIdx.x & 31, w = threadIdx.x >> 5;
    #pragma unroll
    for (int o = 16; o; o >>= 1) v += __shfl_xor_sync(0xffffffffu, v, o);
    if (!lane) red[w] = v;
    __syncthreads();
    if (w == 0) {
        v = red[lane];
        #pragma unroll
        for (int o = 16; o; o >>= 1) v += __shfl_xor_sync(0xffffffffu, v, o);
        if (!lane) red[0] = v;
    }
    __syncthreads();
    v = red[0];
    __syncthreads();
    return v;
}

// ---------------- K1: controller heads ----------------
__global__ void heads_kernel(const float* __restrict__ x,
                             const float* __restrict__ Wv, const float* __restrict__ bv,
                             const float* __restrict__ Wb, const float* __restrict__ bb,
                             const float* __restrict__ Wg, const float* __restrict__ bg) {
    int b = blockIdx.x, t = threadIdx.x;        // 64 threads
    __shared__ float xs[ND];
    __shared__ float red[64];
    for (int i = t; i < ND; i += 64) xs[i] = x[b * ND + i];
    __syncthreads();

    float acc = 0.f;
    #pragma unroll 8
    for (int d = 0; d < ND; ++d) acc = fmaf(xs[d], Wv[d * NW + t], acc);
    float pb = 0.f, pg = 0.f;
    for (int d = t; d < ND; d += 64) {
        pb = fmaf(xs[d], Wb[d], pb);
        pg = fmaf(xs[d], Wg[d], pg);
    }
    float v = acc + bv[t];
    g_v[b * NW + t] = v;
    g_vh[b * NW + t] = __float2bfloat16(v);

    red[t] = v * v; __syncthreads();
    for (int s = 32; s > 0; s >>= 1) { if (t < s) red[t] += red[t + s]; __syncthreads(); }
    if (t == 0) g_vn[b] = sqrtf(red[0]);
    __syncthreads();

    red[t] = pb; __syncthreads();
    for (int s = 32; s > 0; s >>= 1) { if (t < s) red[t] += red[t + s]; __syncthreads(); }
    if (t == 0) g_beta[b] = softplus_f(red[0] + bb[0]);
    __syncthreads();

    red[t] = pg; __syncthreads();
    for (int s = 32; s > 0; s >>= 1) { if (t < s) red[t] += red[t + s]; __syncthreads(); }
    if (t == 0) g_gamma[b] = 1.f + softplus_f(red[0] + bg[0]);
}

// ---------------- K0: memory row norms + bf16 convert (fused, one pass) --------
__global__ void mnh_kernel(const float* __restrict__ mem) {
    int r = blockIdx.x * blockDim.x + threadIdx.x;
    if (r >= NR) return;
    const float4* m4 = (const float4*)(mem + (size_t)r * NW);
    __nv_bfloat162* h2 = (__nv_bfloat162*)(g_memh + (size_t)r * NW);
    float s = 0.f;
    #pragma unroll
    for (int i = 0; i < NW / 4; ++i) {
        float4 t4 = m4[i];
        s += t4.x * t4.x + t4.y * t4.y + t4.z * t4.z + t4.w * t4.w;
        h2[i * 2]     = __float22bfloat162_rn(make_float2(t4.x, t4.y));
        h2[i * 2 + 1] = __float22bfloat162_rn(make_float2(t4.z, t4.w));
    }
    g_mn[r] = sqrtf(s);
}

// ---------------- K2: sim via HMMA bf16 ----------------
#define SLS 72
__global__ void __launch_bounds__(256, 2)
sim_tc_kernel() {
    __shared__ __nv_bfloat16 As[128][SLS];
    __shared__ __nv_bfloat16 Bs[128][SLS];
    int tid = threadIdx.x;
    int lane = tid & 31, wid = tid >> 5;
    int n0 = blockIdx.x * 128;    // r
    int b0 = blockIdx.y * 128;    // b
    int wm0 = (wid & 1) * 64;
    int wn0 = (wid >> 1) * 32;

    #pragma unroll
    for (int i = 0; i < 4; ++i) {
        int q = tid + i * 256;
        int row = q >> 3, seg = (q & 7) * 8;
        *(uint4*)&As[row][seg] = *(const uint4*)&g_vh[(size_t)(b0 + row) * NW + seg];
        *(uint4*)&Bs[row][seg] = *(const uint4*)&g_memh[(size_t)(n0 + row) * NW + seg];
    }
    __syncthreads();

    float d[4][4][4] = {};
    uint32_t as_base = smem_u32(&As[0][0]);
    uint32_t bs_base = smem_u32(&Bs[0][0]);
    int a_row = wm0 + (lane & 15);
    int a_kof = (lane >> 4) * 8;
    int b_rof = ((lane >> 4) * 8) + (lane & 7);
    int b_kof = ((lane >> 3) & 1) * 8;

    #pragma unroll
    for (int ks = 0; ks < 4; ++ks) {
        int k0 = ks * 16;
        uint32_t a[4][4];
        #pragma unroll
        for (int mi = 0; mi < 4; ++mi) {
            uint32_t addr = as_base + ((a_row + mi * 16) * SLS + k0 + a_kof) * 2;
            ldsm_x4(a[mi][0], a[mi][1], a[mi][2], a[mi][3], addr);
        }
        uint32_t bfr[2][4];
        #pragma unroll
        for (int nj = 0; nj < 2; ++nj) {
            uint32_t addr = bs_base + ((wn0 + nj * 16 + b_rof) * SLS + k0 + b_kof) * 2;
            ldsm_x4(bfr[nj][0], bfr[nj][1], bfr[nj][2], bfr[nj][3], addr);
        }
        #pragma unroll
        for (int mi = 0; mi < 4; ++mi)
            #pragma unroll
            for (int ni = 0; ni < 4; ++ni)
                mma16816(d[mi][ni], a[mi], &bfr[ni >> 1][(ni & 1) * 2]);
    }

    int gr = lane >> 2, gc = (lane & 3) * 2;
    #pragma unroll
    for (int mi = 0; mi < 4; ++mi) {
        int bi0 = b0 + wm0 + mi * 16 + gr;
        float s0 = g_beta[bi0] , n0v = g_vn[bi0];
        float s1 = g_beta[bi0 + 8], n1v = g_vn[bi0 + 8];
        #pragma unroll
        for (int ni = 0; ni < 4; ++ni) {
            int c = n0 + wn0 + ni * 8 + gc;
            float m0 = g_mn[c], m1 = g_mn[c + 1];
            *(float2*)&g_sim[(size_t)bi0 * NR + c] = make_float2(
                s0 * d[mi][ni][0] / (n0v * m0 + EPSF),
                s0 * d[mi][ni][1] / (n0v * m1 + EPSF));
            *(float2*)&g_sim[(size_t)(bi0 + 8) * NR + c] = make_float2(
                s1 * d[mi][ni][2] / (n1v * m0 + EPSF),
                s1 * d[mi][ni][3] / (n1v * m1 + EPSF));
        }
    }
}

// ---------------- K3: softmax -> conv(K=3) -> pow(gamma) -> renorm (float4) ---------
__global__ void wa_kernel(const float* __restrict__ conv_k, const float* __restrict__ conv_b) {
    extern __shared__ float ws[];
    __shared__ float red[32];
    int b = blockIdx.x, t = threadIdx.x;   // 1024 threads
    float* row = g_sim + (size_t)b * NR;

    float4 loc[4];
    float mx = -1e30f;
    #pragma unroll
    for (int i = 0; i < 4; ++i) {
        loc[i] = *(const float4*)&row[i * 4096 + t * 4];
        mx = fmaxf(mx, fmaxf(fmaxf(loc[i].x, loc[i].y), fmaxf(loc[i].z, loc[i].w)));
    }
    mx = blk_max(mx, red);

    float sum = 0.f;
    #pragma unroll
    for (int i = 0; i < 4; ++i) {
        float4 e;
        e.x = __expf(loc[i].x - mx); e.y = __expf(loc[i].y - mx);
        e.z = __expf(loc[i].z - mx); e.w = __expf(loc[i].w - mx);
        *(float4*)&ws[i * 4096 + t * 4] = e;
        sum += e.x + e.y + e.z + e.w;
    }
    sum = blk_sum(sum, red);
    float inv = 1.f / sum;

    float c0 = conv_k[0], c1 = conv_k[1], c2 = conv_k[2], cb = conv_b[0];
    float gam = g_gamma[b];
    float la[16];
    float asum = 0.f;
    #pragma unroll
    for (int i = 0; i < 4; ++i) {
        int base = i * 4096 + t * 4;
        #pragma unroll
        for (int c = 0; c < 4; ++c) {
            int r = base + c;
            float wl = (r > 0)      ? ws[r - 1] : 0.f;
            float wr = (r < NR - 1) ? ws[r + 1] : 0.f;
            float wc = fmaf(wl, c0, fmaf(ws[r], c1, wr * c2)) * inv + cb;
            float a = __powf(wc, gam);
            la[i * 4 + c] = a; asum += a;
        }
    }
    asum = blk_sum(asum, red);
    float invd = 1.f / (asum + (float)NR * EPSF);

    #pragma unroll
    for (int i = 0; i < 4; ++i) {
        float4 o;
        o.x = la[i * 4 + 0] * invd; o.y = la[i * 4 + 1] * invd;
        o.z = la[i * 4 + 2] * invd; o.w = la[i * 4 + 3] * invd;
        *(float4*)&row[i * 4096 + t * 4] = o;
    }
}

// ---------------- K4a: add/erase via HMMA bf16 (ldmatrix.trans) ----------------
#define ATS 72
__global__ void __launch_bounds__(128, 4)
add_tc_kernel() {
    __shared__ __nv_bfloat16 As[128][ATS];   // [b-local][r-local 64]
    __shared__ __nv_bfloat16 Vs[128][ATS];   // [b-local][w 64]
    int tid = threadIdx.x, lane = tid & 31, wid = tid >> 5;   // 4 warps
    int r0 = blockIdx.x * 64;
    float acc[8][4] = {};
    float acce[4] = {};
    uint32_t onesf[2] = {0x3F803F80u, 0x3F803F80u};
    uint32_t asb = smem_u32(&As[0][0]), vsb = smem_u32(&Vs[0][0]);
    int m0 = wid * 16;
    int lrow = (lane & 7) + ((lane & 16) >> 1);
    int lcol = lane & 8;

    for (int kb = 0; kb < NB; kb += 128) {
        #pragma unroll
        for (int i = 0; i < 16; ++i) {
            int q = tid + i * 128;
            int kk = q >> 4, c = (q & 15) * 4;
            float4 f = *(const float4*)&g_sim[(size_t)(kb + kk) * NR + r0 + c];
            *(__nv_bfloat162*)&As[kk][c]     = __float22bfloat162_rn(make_float2(f.x, f.y));
            *(__nv_bfloat162*)&As[kk][c + 2] = __float22bfloat162_rn(make_float2(f.z, f.w));
        }
        #pragma unroll
        for (int i = 0; i < 8; ++i) {
            int q = tid + i * 128;
            int kk = q >> 3, c = (q & 7) * 8;
            *(uint4*)&Vs[kk][c] = *(const uint4*)&g_vh[(kb + kk) * NW + c];
        }
        __syncthreads();

        #pragma unroll
        for (int ks = 0; ks < 8; ++ks) {
            int k0 = ks * 16;
            uint32_t a[4];
            ldsm_x4t(a[0], a[1], a[2], a[3],
                     asb + ((k0 + lrow) * ATS + m0 + lcol) * 2);
            uint32_t bfr[4][4];
            #pragma unroll
            for (int nj = 0; nj < 4; ++nj)
                ldsm_x4t(bfr[nj][0], bfr[nj][1], bfr[nj][2], bfr[nj][3],
                         vsb + ((k0 + lrow) * ATS + nj * 16 + lcol) * 2);
            #pragma unroll
            for (int nj = 0; nj < 4; ++nj) {
                uint32_t f1[2] = {bfr[nj][0], bfr[nj][2]};
                uint32_t f2[2] = {bfr[nj][1], bfr[nj][3]};
                mma16816(acc[nj * 2],     a, f1);
                mma16816(acc[nj * 2 + 1], a, f2);
            }
            mma16816(acce, a, onesf);
        }
        __syncthreads();
    }

    int gr = lane >> 2, gc = (lane & 3) * 2;
    int r = r0 + m0 + gr;
    #pragma unroll
    for (int nj = 0; nj < 8; ++nj) {
        int w = nj * 8 + gc;
        *(float2*)&g_add[(size_t)r * NW + w]       = make_float2(acc[nj][0], acc[nj][1]);
        *(float2*)&g_add[(size_t)(r + 8) * NW + w] = make_float2(acc[nj][2], acc[nj][3]);
    }
    if ((lane & 3) == 0) { g_er[r] = acce[0]; g_er[r + 8] = acce[2]; }
}

// ---------------- K4b: mem2 = mem*(1-er/B) + add/B, transpose + bf16 hi/lo ----------
__global__ void mem2t_kernel(const float* __restrict__ mem) {
    __shared__ float t[64][65];
    __shared__ float ev[64];
    int r0 = blockIdx.x * 64;
    int tid = threadIdx.x;
    const float invB = 1.f / (float)NB;

    if (tid < 64) ev[tid] = 1.f - g_er[r0 + tid] * invB;
    __syncthreads();

    #pragma unroll
    for (int i = 0; i < 16; ++i) {
        int q = tid + i * 256;
        int r = q >> 6, w = q & 63;
        t[r][w] = mem[(size_t)(r0 + r) * NW + w] * ev[r] + g_add[(size_t)(r0 + r) * NW + w] * invB;
    }
    __syncthreads();

    #pragma unroll
    for (int i = 0; i < 16; ++i) {
        int q = tid + i * 256;
        int w = q >> 6, r = q & 63;
        float f = t[r][w];
        __nv_bfloat16 h = __float2bfloat16(f);
        __nv_bfloat16 l = __float2bfloat16(f - __bfloat162float(h));
        g_m2h[(size_t)w * NR + r0 + r] = h;
        g_m2l[(size_t)w * NR + r0 + r] = l;
    }
}

// ---------------- prep: xcat = [x_hi | x_lo | x_hi] ----------------
__global__ void xcat_kernel(const float* __restrict__ x) {
    int i = blockIdx.x * 256 + threadIdx.x;
    int b = i >> 8, k = i & 255;
    float f = x[i];
    __nv_bfloat16 h = __float2bfloat16(f);
    __nv_bfloat16 l = __float2bfloat16(f - __bfloat162float(h));
    g_xcat[(size_t)b * KCAT + k]       = h;
    g_xcat[(size_t)b * KCAT + 256 + k] = l;
    g_xcat[(size_t)b * KCAT + 512 + k] = h;
}

// ---------------- prep: wcat ----------------
__global__ void wcat_kernel(const float* __restrict__ Wp) {
    __shared__ float t[32][33];
    int n0 = blockIdx.x * 32, k0 = blockIdx.y * 32;
    int tx = threadIdx.x, ty = threadIdx.y;   // (32, 8)
    #pragma unroll
    for (int i = 0; i < 4; ++i)
        t[ty + 8 * i][tx] = Wp[(size_t)(k0 + ty + 8 * i) * NR + n0 + tx];
    __syncthreads();
    #pragma unroll
    for (int i = 0; i < 4; ++i) {
        int row = ty + 8 * i;
        float f = t[tx][row];
        __nv_bfloat16 h = __float2bfloat16(f);
        __nv_bfloat16 l = __float2bfloat16(f - __bfloat162float(h));
        size_t base = (size_t)(n0 + row) * KCAT + k0 + tx;
        g_wcat[base]       = h;
        g_wcat[base + 256] = h;
        g_wcat[base + 512] = l;
    }
}

// ---------------- K5: p logits, 128x128, 3-stage cp.async, 1 sync/chunk --------------
#define PLS 40
#define PLK (KCAT / 32)
#define PSTG 3
#define PL_BUF (128 * PLS)                 // elements per stage per matrix
#define PL_SMEM (2 * PSTG * PL_BUF * 2)    // bytes

__global__ void __launch_bounds__(256, 2)
pl_mma_kernel(const float* __restrict__ bp) {
    extern __shared__ __nv_bfloat16 plsm[];
    __nv_bfloat16* As = plsm;                    // [PSTG][128][PLS]
    __nv_bfloat16* Bs = plsm + PSTG * PL_BUF;    // [PSTG][128][PLS]
    int tid = threadIdx.x;
    int lane = tid & 31, wid = tid >> 5;          // 8 warps
    int n0 = blockIdx.x * 128;
    int b0 = blockIdx.y * 128;
    int wm0 = (wid & 3) * 32;
    int wn0 = (wid >> 2) * 64;

    uint32_t asb = smem_u32(As), bsb = smem_u32(Bs);
    const uint32_t bufB = PL_BUF * 2;

    // load slots: 2 uint4 per thread per matrix
    int row0 = tid >> 2, seg0 = (tid & 3) * 8;
    int row1 = (tid + 256) >> 2, seg1 = (tid & 3) * 8;

    uint32_t a_sa0 = asb + (row0 * PLS + seg0) * 2;
    uint32_t a_sa1 = asb + (row1 * PLS + seg1) * 2;
    uint32_t b_sa0 = bsb + (row0 * PLS + seg0) * 2;
    uint32_t b_sa1 = bsb + (row1 * PLS + seg1) * 2;
    const __nv_bfloat16* a_g0 = &g_xcat[(size_t)(b0 + row0) * KCAT + seg0];
    const __nv_bfloat16* a_g1 = &g_xcat[(size_t)(b0 + row1) * KCAT + seg1];
    const __nv_bfloat16* b_g0 = &g_wcat[(size_t)(n0 + row0) * KCAT + seg0];
    const __nv_bfloat16* b_g1 = &g_wcat[(size_t)(n0 + row1) * KCAT + seg1];

    // prologue: stages 0 and 1
    #pragma unroll
    for (int s = 0; s < 2; ++s) {
        cp_async16(a_sa0 + s * bufB, a_g0 + s * 32);
        cp_async16(a_sa1 + s * bufB, a_g1 + s * 32);
        cp_async16(b_sa0 + s * bufB, b_g0 + s * 32);
        cp_async16(b_sa1 + s * bufB, b_g1 + s * 32);
        CP_COMMIT();
    }

    float acc[2][8][4] = {};
    int a_row = wm0 + (lane & 15);
    int a_kof = (lane >> 4) * 8;
    int b_rof = ((lane >> 4) * 8) + (lane & 7);
    int b_kof = ((lane >> 3) & 1) * 8;

    for (int kc = 0; kc < PLK; ++kc) {
        int cur = kc % PSTG;
        if (kc + 1 < PLK) CP_WAIT(1); else CP_WAIT(0);
        __syncthreads();          // single barrier per chunk (3-stage: no WAR race)

        // issue stage kc+2 AFTER the barrier (its buffer was last read in chunk kc-1)
        if (kc + 2 < PLK) {
            int nxt = (kc + 2) % PSTG;
            int ko = (kc + 2) * 32;
            cp_async16(a_sa0 + nxt * bufB, a_g0 + ko);
            cp_async16(a_sa1 + nxt * bufB, a_g1 + ko);
            cp_async16(b_sa0 + nxt * bufB, b_g0 + ko);
            cp_async16(b_sa1 + nxt * bufB, b_g1 + ko);
            CP_COMMIT();
        }

        uint32_t abase = asb + cur * bufB;
        uint32_t bbase = bsb + cur * bufB;

        // fragment double-buffer across the 2 k-steps of this chunk
        uint32_t a[2][2][4], bfr[2][4][4];
        #pragma unroll
        for (int mi = 0; mi < 2; ++mi)
            ldsm_x4(a[0][mi][0], a[0][mi][1], a[0][mi][2], a[0][mi][3],
                    abase + ((a_row + mi * 16) * PLS + a_kof) * 2);
        #pragma unroll
        for (int nj = 0; nj < 4; ++nj)
            ldsm_x4(bfr[0][nj][0], bfr[0][nj][1], bfr[0][nj][2], bfr[0][nj][3],
                    bbase + ((wn0 + nj * 16 + b_rof) * PLS + b_kof) * 2);

        #pragma unroll
        for (int ks = 0; ks < 2; ++ks) {
            int c = ks & 1, n = c ^ 1;
            if (ks + 1 < 2) {   // prefetch next k-step's fragments before MMAs
                int k0 = (ks + 1) * 16;
                #pragma unroll
                for (int mi = 0; mi < 2; ++mi)
                    ldsm_x4(a[n][mi][0], a[n][mi][1], a[n][mi][2], a[n][mi][3],
                            abase + ((a_row + mi * 16) * PLS + k0 + a_kof) * 2);
                #pragma unroll
                for (int nj = 0; nj < 4; ++nj)
                    ldsm_x4(bfr[n][nj][0], bfr[n][nj][1], bfr[n][nj][2], bfr[n][nj][3],
                            bbase + ((wn0 + nj * 16 + b_rof) * PLS + k0 + b_kof) * 2);
            }
            #pragma unroll
            for (int mi = 0; mi < 2; ++mi)
                #pragma unroll
                for (int nj = 0; nj < 4; ++nj) {
                    mma16816(acc[mi][nj * 2],     a[c][mi], &bfr[c][nj][0]);
                    mma16816(acc[mi][nj * 2 + 1], a[c][mi], &bfr[c][nj][2]);
                }
        }
    }

    int gr = lane >> 2, gc = (lane & 3) * 2;
    #pragma unroll
    for (int mi = 0; mi < 2; ++mi) {
        int r1 = b0 + wm0 + mi * 16 + gr;
        #pragma unroll
        for (int j = 0; j < 8; ++j) {
            int c = n0 + wn0 + j * 8 + gc;
            float bpx = bp[c], bpy = bp[c + 1];
            *(float2*)&g_pl[(size_t)r1 * NR + c] =
                make_float2(acc[mi][j][0] + bpx, acc[mi][j][1] + bpy);
            *(float2*)&g_pl[(size_t)(r1 + 8) * NR + c] =
                make_float2(acc[mi][j][2] + bpx, acc[mi][j][3] + bpy);
        }
    }
}

// ---------------- K6: per-row softmax stats for p (float4) ----------------
__global__ void __launch_bounds__(1024, 2)
pstats_kernel() {
    __shared__ float red[32];
    int b = blockIdx.x, t = threadIdx.x;
    const float* row = g_pl + (size_t)b * NR;

    float4 loc[4];
    float mx = -1e30f;
    #pragma unroll
    for (int i = 0; i < 4; ++i) {
        loc[i] = *(const float4*)&row[i * 4096 + t * 4];
        mx = fmaxf(mx, fmaxf(fmaxf(loc[i].x, loc[i].y), fmaxf(loc[i].z, loc[i].w)));
    }
    mx = blk_max(mx, red);

    float sum = 0.f;
    #pragma unroll
    for (int i = 0; i < 4; ++i)
        sum += __expf(loc[i].x - mx) + __expf(loc[i].y - mx)
             + __expf(loc[i].z - mx) + __expf(loc[i].w - mx);
    sum = blk_sum(sum, red);

    if (t == 0) { g_pmx[b] = mx; g_pinv[b] = 1.f / sum; }
}

// ---------------- K7: out = softmax(pl) @ mem2 via HMMA hi/lo split ----------------
#define OLS 72
#define O_EH 0
#define O_EL (128 * OLS)
#define O_MH (256 * OLS)
#define O_ML (320 * OLS)
#define O_SMEM (384 * OLS * 2)

__global__ void __launch_bounds__(256, 2)
out_tc_kernel() {
    extern __shared__ __nv_bfloat16 osm[];
    __nv_bfloat16* EH = osm + O_EH;
    __nv_bfloat16* EL = osm + O_EL;
    __nv_bfloat16* MH = osm + O_MH;
    __nv_bfloat16* ML = osm + O_ML;
    int tid = threadIdx.x;
    int lane = tid & 31, wid = tid >> 5;
    int split = blockIdx.x;
    int b0 = blockIdx.y * 128;
    int kbase = split * (NR / NSPLIT);

    int la = tid >> 4, lb = tid & 15;
    float mxv[8], invv[8];
    #pragma unroll
    for (int i = 0; i < 8; ++i) {
        mxv[i]  = g_pmx[b0 + la + 16 * i];
        invv[i] = g_pinv[b0 + la + 16 * i];
    }
    int m_row0 = tid >> 3, m_seg0 = (tid & 7) * 8;
    int m_row1 = (tid + 256) >> 3, m_seg1 = (tid & 7) * 8;

    uint32_t ehb = smem_u32(EH), elb = smem_u32(EL);
    uint32_t mhb = smem_u32(MH), mlb = smem_u32(ML);

    float acc[8][4] = {};
    int a_row = wid * 16 + (lane & 15);
    int a_kof = (lane >> 4) * 8;
    int b_rof = ((lane >> 4) * 8) + (lane & 7);
    int b_kof = ((lane >> 3) & 1) * 8;

    for (int kg = kbase; kg < kbase + NR / NSPLIT; kg += 64) {
        #pragma unroll
        for (int i = 0; i < 8; ++i) {
            int row = la + 16 * i;
            float4 l4 = *(const float4*)&g_pl[(size_t)(b0 + row) * NR + kg + lb * 4];
            float e0 = __expf(l4.x - mxv[i]) * invv[i];
            float e1 = __expf(l4.y - mxv[i]) * invv[i];
            float e2 = __expf(l4.z - mxv[i]) * invv[i];
            float e3 = __expf(l4.w - mxv[i]) * invv[i];
            __nv_bfloat16 h0 = __float2bfloat16(e0), h1 = __float2bfloat16(e1);
            __nv_bfloat16 h2 = __float2bfloat16(e2), h3 = __float2bfloat16(e3);
            __nv_bfloat16 l0 = __float2bfloat16(e0 - __bfloat162float(h0));
            __nv_bfloat16 l1 = __float2bfloat16(e1 - __bfloat162float(h1));
            __nv_bfloat16 l2 = __float2bfloat16(e2 - __bfloat162float(h2));
            __nv_bfloat16 l3 = __float2bfloat16(e3 - __bfloat162float(h3));
            __nv_bfloat16* eh = &EH[row * OLS + lb * 4];
            __nv_bfloat16* el = &EL[row * OLS + lb * 4];
            eh[0] = h0; eh[1] = h1; eh[2] = h2; eh[3] = h3;
            el[0] = l0; el[1] = l1; el[2] = l2; el[3] = l3;
        }
        *(uint4*)&MH[m_row0 * OLS + m_seg0] = *(const uint4*)&g_m2h[(size_t)m_row0 * NR + kg + m_seg0];
        *(uint4*)&MH[m_row1 * OLS + m_seg1] = *(const uint4*)&g_m2h[(size_t)m_row1 * NR + kg + m_seg1];
        *(uint4*)&ML[m_row0 * OLS + m_seg0] = *(const uint4*)&g_m2l[(size_t)m_row0 * NR + kg + m_seg0];
        *(uint4*)&ML[m_row1 * OLS + m_seg1] = *(const uint4*)&g_m2l[(size_t)m_row1 * NR + kg + m_seg1];
        __syncthreads();

        #pragma unroll
        for (int ks = 0; ks < 4; ++ks) {
            int k0 = ks * 16;
            uint32_t ah[4], al[4];
            {
                uint32_t addr = ehb + (a_row * OLS + k0 + a_kof) * 2;
                ldsm_x4(ah[0], ah[1], ah[2], ah[3], addr);
                addr = elb + (a_row * OLS + k0 + a_kof) * 2;
                ldsm_x4(al[0], al[1], al[2], al[3], addr);
            }
            uint32_t bh[4][4], bl[4][4];
            #pragma unroll
            for (int g = 0; g < 4; ++g) {
                uint32_t addr = mhb + ((g * 16 + b_rof) * OLS + k0 + b_kof) * 2;
                ldsm_x4(bh[g][0], bh[g][1], bh[g][2], bh[g][3], addr);
                addr = mlb + ((g * 16 + b_rof) * OLS + k0 + b_kof) * 2;
                ldsm_x4(bl[g][0], bl[g][1], bl[g][2], bl[g][3], addr);
            }
            #pragma unroll
            for (int g = 0; g < 4; ++g) {
                mma16816(acc[g * 2],     ah, &bh[g][0]);
                mma16816(acc[g * 2 + 1], ah, &bh[g][2]);
                mma16816(acc[g * 2],     al, &bh[g][0]);
                mma16816(acc[g * 2 + 1], al, &bh[g][2]);
                mma16816(acc[g * 2],     ah, &bl[g][0]);
                mma16816(acc[g * 2 + 1], ah, &bl[g][2]);
            }
        }
        __syncthreads();
    }

    int gr = lane >> 2, gc = (lane & 3) * 2;
    int r1 = b0 + wid * 16 + gr;
    #pragma unroll
    for (int j = 0; j < 8; ++j) {
        int c = j * 8 + gc;
        *(float2*)&g_part[(size_t)split * (NB * NW) + (size_t)r1 * NW + c] =
            make_float2(acc[j][0], acc[j][1]);
        *(float2*)&g_part[(size_t)split * (NB * NW) + (size_t)(r1 + 8) * NW + c] =
            make_float2(acc[j][2], acc[j][3]);
    }
}

__global__ void out_reduce(float* __restrict__ out) {
    int i = blockIdx.x * blockDim.x + threadIdx.x;
    float s = 0.f;
    #pragma unroll
    for (int p = 0; p < NSPLIT; ++p) s += g_part[(size_t)p * (NB * NW) + i];
    out[i] = s;
}

// ---------------- launch ----------------
extern "C" void kernel_launch(void* const* d_in, const int* in_sizes, int n_in,
                              void* d_out, int out_size) {
    const float* x   = (const float*)d_in[0];
    const float* Wv  = (const float*)d_in[1];
    const float* bv  = (const float*)d_in[2];
    const float* Wb  = (const float*)d_in[3];
    const float* bb  = (const float*)d_in[4];
    const float* Wg  = (const float*)d_in[5];
    const float* bg  = (const float*)d_in[6];
    const float* Wp  = (const float*)d_in[7];
    const float* bp  = (const float*)d_in[8];
    const float* ck  = (const float*)d_in[9];
    const float* cbv = (const float*)d_in[10];
    const float* mem = (const float*)d_in[11];
    float* out = (float*)d_out;
    (void)in_sizes; (void)n_in; (void)out_size;

    cudaFuncSetAttribute(wa_kernel, cudaFuncAttributeMaxDynamicSharedMemorySize, NR * 4);
    cudaFuncSetAttribute(pl_mma_kernel, cudaFuncAttributeMaxDynamicSharedMemorySize, PL_SMEM);
    cudaFuncSetAttribute(out_tc_kernel, cudaFuncAttributeMaxDynamicSharedMemorySize, O_SMEM);

    // order chosen so pl_mma_kernel is launch index 3 (ncu capture slot)
    xcat_kernel<<<NB * ND / 256, 256>>>(x);
    wcat_kernel<<<dim3(NR / 32, ND / 32), dim3(32, 8)>>>(Wp);
    heads_kernel<<<NB, 64>>>(x, Wv, bv, Wb, bb, Wg, bg);
    pl_mma_kernel<<<dim3(NR / 128, NB / 128), 256, PL_SMEM>>>(bp);
    mnh_kernel<<<NR / 256, 256>>>(mem);
    sim_tc_kernel<<<dim3(NR / 128, NB / 128), 256>>>();
    wa_kernel<<<NB, 1024, NR * 4>>>(ck, cbv);
    add_tc_kernel<<<NR / 64, 128>>>();
    mem2t_kernel<<<NR / 64, 256>>>(mem);
    pstats_kernel<<<NB, 1024>>>();
    out_tc_kernel<<<dim3(NSPLIT, NB / 128), 256, O_SMEM>>>();
    out_reduce<<<NB * NW / 256, 256>>>(out);
}

// round 10
// speedup vs baseline: 1.2781x; 1.2778x over previous
#include <cuda_runtime.h>
#include <cuda_bf16.h>
#include <cuda_fp16.h>
#include <math.h>
#include <cstdint>

#define NB 1024
#define ND 256
#define NR 16384
#define NW 64
#define NSPLIT 32
#define EPSF 1e-16f

// ---------------- scratch (no allocations allowed) ----------------
__device__ float g_sim[(size_t)NB * NR];   // beta*sim logits, then a (in place)
__device__ float g_pl [(size_t)NB * NR];   // p logits (raw fp32)
__device__ float g_v  [NB * NW];
__device__ float g_vn [NB];
__device__ float g_beta[NB];
__device__ float g_gamma[NB];
__device__ float g_mn [NR];
__device__ float g_part[(size_t)NSPLIT * NB * NW];
__device__ float g_add[(size_t)NR * NW];
__device__ float g_er [NR];
__device__ float g_pmx [NB];
__device__ float g_pinv[NB];
__device__ __half g_xh[(size_t)NB * ND];              // x in fp16
__device__ __half g_wt[(size_t)NR * ND];              // Wp^T in fp16 [r][k]
__device__ __nv_bfloat16 g_vh  [NB * NW];
__device__ __nv_bfloat16 g_memh[NR * NW];
__device__ __nv_bfloat16 g_m2h[(size_t)NW * NR];      // mem2^T hi  [w][r]
__device__ __nv_bfloat16 g_m2l[(size_t)NW * NR];      // mem2^T lo  [w][r]

__device__ __forceinline__ float softplus_f(float z) {
    return z > 0.f ? z + log1pf(expf(-z)) : log1pf(expf(z));
}
__device__ __forceinline__ uint32_t smem_u32(const void* p) {
    uint32_t a;
    asm("{ .reg .u64 t; cvta.to.shared.u64 t, %1; cvt.u32.u64 %0, t; }" : "=r"(a) : "l"(p));
    return a;
}
__device__ __forceinline__ void ldsm_x4(uint32_t& r0, uint32_t& r1, uint32_t& r2, uint32_t& r3,
                                        uint32_t addr) {
    asm volatile("ldmatrix.sync.aligned.m8n8.x4.shared.b16 {%0, %1, %2, %3}, [%4];"
                 : "=r"(r0), "=r"(r1), "=r"(r2), "=r"(r3) : "r"(addr));
}
__device__ __forceinline__ void ldsm_x4t(uint32_t& r0, uint32_t& r1, uint32_t& r2, uint32_t& r3,
                                         uint32_t addr) {
    asm volatile("ldmatrix.sync.aligned.m8n8.x4.trans.shared.b16 {%0, %1, %2, %3}, [%4];"
                 : "=r"(r0), "=r"(r1), "=r"(r2), "=r"(r3) : "r"(addr));
}
__device__ __forceinline__ void mma16816(float* d, const uint32_t* a, const uint32_t* b) {
    asm volatile(
        "mma.sync.aligned.m16n8k16.row.col.f32.bf16.bf16.f32 "
        "{%0, %1, %2, %3}, {%4, %5, %6, %7}, {%8, %9}, {%0, %1, %2, %3};"
        : "+f"(d[0]), "+f"(d[1]), "+f"(d[2]), "+f"(d[3])
        : "r"(a[0]), "r"(a[1]), "r"(a[2]), "r"(a[3]), "r"(b[0]), "r"(b[1]));
}
__device__ __forceinline__ void mma16816h(float* d, const uint32_t* a, const uint32_t* b) {
    asm volatile(
        "mma.sync.aligned.m16n8k16.row.col.f32.f16.f16.f32 "
        "{%0, %1, %2, %3}, {%4, %5, %6, %7}, {%8, %9}, {%0, %1, %2, %3};"
        : "+f"(d[0]), "+f"(d[1]), "+f"(d[2]), "+f"(d[3])
        : "r"(a[0]), "r"(a[1]), "r"(a[2]), "r"(a[3]), "r"(b[0]), "r"(b[1]));
}
__device__ __forceinline__ void cp_async16(uint32_t saddr, const void* g) {
    asm volatile("cp.async.cg.shared.global [%0], [%1], 16;" :: "r"(saddr), "l"(g));
}
#define CP_COMMIT() asm volatile("cp.async.commit_group;" ::: "memory")
#define CP_WAIT(n)  asm volatile("cp.async.wait_group %0;" :: "n"(n) : "memory")

// block reductions for 1024 threads (32 warps)
__device__ __forceinline__ float blk_max(float v, float* red) {
    int lane = threadIdx.x & 31, w = threadIdx.x >> 5;
    #pragma unroll
    for (int o = 16; o; o >>= 1) v = fmaxf(v, __shfl_xor_sync(0xffffffffu, v, o));
    if (!lane) red[w] = v;
    __syncthreads();
    if (w == 0) {
        v = red[lane];
        #pragma unroll
        for (int o = 16; o; o >>= 1) v = fmaxf(v, __shfl_xor_sync(0xffffffffu, v, o));
        if (!lane) red[0] = v;
    }
    __syncthreads();
    v = red[0];
    __syncthreads();
    return v;
}
__device__ __forceinline__ float blk_sum(float v, float* red) {
    int lane = threadIdx.x & 31, w = threadIdx.x >> 5;
    #pragma unroll
    for (int o = 16; o; o >>= 1) v += __shfl_xor_sync(0xffffffffu, v, o);
    if (!lane) red[w] = v;
    __syncthreads();
    if (w == 0) {
        v = red[lane];
        #pragma unroll
        for (int o = 16; o; o >>= 1) v += __shfl_xor_sync(0xffffffffu, v, o);
        if (!lane) red[0] = v;
    }
    __syncthreads();
    v = red[0];
    __syncthreads();
    return v;
}

// ---------------- K1: controller heads ----------------
__global__ void heads_kernel(const float* __restrict__ x,
                             const float* __restrict__ Wv, const float* __restrict__ bv,
                             const float* __restrict__ Wb, const float* __restrict__ bb,
                             const float* __restrict__ Wg, const float* __restrict__ bg) {
    int b = blockIdx.x, t = threadIdx.x;        // 64 threads
    __shared__ float xs[ND];
    __shared__ float red[64];
    for (int i = t; i < ND; i += 64) xs[i] = x[b * ND + i];
    __syncthreads();

    float acc = 0.f;
    #pragma unroll 8
    for (int d = 0; d < ND; ++d) acc = fmaf(xs[d], Wv[d * NW + t], acc);
    float pb = 0.f, pg = 0.f;
    for (int d = t; d < ND; d += 64) {
        pb = fmaf(xs[d], Wb[d], pb);
        pg = fmaf(xs[d], Wg[d], pg);
    }
    float v = acc + bv[t];
    g_v[b * NW + t] = v;
    g_vh[b * NW + t] = __float2bfloat16(v);

    red[t] = v * v; __syncthreads();
    for (int s = 32; s > 0; s >>= 1) { if (t < s) red[t] += red[t + s]; __syncthreads(); }
    if (t == 0) g_vn[b] = sqrtf(red[0]);
    __syncthreads();

    red[t] = pb; __syncthreads();
    for (int s = 32; s > 0; s >>= 1) { if (t < s) red[t] += red[t + s]; __syncthreads(); }
    if (t == 0) g_beta[b] = softplus_f(red[0] + bb[0]);
    __syncthreads();

    red[t] = pg; __syncthreads();
    for (int s = 32; s > 0; s >>= 1) { if (t < s) red[t] += red[t + s]; __syncthreads(); }
    if (t == 0) g_gamma[b] = 1.f + softplus_f(red[0] + bg[0]);
}

// ---------------- K0: memory row norms + bf16 convert (fused, one pass) --------
__global__ void mnh_kernel(const float* __restrict__ mem) {
    int r = blockIdx.x * blockDim.x + threadIdx.x;
    if (r >= NR) return;
    const float4* m4 = (const float4*)(mem + (size_t)r * NW);
    __nv_bfloat162* h2 = (__nv_bfloat162*)(g_memh + (size_t)r * NW);
    float s = 0.f;
    #pragma unroll
    for (int i = 0; i < NW / 4; ++i) {
        float4 t4 = m4[i];
        s += t4.x * t4.x + t4.y * t4.y + t4.z * t4.z + t4.w * t4.w;
        h2[i * 2]     = __float22bfloat162_rn(make_float2(t4.x, t4.y));
        h2[i * 2 + 1] = __float22bfloat162_rn(make_float2(t4.z, t4.w));
    }
    g_mn[r] = sqrtf(s);
}

// ---------------- K2: sim via HMMA bf16 ----------------
#define SLS 72
__global__ void __launch_bounds__(256, 2)
sim_tc_kernel() {
    __shared__ __nv_bfloat16 As[128][SLS];
    __shared__ __nv_bfloat16 Bs[128][SLS];
    int tid = threadIdx.x;
    int lane = tid & 31, wid = tid >> 5;
    int n0 = blockIdx.x * 128;    // r
    int b0 = blockIdx.y * 128;    // b
    int wm0 = (wid & 1) * 64;
    int wn0 = (wid >> 1) * 32;

    #pragma unroll
    for (int i = 0; i < 4; ++i) {
        int q = tid + i * 256;
        int row = q >> 3, seg = (q & 7) * 8;
        *(uint4*)&As[row][seg] = *(const uint4*)&g_vh[(size_t)(b0 + row) * NW + seg];
        *(uint4*)&Bs[row][seg] = *(const uint4*)&g_memh[(size_t)(n0 + row) * NW + seg];
    }
    __syncthreads();

    float d[4][4][4] = {};
    uint32_t as_base = smem_u32(&As[0][0]);
    uint32_t bs_base = smem_u32(&Bs[0][0]);
    int a_row = wm0 + (lane & 15);
    int a_kof = (lane >> 4) * 8;
    int b_rof = ((lane >> 4) * 8) + (lane & 7);
    int b_kof = ((lane >> 3) & 1) * 8;

    #pragma unroll
    for (int ks = 0; ks < 4; ++ks) {
        int k0 = ks * 16;
        uint32_t a[4][4];
        #pragma unroll
        for (int mi = 0; mi < 4; ++mi) {
            uint32_t addr = as_base + ((a_row + mi * 16) * SLS + k0 + a_kof) * 2;
            ldsm_x4(a[mi][0], a[mi][1], a[mi][2], a[mi][3], addr);
        }
        uint32_t bfr[2][4];
        #pragma unroll
        for (int nj = 0; nj < 2; ++nj) {
            uint32_t addr = bs_base + ((wn0 + nj * 16 + b_rof) * SLS + k0 + b_kof) * 2;
            ldsm_x4(bfr[nj][0], bfr[nj][1], bfr[nj][2], bfr[nj][3], addr);
        }
        #pragma unroll
        for (int mi = 0; mi < 4; ++mi)
            #pragma unroll
            for (int ni = 0; ni < 4; ++ni)
                mma16816(d[mi][ni], a[mi], &bfr[ni >> 1][(ni & 1) * 2]);
    }

    int gr = lane >> 2, gc = (lane & 3) * 2;
    #pragma unroll
    for (int mi = 0; mi < 4; ++mi) {
        int bi0 = b0 + wm0 + mi * 16 + gr;
        float s0 = g_beta[bi0] , n0v = g_vn[bi0];
        float s1 = g_beta[bi0 + 8], n1v = g_vn[bi0 + 8];
        #pragma unroll
        for (int ni = 0; ni < 4; ++ni) {
            int c = n0 + wn0 + ni * 8 + gc;
            float m0 = g_mn[c], m1 = g_mn[c + 1];
            *(float2*)&g_sim[(size_t)bi0 * NR + c] = make_float2(
                s0 * d[mi][ni][0] / (n0v * m0 + EPSF),
                s0 * d[mi][ni][1] / (n0v * m1 + EPSF));
            *(float2*)&g_sim[(size_t)(bi0 + 8) * NR + c] = make_float2(
                s1 * d[mi][ni][2] / (n1v * m0 + EPSF),
                s1 * d[mi][ni][3] / (n1v * m1 + EPSF));
        }
    }
}

// ---------------- K3: softmax -> conv(K=3) -> pow(gamma) -> renorm (float4) ---------
__global__ void wa_kernel(const float* __restrict__ conv_k, const float* __restrict__ conv_b) {
    extern __shared__ float ws[];
    __shared__ float red[32];
    int b = blockIdx.x, t = threadIdx.x;   // 1024 threads
    float* row = g_sim + (size_t)b * NR;

    float4 loc[4];
    float mx = -1e30f;
    #pragma unroll
    for (int i = 0; i < 4; ++i) {
        loc[i] = *(const float4*)&row[i * 4096 + t * 4];
        mx = fmaxf(mx, fmaxf(fmaxf(loc[i].x, loc[i].y), fmaxf(loc[i].z, loc[i].w)));
    }
    mx = blk_max(mx, red);

    float sum = 0.f;
    #pragma unroll
    for (int i = 0; i < 4; ++i) {
        float4 e;
        e.x = __expf(loc[i].x - mx); e.y = __expf(loc[i].y - mx);
        e.z = __expf(loc[i].z - mx); e.w = __expf(loc[i].w - mx);
        *(float4*)&ws[i * 4096 + t * 4] = e;
        sum += e.x + e.y + e.z + e.w;
    }
    sum = blk_sum(sum, red);
    float inv = 1.f / sum;

    float c0 = conv_k[0], c1 = conv_k[1], c2 = conv_k[2], cb = conv_b[0];
    float gam = g_gamma[b];
    float la[16];
    float asum = 0.f;
    #pragma unroll
    for (int i = 0; i < 4; ++i) {
        int base = i * 4096 + t * 4;
        #pragma unroll
        for (int c = 0; c < 4; ++c) {
            int r = base + c;
            float wl = (r > 0)      ? ws[r - 1] : 0.f;
            float wr = (r < NR - 1) ? ws[r + 1] : 0.f;
            float wc = fmaf(wl, c0, fmaf(ws[r], c1, wr * c2)) * inv + cb;
            float a = __powf(wc, gam);
            la[i * 4 + c] = a; asum += a;
        }
    }
    asum = blk_sum(asum, red);
    float invd = 1.f / (asum + (float)NR * EPSF);

    #pragma unroll
    for (int i = 0; i < 4; ++i) {
        float4 o;
        o.x = la[i * 4 + 0] * invd; o.y = la[i * 4 + 1] * invd;
        o.z = la[i * 4 + 2] * invd; o.w = la[i * 4 + 3] * invd;
        *(float4*)&row[i * 4096 + t * 4] = o;
    }
}

// ---------------- K4a: add/erase via HMMA bf16 (ldmatrix.trans) ----------------
#define ATS 72
__global__ void __launch_bounds__(128, 4)
add_tc_kernel() {
    __shared__ __nv_bfloat16 As[128][ATS];   // [b-local][r-local 64]
    __shared__ __nv_bfloat16 Vs[128][ATS];   // [b-local][w 64]
    int tid = threadIdx.x, lane = tid & 31, wid = tid >> 5;   // 4 warps
    int r0 = blockIdx.x * 64;
    float acc[8][4] = {};
    float acce[4] = {};
    uint32_t onesf[2] = {0x3F803F80u, 0x3F803F80u};
    uint32_t asb = smem_u32(&As[0][0]), vsb = smem_u32(&Vs[0][0]);
    int m0 = wid * 16;
    int lrow = (lane & 7) + ((lane & 16) >> 1);
    int lcol = lane & 8;

    for (int kb = 0; kb < NB; kb += 128) {
        #pragma unroll
        for (int i = 0; i < 16; ++i) {
            int q = tid + i * 128;
            int kk = q >> 4, c = (q & 15) * 4;
            float4 f = *(const float4*)&g_sim[(size_t)(kb + kk) * NR + r0 + c];
            *(__nv_bfloat162*)&As[kk][c]     = __float22bfloat162_rn(make_float2(f.x, f.y));
            *(__nv_bfloat162*)&As[kk][c + 2] = __float22bfloat162_rn(make_float2(f.z, f.w));
        }
        #pragma unroll
        for (int i = 0; i < 8; ++i) {
            int q = tid + i * 128;
            int kk = q >> 3, c = (q & 7) * 8;
            *(uint4*)&Vs[kk][c] = *(const uint4*)&g_vh[(kb + kk) * NW + c];
        }
        __syncthreads();

        #pragma unroll
        for (int ks = 0; ks < 8; ++ks) {
            int k0 = ks * 16;
            uint32_t a[4];
            ldsm_x4t(a[0], a[1], a[2], a[3],
                     asb + ((k0 + lrow) * ATS + m0 + lcol) * 2);
            uint32_t bfr[4][4];
            #pragma unroll
            for (int nj = 0; nj < 4; ++nj)
                ldsm_x4t(bfr[nj][0], bfr[nj][1], bfr[nj][2], bfr[nj][3],
                         vsb + ((k0 + lrow) * ATS + nj * 16 + lcol) * 2);
            #pragma unroll
            for (int nj = 0; nj < 4; ++nj) {
                uint32_t f1[2] = {bfr[nj][0], bfr[nj][2]};
                uint32_t f2[2] = {bfr[nj][1], bfr[nj][3]};
                mma16816(acc[nj * 2],     a, f1);
                mma16816(acc[nj * 2 + 1], a, f2);
            }
            mma16816(acce, a, onesf);
        }
        __syncthreads();
    }

    int gr = lane >> 2, gc = (lane & 3) * 2;
    int r = r0 + m0 + gr;
    #pragma unroll
    for (int nj = 0; nj < 8; ++nj) {
        int w = nj * 8 + gc;
        *(float2*)&g_add[(size_t)r * NW + w]       = make_float2(acc[nj][0], acc[nj][1]);
        *(float2*)&g_add[(size_t)(r + 8) * NW + w] = make_float2(acc[nj][2], acc[nj][3]);
    }
    if ((lane & 3) == 0) { g_er[r] = acce[0]; g_er[r + 8] = acce[2]; }
}

// ---------------- K4b: mem2 = mem*(1-er/B) + add/B, transpose + bf16 hi/lo ----------
__global__ void mem2t_kernel(const float* __restrict__ mem) {
    __shared__ float t[64][65];
    __shared__ float ev[64];
    int r0 = blockIdx.x * 64;
    int tid = threadIdx.x;
    const float invB = 1.f / (float)NB;

    if (tid < 64) ev[tid] = 1.f - g_er[r0 + tid] * invB;
    __syncthreads();

    #pragma unroll
    for (int i = 0; i < 16; ++i) {
        int q = tid + i * 256;
        int r = q >> 6, w = q & 63;
        t[r][w] = mem[(size_t)(r0 + r) * NW + w] * ev[r] + g_add[(size_t)(r0 + r) * NW + w] * invB;
    }
    __syncthreads();

    #pragma unroll
    for (int i = 0; i < 16; ++i) {
        int q = tid + i * 256;
        int w = q >> 6, r = q & 63;
        float f = t[r][w];
        __nv_bfloat16 h = __float2bfloat16(f);
        __nv_bfloat16 l = __float2bfloat16(f - __bfloat162float(h));
        g_m2h[(size_t)w * NR + r0 + r] = h;
        g_m2l[(size_t)w * NR + r0 + r] = l;
    }
}

// ---------------- prep: x -> fp16 ----------------
__global__ void xh_kernel(const float* __restrict__ x) {
    int i = blockIdx.x * 256 + threadIdx.x;    // over NB*ND/4 float4 slots
    float4 f = *(const float4*)&x[(size_t)i * 4];
    __half2 h0 = __floats2half2_rn(f.x, f.y);
    __half2 h1 = __floats2half2_rn(f.z, f.w);
    *(__half2*)&g_xh[(size_t)i * 4]     = h0;
    *(__half2*)&g_xh[(size_t)i * 4 + 2] = h1;
}

// ---------------- prep: Wp^T -> fp16 [r][k] ----------------
__global__ void wt_kernel(const float* __restrict__ Wp) {
    __shared__ float t[32][33];
    int n0 = blockIdx.x * 32, k0 = blockIdx.y * 32;
    int tx = threadIdx.x, ty = threadIdx.y;   // (32, 8)
    #pragma unroll
    for (int i = 0; i < 4; ++i)
        t[ty + 8 * i][tx] = Wp[(size_t)(k0 + ty + 8 * i) * NR + n0 + tx];
    __syncthreads();
    #pragma unroll
    for (int i = 0; i < 4; ++i) {
        int row = ty + 8 * i;
        g_wt[(size_t)(n0 + row) * ND + k0 + tx] = __float2half(t[tx][row]);
    }
}

// ---------------- K5: p logits = x @ Wp (fp16 HMMA, K=256), 3-stage cp.async ---------
#define PLS 40
#define PLK (ND / 32)
#define PSTG 3
#define PL_BUF (128 * PLS)
#define PL_SMEM (2 * PSTG * PL_BUF * 2)

__global__ void __launch_bounds__(256, 2)
pl_mma_kernel(const float* __restrict__ bp) {
    extern __shared__ __half plsm[];
    __half* As = plsm;                    // [PSTG][128][PLS]
    __half* Bs = plsm + PSTG * PL_BUF;    // [PSTG][128][PLS]
    int tid = threadIdx.x;
    int lane = tid & 31, wid = tid >> 5;          // 8 warps
    int n0 = blockIdx.x * 128;
    int b0 = blockIdx.y * 128;
    int wm0 = (wid & 3) * 32;
    int wn0 = (wid >> 2) * 64;

    uint32_t asb = smem_u32(As), bsb = smem_u32(Bs);
    const uint32_t bufB = PL_BUF * 2;

    int row0 = tid >> 2, seg0 = (tid & 3) * 8;
    int row1 = (tid + 256) >> 2, seg1 = (tid & 3) * 8;

    uint32_t a_sa0 = asb + (row0 * PLS + seg0) * 2;
    uint32_t a_sa1 = asb + (row1 * PLS + seg1) * 2;
    uint32_t b_sa0 = bsb + (row0 * PLS + seg0) * 2;
    uint32_t b_sa1 = bsb + (row1 * PLS + seg1) * 2;
    const __half* a_g0 = &g_xh[(size_t)(b0 + row0) * ND + seg0];
    const __half* a_g1 = &g_xh[(size_t)(b0 + row1) * ND + seg1];
    const __half* b_g0 = &g_wt[(size_t)(n0 + row0) * ND + seg0];
    const __half* b_g1 = &g_wt[(size_t)(n0 + row1) * ND + seg1];

    // prologue: stages 0 and 1
    #pragma unroll
    for (int s = 0; s < 2; ++s) {
        cp_async16(a_sa0 + s * bufB, a_g0 + s * 32);
        cp_async16(a_sa1 + s * bufB, a_g1 + s * 32);
        cp_async16(b_sa0 + s * bufB, b_g0 + s * 32);
        cp_async16(b_sa1 + s * bufB, b_g1 + s * 32);
        CP_COMMIT();
    }

    float acc[2][8][4] = {};
    int a_row = wm0 + (lane & 15);
    int a_kof = (lane >> 4) * 8;
    int b_rof = ((lane >> 4) * 8) + (lane & 7);
    int b_kof = ((lane >> 3) & 1) * 8;

    for (int kc = 0; kc < PLK; ++kc) {
        int cur = kc % PSTG;
        if (kc + 1 < PLK) CP_WAIT(1); else CP_WAIT(0);
        __syncthreads();

        if (kc + 2 < PLK) {
            int nxt = (kc + 2) % PSTG;
            int ko = (kc + 2) * 32;
            cp_async16(a_sa0 + nxt * bufB, a_g0 + ko);
            cp_async16(a_sa1 + nxt * bufB, a_g1 + ko);
            cp_async16(b_sa0 + nxt * bufB, b_g0 + ko);
            cp_async16(b_sa1 + nxt * bufB, b_g1 + ko);
            CP_COMMIT();
        }

        uint32_t abase = asb + cur * bufB;
        uint32_t bbase = bsb + cur * bufB;

        uint32_t a[2][2][4], bfr[2][4][4];
        #pragma unroll
        for (int mi = 0; mi < 2; ++mi)
            ldsm_x4(a[0][mi][0], a[0][mi][1], a[0][mi][2], a[0][mi][3],
                    abase + ((a_row + mi * 16) * PLS + a_kof) * 2);
        #pragma unroll
        for (int nj = 0; nj < 4; ++nj)
            ldsm_x4(bfr[0][nj][0], bfr[0][nj][1], bfr[0][nj][2], bfr[0][nj][3],
                    bbase + ((wn0 + nj * 16 + b_rof) * PLS + b_kof) * 2);

        #pragma unroll
        for (int ks = 0; ks < 2; ++ks) {
            int c = ks & 1, n = c ^ 1;
            if (ks + 1 < 2) {
                int k0 = (ks + 1) * 16;
                #pragma unroll
                for (int mi = 0; mi < 2; ++mi)
                    ldsm_x4(a[n][mi][0], a[n][mi][1], a[n][mi][2], a[n][mi][3],
                            abase + ((a_row + mi * 16) * PLS + k0 + a_kof) * 2);
                #pragma unroll
                for (int nj = 0; nj < 4; ++nj)
                    ldsm_x4(bfr[n][nj][0], bfr[n][nj][1], bfr[n][nj][2], bfr[n][nj][3],
                            bbase + ((wn0 + nj * 16 + b_rof) * PLS + k0 + b_kof) * 2);
            }
            #pragma unroll
            for (int mi = 0; mi < 2; ++mi)
                #pragma unroll
                for (int nj = 0; nj < 4; ++nj) {
                    mma16816h(acc[mi][nj * 2],     a[c][mi], &bfr[c][nj][0]);
                    mma16816h(acc[mi][nj * 2 + 1], a[c][mi], &bfr[c][nj][2]);
                }
        }
    }

    int gr = lane >> 2, gc = (lane & 3) * 2;
    #pragma unroll
    for (int mi = 0; mi < 2; ++mi) {
        int r1 = b0 + wm0 + mi * 16 + gr;
        #pragma unroll
        for (int j = 0; j < 8; ++j) {
            int c = n0 + wn0 + j * 8 + gc;
            float bpx = bp[c], bpy = bp[c + 1];
            *(float2*)&g_pl[(size_t)r1 * NR + c] =
                make_float2(acc[mi][j][0] + bpx, acc[mi][j][1] + bpy);
            *(float2*)&g_pl[(size_t)(r1 + 8) * NR + c] =
                make_float2(acc[mi][j][2] + bpx, acc[mi][j][3] + bpy);
        }
    }
}

// ---------------- K6: per-row softmax stats for p (float4) ----------------
__global__ void __launch_bounds__(1024, 2)
pstats_kernel() {
    __shared__ float red[32];
    int b = blockIdx.x, t = threadIdx.x;
    const float* row = g_pl + (size_t)b * NR;

    float4 loc[4];
    float mx = -1e30f;
    #pragma unroll
    for (int i = 0; i < 4; ++i) {
        loc[i] = *(const float4*)&row[i * 4096 + t * 4];
        mx = fmaxf(mx, fmaxf(fmaxf(loc[i].x, loc[i].y), fmaxf(loc[i].z, loc[i].w)));
    }
    mx = blk_max(mx, red);

    float sum = 0.f;
    #pragma unroll
    for (int i = 0; i < 4; ++i)
        sum += __expf(loc[i].x - mx) + __expf(loc[i].y - mx)
             + __expf(loc[i].z - mx) + __expf(loc[i].w - mx);
    sum = blk_sum(sum, red);

    if (t == 0) { g_pmx[b] = mx; g_pinv[b] = 1.f / sum; }
}

// ---------------- K7: out = softmax(pl) @ mem2 via HMMA hi/lo split ----------------
#define OLS 72
#define O_EH 0
#define O_EL (128 * OLS)
#define O_MH (256 * OLS)
#define O_ML (320 * OLS)
#define O_SMEM (384 * OLS * 2)

__global__ void __launch_bounds__(256, 2)
out_tc_kernel() {
    extern __shared__ __nv_bfloat16 osm[];
    __nv_bfloat16* EH = osm + O_EH;
    __nv_bfloat16* EL = osm + O_EL;
    __nv_bfloat16* MH = osm + O_MH;
    __nv_bfloat16* ML = osm + O_ML;
    int tid = threadIdx.x;
    int lane = tid & 31, wid = tid >> 5;
    int split = blockIdx.x;
    int b0 = blockIdx.y * 128;
    int kbase = split * (NR / NSPLIT);

    int la = tid >> 4, lb = tid & 15;
    float mxv[8], invv[8];
    #pragma unroll
    for (int i = 0; i < 8; ++i) {
        mxv[i]  = g_pmx[b0 + la + 16 * i];
        invv[i] = g_pinv[b0 + la + 16 * i];
    }
    int m_row0 = tid >> 3, m_seg0 = (tid & 7) * 8;
    int m_row1 = (tid + 256) >> 3, m_seg1 = (tid & 7) * 8;

    uint32_t ehb = smem_u32(EH), elb = smem_u32(EL);
    uint32_t mhb = smem_u32(MH), mlb = smem_u32(ML);

    float acc[8][4] = {};
    int a_row = wid * 16 + (lane & 15);
    int a_kof = (lane >> 4) * 8;
    int b_rof = ((lane >> 4) * 8) + (lane & 7);
    int b_kof = ((lane >> 3) & 1) * 8;

    for (int kg = kbase; kg < kbase + NR / NSPLIT; kg += 64) {
        #pragma unroll
        for (int i = 0; i < 8; ++i) {
            int row = la + 16 * i;
            float4 l4 = *(const float4*)&g_pl[(size_t)(b0 + row) * NR + kg + lb * 4];
            float e0 = __expf(l4.x - mxv[i]) * invv[i];
            float e1 = __expf(l4.y - mxv[i]) * invv[i];
            float e2 = __expf(l4.z - mxv[i]) * invv[i];
            float e3 = __expf(l4.w - mxv[i]) * invv[i];
            __nv_bfloat16 h0 = __float2bfloat16(e0), h1 = __float2bfloat16(e1);
            __nv_bfloat16 h2 = __float2bfloat16(e2), h3 = __float2bfloat16(e3);
            __nv_bfloat16 l0 = __float2bfloat16(e0 - __bfloat162float(h0));
            __nv_bfloat16 l1 = __float2bfloat16(e1 - __bfloat162float(h1));
            __nv_bfloat16 l2 = __float2bfloat16(e2 - __bfloat162float(h2));
            __nv_bfloat16 l3 = __float2bfloat16(e3 - __bfloat162float(h3));
            __nv_bfloat16* eh = &EH[row * OLS + lb * 4];
            __nv_bfloat16* el = &EL[row * OLS + lb * 4];
            eh[0] = h0; eh[1] = h1; eh[2] = h2; eh[3] = h3;
            el[0] = l0; el[1] = l1; el[2] = l2; el[3] = l3;
        }
        *(uint4*)&MH[m_row0 * OLS + m_seg0] = *(const uint4*)&g_m2h[(size_t)m_row0 * NR + kg + m_seg0];
        *(uint4*)&MH[m_row1 * OLS + m_seg1] = *(const uint4*)&g_m2h[(size_t)m_row1 * NR + kg + m_seg1];
        *(uint4*)&ML[m_row0 * OLS + m_seg0] = *(const uint4*)&g_m2l[(size_t)m_row0 * NR + kg + m_seg0];
        *(uint4*)&ML[m_row1 * OLS + m_seg1] = *(const uint4*)&g_m2l[(size_t)m_row1 * NR + kg + m_seg1];
        __syncthreads();

        #pragma unroll
        for (int ks = 0; ks < 4; ++ks) {
            int k0 = ks * 16;
            uint32_t ah[4], al[4];
            {
                uint32_t addr = ehb + (a_row * OLS + k0 + a_kof) * 2;
                ldsm_x4(ah[0], ah[1], ah[2], ah[3], addr);
                addr = elb + (a_row * OLS + k0 + a_kof) * 2;
                ldsm_x4(al[0], al[1], al[2], al[3], addr);
            }
            uint32_t bh[4][4], bl[4][4];
            #pragma unroll
            for (int g = 0; g < 4; ++g) {
                uint32_t addr = mhb + ((g * 16 + b_rof) * OLS + k0 + b_kof) * 2;
                ldsm_x4(bh[g][0], bh[g][1], bh[g][2], bh[g][3], addr);
                addr = mlb + ((g * 16 + b_rof) * OLS + k0 + b_kof) * 2;
                ldsm_x4(bl[g][0], bl[g][1], bl[g][2], bl[g][3], addr);
            }
            #pragma unroll
            for (int g = 0; g < 4; ++g) {
                mma16816(acc[g * 2],     ah, &bh[g][0]);
                mma16816(acc[g * 2 + 1], ah, &bh[g][2]);
                mma16816(acc[g * 2],     al, &bh[g][0]);
                mma16816(acc[g * 2 + 1], al, &bh[g][2]);
                mma16816(acc[g * 2],     ah, &bl[g][0]);
                mma16816(acc[g * 2 + 1], ah, &bl[g][2]);
            }
        }
        __syncthreads();
    }

    int gr = lane >> 2, gc = (lane & 3) * 2;
    int r1 = b0 + wid * 16 + gr;
    #pragma unroll
    for (int j = 0; j < 8; ++j) {
        int c = j * 8 + gc;
        *(float2*)&g_part[(size_t)split * (NB * NW) + (size_t)r1 * NW + c] =
            make_float2(acc[j][0], acc[j][1]);
        *(float2*)&g_part[(size_t)split * (NB * NW) + (size_t)(r1 + 8) * NW + c] =
            make_float2(acc[j][2], acc[j][3]);
    }
}

__global__ void out_reduce(float* __restrict__ out) {
    int i = blockIdx.x * blockDim.x + threadIdx.x;
    float s = 0.f;
    #pragma unroll
    for (int p = 0; p < NSPLIT; ++p) s += g_part[(size_t)p * (NB * NW) + i];
    out[i] = s;
}

// ---------------- launch ----------------
extern "C" void kernel_launch(void* const* d_in, const int* in_sizes, int n_in,
                              void* d_out, int out_size) {
    const float* x   = (const float*)d_in[0];
    const float* Wv  = (const float*)d_in[1];
    const float* bv  = (const float*)d_in[2];
    const float* Wb  = (const float*)d_in[3];
    const float* bb  = (const float*)d_in[4];
    const float* Wg  = (const float*)d_in[5];
    const float* bg  = (const float*)d_in[6];
    const float* Wp  = (const float*)d_in[7];
    const float* bp  = (const float*)d_in[8];
    const float* ck  = (const float*)d_in[9];
    const float* cbv = (const float*)d_in[10];
    const float* mem = (const float*)d_in[11];
    float* out = (float*)d_out;
    (void)in_sizes; (void)n_in; (void)out_size;

    cudaFuncSetAttribute(wa_kernel, cudaFuncAttributeMaxDynamicSharedMemorySize, NR * 4);
    cudaFuncSetAttribute(pl_mma_kernel, cudaFuncAttributeMaxDynamicSharedMemorySize, PL_SMEM);
    cudaFuncSetAttribute(out_tc_kernel, cudaFuncAttributeMaxDynamicSharedMemorySize, O_SMEM);

    // order chosen so pl_mma_kernel is launch index 3 (ncu capture slot)
    xh_kernel<<<NB * ND / 4 / 256, 256>>>(x);
    wt_kernel<<<dim3(NR / 32, ND / 32), dim3(32, 8)>>>(Wp);
    heads_kernel<<<NB, 64>>>(x, Wv, bv, Wb, bb, Wg, bg);
    pl_mma_kernel<<<dim3(NR / 128, NB / 128), 256, PL_SMEM>>>(bp);
    mnh_kernel<<<NR / 256, 256>>>(mem);
    sim_tc_kernel<<<dim3(NR / 128, NB / 128), 256>>>();
    wa_kernel<<<NB, 1024, NR * 4>>>(ck, cbv);
    add_tc_kernel<<<NR / 64, 128>>>();
    mem2t_kernel<<<NR / 64, 256>>>(mem);
    pstats_kernel<<<NB, 1024>>>();
    out_tc_kernel<<<dim3(NSPLIT, NB / 128), 256, O_SMEM>>>();
    out_reduce<<<NB * NW / 256, 256>>>(out);
}

// round 11
// speedup vs baseline: 1.3861x; 1.0845x over previous
#include <cuda_runtime.h>
#include <cuda_bf16.h>
#include <cuda_fp16.h>
#include <math.h>
#include <cstdint>

#define NB 1024
#define ND 256
#define NR 16384
#define NW 64
#define NSPLIT 32
#define EPSF 1e-16f

// ---------------- scratch (no allocations allowed) ----------------
__device__ __nv_bfloat16 g_simh[(size_t)NB * NR]; // sim logits (bf16), then a (in place)
__device__ __half g_plh[(size_t)NB * NR];         // p logits (fp16)
__device__ float g_v  [NB * NW];
__device__ float g_vn [NB];
__device__ float g_beta[NB];
__device__ float g_gamma[NB];
__device__ float g_mn [NR];
__device__ float g_part[(size_t)NSPLIT * NB * NW];
__device__ float g_add[(size_t)NR * NW];
__device__ float g_er [NR];
__device__ float g_pmx [NB];
__device__ float g_pinv[NB];
__device__ float g_psm[(size_t)NB * 128];         // per (row, n-tile) max
__device__ float g_pss[(size_t)NB * 128];         // per (row, n-tile) sumexp
__device__ __half g_xh[(size_t)NB * ND];          // x in fp16
__device__ __half g_wt[(size_t)NR * ND];          // Wp^T in fp16 [r][k]
__device__ __nv_bfloat16 g_vh  [NB * NW];
__device__ __nv_bfloat16 g_memh[NR * NW];
__device__ __nv_bfloat16 g_m2h[(size_t)NW * NR];  // mem2^T hi  [w][r]
__device__ __nv_bfloat16 g_m2l[(size_t)NW * NR];  // mem2^T lo  [w][r]

__device__ __forceinline__ float softplus_f(float z) {
    return z > 0.f ? z + log1pf(expf(-z)) : log1pf(expf(z));
}
__device__ __forceinline__ uint32_t smem_u32(const void* p) {
    uint32_t a;
    asm("{ .reg .u64 t; cvta.to.shared.u64 t, %1; cvt.u32.u64 %0, t; }" : "=r"(a) : "l"(p));
    return a;
}
__device__ __forceinline__ void ldsm_x4(uint32_t& r0, uint32_t& r1, uint32_t& r2, uint32_t& r3,
                                        uint32_t addr) {
    asm volatile("ldmatrix.sync.aligned.m8n8.x4.shared.b16 {%0, %1, %2, %3}, [%4];"
                 : "=r"(r0), "=r"(r1), "=r"(r2), "=r"(r3) : "r"(addr));
}
__device__ __forceinline__ void ldsm_x4t(uint32_t& r0, uint32_t& r1, uint32_t& r2, uint32_t& r3,
                                         uint32_t addr) {
    asm volatile("ldmatrix.sync.aligned.m8n8.x4.trans.shared.b16 {%0, %1, %2, %3}, [%4];"
                 : "=r"(r0), "=r"(r1), "=r"(r2), "=r"(r3) : "r"(addr));
}
__device__ __forceinline__ void mma16816(float* d, const uint32_t* a, const uint32_t* b) {
    asm volatile(
        "mma.sync.aligned.m16n8k16.row.col.f32.bf16.bf16.f32 "
        "{%0, %1, %2, %3}, {%4, %5, %6, %7}, {%8, %9}, {%0, %1, %2, %3};"
        : "+f"(d[0]), "+f"(d[1]), "+f"(d[2]), "+f"(d[3])
        : "r"(a[0]), "r"(a[1]), "r"(a[2]), "r"(a[3]), "r"(b[0]), "r"(b[1]));
}
__device__ __forceinline__ void mma16816h(float* d, const uint32_t* a, const uint32_t* b) {
    asm volatile(
        "mma.sync.aligned.m16n8k16.row.col.f32.f16.f16.f32 "
        "{%0, %1, %2, %3}, {%4, %5, %6, %7}, {%8, %9}, {%0, %1, %2, %3};"
        : "+f"(d[0]), "+f"(d[1]), "+f"(d[2]), "+f"(d[3])
        : "r"(a[0]), "r"(a[1]), "r"(a[2]), "r"(a[3]), "r"(b[0]), "r"(b[1]));
}
__device__ __forceinline__ void cp_async16(uint32_t saddr, const void* g) {
    asm volatile("cp.async.cg.shared.global [%0], [%1], 16;" :: "r"(saddr), "l"(g));
}
#define CP_COMMIT() asm volatile("cp.async.commit_group;" ::: "memory")
#define CP_WAIT(n)  asm volatile("cp.async.wait_group %0;" :: "n"(n) : "memory")

// block reductions for 1024 threads (32 warps)
__device__ __forceinline__ float blk_max(float v, float* red) {
    int lane = threadIdx.x & 31, w = threadIdx.x >> 5;
    #pragma unroll
    for (int o = 16; o; o >>= 1) v = fmaxf(v, __shfl_xor_sync(0xffffffffu, v, o));
    if (!lane) red[w] = v;
    __syncthreads();
    if (w == 0) {
        v = red[lane];
        #pragma unroll
        for (int o = 16; o; o >>= 1) v = fmaxf(v, __shfl_xor_sync(0xffffffffu, v, o));
        if (!lane) red[0] = v;
    }
    __syncthreads();
    v = red[0];
    __syncthreads();
    return v;
}
__device__ __forceinline__ float blk_sum(float v, float* red) {
    int lane = threadIdx.x & 31, w = threadIdx.x >> 5;
    #pragma unroll
    for (int o = 16; o; o >>= 1) v += __shfl_xor_sync(0xffffffffu, v, o);
    if (!lane) red[w] = v;
    __syncthreads();
    if (w == 0) {
        v = red[lane];
        #pragma unroll
        for (int o = 16; o; o >>= 1) v += __shfl_xor_sync(0xffffffffu, v, o);
        if (!lane) red[0] = v;
    }
    __syncthreads();
    v = red[0];
    __syncthreads();
    return v;
}

// ---------------- K1: controller heads ----------------
__global__ void heads_kernel(const float* __restrict__ x,
                             const float* __restrict__ Wv, const float* __restrict__ bv,
                             const float* __restrict__ Wb, const float* __restrict__ bb,
                             const float* __restrict__ Wg, const float* __restrict__ bg) {
    int b = blockIdx.x, t = threadIdx.x;        // 64 threads
    __shared__ float xs[ND];
    __shared__ float red[64];
    for (int i = t; i < ND; i += 64) xs[i] = x[b * ND + i];
    __syncthreads();

    float acc = 0.f;
    #pragma unroll 8
    for (int d = 0; d < ND; ++d) acc = fmaf(xs[d], Wv[d * NW + t], acc);
    float pb = 0.f, pg = 0.f;
    for (int d = t; d < ND; d += 64) {
        pb = fmaf(xs[d], Wb[d], pb);
        pg = fmaf(xs[d], Wg[d], pg);
    }
    float v = acc + bv[t];
    g_v[b * NW + t] = v;
    g_vh[b * NW + t] = __float2bfloat16(v);

    red[t] = v * v; __syncthreads();
    for (int s = 32; s > 0; s >>= 1) { if (t < s) red[t] += red[t + s]; __syncthreads(); }
    if (t == 0) g_vn[b] = sqrtf(red[0]);
    __syncthreads();

    red[t] = pb; __syncthreads();
    for (int s = 32; s > 0; s >>= 1) { if (t < s) red[t] += red[t + s]; __syncthreads(); }
    if (t == 0) g_beta[b] = softplus_f(red[0] + bb[0]);
    __syncthreads();

    red[t] = pg; __syncthreads();
    for (int s = 32; s > 0; s >>= 1) { if (t < s) red[t] += red[t + s]; __syncthreads(); }
    if (t == 0) g_gamma[b] = 1.f + softplus_f(red[0] + bg[0]);
}

// ---------------- K0: memory row norms + bf16 convert (fused, one pass) --------
__global__ void mnh_kernel(const float* __restrict__ mem) {
    int r = blockIdx.x * blockDim.x + threadIdx.x;
    if (r >= NR) return;
    const float4* m4 = (const float4*)(mem + (size_t)r * NW);
    __nv_bfloat162* h2 = (__nv_bfloat162*)(g_memh + (size_t)r * NW);
    float s = 0.f;
    #pragma unroll
    for (int i = 0; i < NW / 4; ++i) {
        float4 t4 = m4[i];
        s += t4.x * t4.x + t4.y * t4.y + t4.z * t4.z + t4.w * t4.w;
        h2[i * 2]     = __float22bfloat162_rn(make_float2(t4.x, t4.y));
        h2[i * 2 + 1] = __float22bfloat162_rn(make_float2(t4.z, t4.w));
    }
    g_mn[r] = sqrtf(s);
}

// ---------------- K2: sim via HMMA bf16 (bf16 logits out) ----------------
#define SLS 72
__global__ void __launch_bounds__(256, 2)
sim_tc_kernel() {
    __shared__ __nv_bfloat16 As[128][SLS];
    __shared__ __nv_bfloat16 Bs[128][SLS];
    int tid = threadIdx.x;
    int lane = tid & 31, wid = tid >> 5;
    int n0 = blockIdx.x * 128;    // r
    int b0 = blockIdx.y * 128;    // b
    int wm0 = (wid & 1) * 64;
    int wn0 = (wid >> 1) * 32;

    #pragma unroll
    for (int i = 0; i < 4; ++i) {
        int q = tid + i * 256;
        int row = q >> 3, seg = (q & 7) * 8;
        *(uint4*)&As[row][seg] = *(const uint4*)&g_vh[(size_t)(b0 + row) * NW + seg];
        *(uint4*)&Bs[row][seg] = *(const uint4*)&g_memh[(size_t)(n0 + row) * NW + seg];
    }
    __syncthreads();

    float d[4][4][4] = {};
    uint32_t as_base = smem_u32(&As[0][0]);
    uint32_t bs_base = smem_u32(&Bs[0][0]);
    int a_row = wm0 + (lane & 15);
    int a_kof = (lane >> 4) * 8;
    int b_rof = ((lane >> 4) * 8) + (lane & 7);
    int b_kof = ((lane >> 3) & 1) * 8;

    #pragma unroll
    for (int ks = 0; ks < 4; ++ks) {
        int k0 = ks * 16;
        uint32_t a[4][4];
        #pragma unroll
        for (int mi = 0; mi < 4; ++mi) {
            uint32_t addr = as_base + ((a_row + mi * 16) * SLS + k0 + a_kof) * 2;
            ldsm_x4(a[mi][0], a[mi][1], a[mi][2], a[mi][3], addr);
        }
        uint32_t bfr[2][4];
        #pragma unroll
        for (int nj = 0; nj < 2; ++nj) {
            uint32_t addr = bs_base + ((wn0 + nj * 16 + b_rof) * SLS + k0 + b_kof) * 2;
            ldsm_x4(bfr[nj][0], bfr[nj][1], bfr[nj][2], bfr[nj][3], addr);
        }
        #pragma unroll
        for (int mi = 0; mi < 4; ++mi)
            #pragma unroll
            for (int ni = 0; ni < 4; ++ni)
                mma16816(d[mi][ni], a[mi], &bfr[ni >> 1][(ni & 1) * 2]);
    }

    int gr = lane >> 2, gc = (lane & 3) * 2;
    #pragma unroll
    for (int mi = 0; mi < 4; ++mi) {
        int bi0 = b0 + wm0 + mi * 16 + gr;
        float s0 = g_beta[bi0] , n0v = g_vn[bi0];
        float s1 = g_beta[bi0 + 8], n1v = g_vn[bi0 + 8];
        #pragma unroll
        for (int ni = 0; ni < 4; ++ni) {
            int c = n0 + wn0 + ni * 8 + gc;
            float m0 = g_mn[c], m1 = g_mn[c + 1];
            *(__nv_bfloat162*)&g_simh[(size_t)bi0 * NR + c] =
                __float22bfloat162_rn(make_float2(
                    s0 * d[mi][ni][0] / (n0v * m0 + EPSF),
                    s0 * d[mi][ni][1] / (n0v * m1 + EPSF)));
            *(__nv_bfloat162*)&g_simh[(size_t)(bi0 + 8) * NR + c] =
                __float22bfloat162_rn(make_float2(
                    s1 * d[mi][ni][2] / (n1v * m0 + EPSF),
                    s1 * d[mi][ni][3] / (n1v * m1 + EPSF)));
        }
    }
}

// ---------------- K3: softmax -> conv(K=3) -> pow(gamma) -> renorm (bf16 I/O) -------
__global__ void wa_kernel(const float* __restrict__ conv_k, const float* __restrict__ conv_b) {
    extern __shared__ float ws[];
    __shared__ float red[32];
    int b = blockIdx.x, t = threadIdx.x;   // 1024 threads
    __nv_bfloat16* row = g_simh + (size_t)b * NR;

    float loc[16];
    float mx = -1e30f;
    #pragma unroll
    for (int i = 0; i < 2; ++i) {
        uint4 raw = *(const uint4*)&row[i * 8192 + t * 8];
        const __nv_bfloat162* p2 = (const __nv_bfloat162*)&raw;
        #pragma unroll
        for (int k = 0; k < 4; ++k) {
            float2 f = __bfloat1622float2(p2[k]);
            loc[i * 8 + 2 * k]     = f.x;
            loc[i * 8 + 2 * k + 1] = f.y;
            mx = fmaxf(mx, fmaxf(f.x, f.y));
        }
    }
    mx = blk_max(mx, red);

    float sum = 0.f;
    #pragma unroll
    for (int i = 0; i < 2; ++i)
        #pragma unroll
        for (int k = 0; k < 8; ++k) {
            float e = __expf(loc[i * 8 + k] - mx);
            ws[i * 8192 + t * 8 + k] = e;
            sum += e;
        }
    sum = blk_sum(sum, red);
    float inv = 1.f / sum;

    float c0 = conv_k[0], c1 = conv_k[1], c2 = conv_k[2], cb = conv_b[0];
    float gam = g_gamma[b];
    float la[16];
    float asum = 0.f;
    #pragma unroll
    for (int i = 0; i < 2; ++i)
        #pragma unroll
        for (int k = 0; k < 8; ++k) {
            int r = i * 8192 + t * 8 + k;
            float wl = (r > 0)      ? ws[r - 1] : 0.f;
            float wr = (r < NR - 1) ? ws[r + 1] : 0.f;
            float wc = fmaf(wl, c0, fmaf(ws[r], c1, wr * c2)) * inv + cb;
            float a = __powf(wc, gam);
            la[i * 8 + k] = a; asum += a;
        }
    asum = blk_sum(asum, red);
    float invd = 1.f / (asum + (float)NR * EPSF);

    #pragma unroll
    for (int i = 0; i < 2; ++i) {
        uint4 raw;
        __nv_bfloat162* p2 = (__nv_bfloat162*)&raw;
        #pragma unroll
        for (int k = 0; k < 4; ++k)
            p2[k] = __float22bfloat162_rn(make_float2(
                la[i * 8 + 2 * k] * invd, la[i * 8 + 2 * k + 1] * invd));
        *(uint4*)&row[i * 8192 + t * 8] = raw;
    }
}

// ---------------- K4a: add/erase via HMMA bf16 (bf16 a input) ----------------
#define ATS 72
__global__ void __launch_bounds__(128, 4)
add_tc_kernel() {
    __shared__ __nv_bfloat16 As[128][ATS];   // [b-local][r-local 64]
    __shared__ __nv_bfloat16 Vs[128][ATS];   // [b-local][w 64]
    int tid = threadIdx.x, lane = tid & 31, wid = tid >> 5;   // 4 warps
    int r0 = blockIdx.x * 64;
    float acc[8][4] = {};
    float acce[4] = {};
    uint32_t onesf[2] = {0x3F803F80u, 0x3F803F80u};
    uint32_t asb = smem_u32(&As[0][0]), vsb = smem_u32(&Vs[0][0]);
    int m0 = wid * 16;
    int lrow = (lane & 7) + ((lane & 16) >> 1);
    int lcol = lane & 8;

    for (int kb = 0; kb < NB; kb += 128) {
        #pragma unroll
        for (int i = 0; i < 8; ++i) {
            int q = tid + i * 128;
            int kk = q >> 3, c = (q & 7) * 8;
            *(uint4*)&As[kk][c] = *(const uint4*)&g_simh[(size_t)(kb + kk) * NR + r0 + c];
            *(uint4*)&Vs[kk][c] = *(const uint4*)&g_vh[(kb + kk) * NW + c];
        }
        __syncthreads();

        #pragma unroll
        for (int ks = 0; ks < 8; ++ks) {
            int k0 = ks * 16;
            uint32_t a[4];
            ldsm_x4t(a[0], a[1], a[2], a[3],
                     asb + ((k0 + lrow) * ATS + m0 + lcol) * 2);
            uint32_t bfr[4][4];
            #pragma unroll
            for (int nj = 0; nj < 4; ++nj)
                ldsm_x4t(bfr[nj][0], bfr[nj][1], bfr[nj][2], bfr[nj][3],
                         vsb + ((k0 + lrow) * ATS + nj * 16 + lcol) * 2);
            #pragma unroll
            for (int nj = 0; nj < 4; ++nj) {
                uint32_t f1[2] = {bfr[nj][0], bfr[nj][2]};
                uint32_t f2[2] = {bfr[nj][1], bfr[nj][3]};
                mma16816(acc[nj * 2],     a, f1);
                mma16816(acc[nj * 2 + 1], a, f2);
            }
            mma16816(acce, a, onesf);
        }
        __syncthreads();
    }

    int gr = lane >> 2, gc = (lane & 3) * 2;
    int r = r0 + m0 + gr;
    #pragma unroll
    for (int nj = 0; nj < 8; ++nj) {
        int w = nj * 8 + gc;
        *(float2*)&g_add[(size_t)r * NW + w]       = make_float2(acc[nj][0], acc[nj][1]);
        *(float2*)&g_add[(size_t)(r + 8) * NW + w] = make_float2(acc[nj][2], acc[nj][3]);
    }
    if ((lane & 3) == 0) { g_er[r] = acce[0]; g_er[r + 8] = acce[2]; }
}

// ---------------- K4b: mem2 = mem*(1-er/B) + add/B, transpose + bf16 hi/lo ----------
__global__ void mem2t_kernel(const float* __restrict__ mem) {
    __shared__ float t[64][65];
    __shared__ float ev[64];
    int r0 = blockIdx.x * 64;
    int tid = threadIdx.x;
    const float invB = 1.f / (float)NB;

    if (tid < 64) ev[tid] = 1.f - g_er[r0 + tid] * invB;
    __syncthreads();

    #pragma unroll
    for (int i = 0; i < 16; ++i) {
        int q = tid + i * 256;
        int r = q >> 6, w = q & 63;
        t[r][w] = mem[(size_t)(r0 + r) * NW + w] * ev[r] + g_add[(size_t)(r0 + r) * NW + w] * invB;
    }
    __syncthreads();

    #pragma unroll
    for (int i = 0; i < 16; ++i) {
        int q = tid + i * 256;
        int w = q >> 6, r = q & 63;
        float f = t[r][w];
        __nv_bfloat16 h = __float2bfloat16(f);
        __nv_bfloat16 l = __float2bfloat16(f - __bfloat162float(h));
        g_m2h[(size_t)w * NR + r0 + r] = h;
        g_m2l[(size_t)w * NR + r0 + r] = l;
    }
}

// ---------------- prep: x -> fp16 ----------------
__global__ void xh_kernel(const float* __restrict__ x) {
    int i = blockIdx.x * 256 + threadIdx.x;    // over NB*ND/4 float4 slots
    float4 f = *(const float4*)&x[(size_t)i * 4];
    __half2 h0 = __floats2half2_rn(f.x, f.y);
    __half2 h1 = __floats2half2_rn(f.z, f.w);
    *(__half2*)&g_xh[(size_t)i * 4]     = h0;
    *(__half2*)&g_xh[(size_t)i * 4 + 2] = h1;
}

// ---------------- prep: Wp^T -> fp16 [r][k] ----------------
__global__ void wt_kernel(const float* __restrict__ Wp) {
    __shared__ float t[32][33];
    int n0 = blockIdx.x * 32, k0 = blockIdx.y * 32;
    int tx = threadIdx.x, ty = threadIdx.y;   // (32, 8)
    #pragma unroll
    for (int i = 0; i < 4; ++i)
        t[ty + 8 * i][tx] = Wp[(size_t)(k0 + ty + 8 * i) * NR + n0 + tx];
    __syncthreads();
    #pragma unroll
    for (int i = 0; i < 4; ++i) {
        int row = ty + 8 * i;
        g_wt[(size_t)(n0 + row) * ND + k0 + tx] = __float2half(t[tx][row]);
    }
}

// ---------------- K5: p logits (fp16 HMMA, K=256) + fused per-tile softmax stats -----
#define PLS 40
#define PLK (ND / 32)
#define PSTG 3
#define PL_BUF (128 * PLS)
#define PL_SMEM (2 * PSTG * PL_BUF * 2)

__global__ void __launch_bounds__(256, 2)
pl_mma_kernel(const float* __restrict__ bp) {
    extern __shared__ __half plsm[];
    __half* As = plsm;                    // [PSTG][128][PLS]
    __half* Bs = plsm + PSTG * PL_BUF;    // [PSTG][128][PLS]
    __shared__ float s_mx[128][2];
    __shared__ float s_sm[128][2];
    int tid = threadIdx.x;
    int lane = tid & 31, wid = tid >> 5;          // 8 warps
    int n0 = blockIdx.x * 128;
    int b0 = blockIdx.y * 128;
    int wm0 = (wid & 3) * 32;
    int wn0 = (wid >> 2) * 64;
    int half_id = wid >> 2;

    uint32_t asb = smem_u32(As), bsb = smem_u32(Bs);
    const uint32_t bufB = PL_BUF * 2;

    int row0 = tid >> 2, seg0 = (tid & 3) * 8;
    int row1 = (tid + 256) >> 2, seg1 = (tid & 3) * 8;

    uint32_t a_sa0 = asb + (row0 * PLS + seg0) * 2;
    uint32_t a_sa1 = asb + (row1 * PLS + seg1) * 2;
    uint32_t b_sa0 = bsb + (row0 * PLS + seg0) * 2;
    uint32_t b_sa1 = bsb + (row1 * PLS + seg1) * 2;
    const __half* a_g0 = &g_xh[(size_t)(b0 + row0) * ND + seg0];
    const __half* a_g1 = &g_xh[(size_t)(b0 + row1) * ND + seg1];
    const __half* b_g0 = &g_wt[(size_t)(n0 + row0) * ND + seg0];
    const __half* b_g1 = &g_wt[(size_t)(n0 + row1) * ND + seg1];

    #pragma unroll
    for (int s = 0; s < 2; ++s) {
        cp_async16(a_sa0 + s * bufB, a_g0 + s * 32);
        cp_async16(a_sa1 + s * bufB, a_g1 + s * 32);
        cp_async16(b_sa0 + s * bufB, b_g0 + s * 32);
        cp_async16(b_sa1 + s * bufB, b_g1 + s * 32);
        CP_COMMIT();
    }

    float acc[2][8][4] = {};
    int a_row = wm0 + (lane & 15);
    int a_kof = (lane >> 4) * 8;
    int b_rof = ((lane >> 4) * 8) + (lane & 7);
    int b_kof = ((lane >> 3) & 1) * 8;

    for (int kc = 0; kc < PLK; ++kc) {
        int cur = kc % PSTG;
        if (kc + 1 < PLK) CP_WAIT(1); else CP_WAIT(0);
        __syncthreads();

        if (kc + 2 < PLK) {
            int nxt = (kc + 2) % PSTG;
            int ko = (kc + 2) * 32;
            cp_async16(a_sa0 + nxt * bufB, a_g0 + ko);
            cp_async16(a_sa1 + nxt * bufB, a_g1 + ko);
            cp_async16(b_sa0 + nxt * bufB, b_g0 + ko);
            cp_async16(b_sa1 + nxt * bufB, b_g1 + ko);
            CP_COMMIT();
        }

        uint32_t abase = asb + cur * bufB;
        uint32_t bbase = bsb + cur * bufB;

        uint32_t a[2][2][4], bfr[2][4][4];
        #pragma unroll
        for (int mi = 0; mi < 2; ++mi)
            ldsm_x4(a[0][mi][0], a[0][mi][1], a[0][mi][2], a[0][mi][3],
                    abase + ((a_row + mi * 16) * PLS + a_kof) * 2);
        #pragma unroll
        for (int nj = 0; nj < 4; ++nj)
            ldsm_x4(bfr[0][nj][0], bfr[0][nj][1], bfr[0][nj][2], bfr[0][nj][3],
                    bbase + ((wn0 + nj * 16 + b_rof) * PLS + b_kof) * 2);

        #pragma unroll
        for (int ks = 0; ks < 2; ++ks) {
            int c = ks & 1, n = c ^ 1;
            if (ks + 1 < 2) {
                int k0 = (ks + 1) * 16;
                #pragma unroll
                for (int mi = 0; mi < 2; ++mi)
                    ldsm_x4(a[n][mi][0], a[n][mi][1], a[n][mi][2], a[n][mi][3],
                            abase + ((a_row + mi * 16) * PLS + k0 + a_kof) * 2);
                #pragma unroll
                for (int nj = 0; nj < 4; ++nj)
                    ldsm_x4(bfr[n][nj][0], bfr[n][nj][1], bfr[n][nj][2], bfr[n][nj][3],
                            bbase + ((wn0 + nj * 16 + b_rof) * PLS + k0 + b_kof) * 2);
            }
            #pragma unroll
            for (int mi = 0; mi < 2; ++mi)
                #pragma unroll
                for (int nj = 0; nj < 4; ++nj) {
                    mma16816h(acc[mi][nj * 2],     a[c][mi], &bfr[c][nj][0]);
                    mma16816h(acc[mi][nj * 2 + 1], a[c][mi], &bfr[c][nj][2]);
                }
        }
    }

    // epilogue: bias, fp16 logit store, per-tile softmax partials
    int gr = lane >> 2, gc = (lane & 3) * 2;
    float bpv[8][2];
    #pragma unroll
    for (int j = 0; j < 8; ++j) {
        int c = n0 + wn0 + j * 8 + gc;
        bpv[j][0] = bp[c]; bpv[j][1] = bp[c + 1];
    }
    #pragma unroll
    for (int mi = 0; mi < 2; ++mi) {
        int rl = wm0 + mi * 16 + gr;
        int r1 = b0 + rl;
        float m0 = -1e30f, m1 = -1e30f;
        #pragma unroll
        for (int j = 0; j < 8; ++j) {
            float v0 = acc[mi][j][0] + bpv[j][0];
            float v1 = acc[mi][j][1] + bpv[j][1];
            float v2 = acc[mi][j][2] + bpv[j][0];
            float v3 = acc[mi][j][3] + bpv[j][1];
            acc[mi][j][0] = v0; acc[mi][j][1] = v1;
            acc[mi][j][2] = v2; acc[mi][j][3] = v3;
            int c = n0 + wn0 + j * 8 + gc;
            *(__half2*)&g_plh[(size_t)r1 * NR + c]       = __floats2half2_rn(v0, v1);
            *(__half2*)&g_plh[(size_t)(r1 + 8) * NR + c] = __floats2half2_rn(v2, v3);
            m0 = fmaxf(m0, fmaxf(v0, v1));
            m1 = fmaxf(m1, fmaxf(v2, v3));
        }
        #pragma unroll
        for (int o = 1; o <= 2; o <<= 1) {
            m0 = fmaxf(m0, __shfl_xor_sync(0xffffffffu, m0, o));
            m1 = fmaxf(m1, __shfl_xor_sync(0xffffffffu, m1, o));
        }
        float s0 = 0.f, s1 = 0.f;
        #pragma unroll
        for (int j = 0; j < 8; ++j) {
            s0 += __expf(acc[mi][j][0] - m0) + __expf(acc[mi][j][1] - m0);
            s1 += __expf(acc[mi][j][2] - m1) + __expf(acc[mi][j][3] - m1);
        }
        #pragma unroll
        for (int o = 1; o <= 2; o <<= 1) {
            s0 += __shfl_xor_sync(0xffffffffu, s0, o);
            s1 += __shfl_xor_sync(0xffffffffu, s1, o);
        }
        if ((lane & 3) == 0) {
            s_mx[rl][half_id] = m0; s_sm[rl][half_id] = s0;
            s_mx[rl + 8][half_id] = m1; s_sm[rl + 8][half_id] = s1;
        }
    }
    __syncthreads();
    if (tid < 128) {
        float ma = s_mx[tid][0], mb = s_mx[tid][1];
        float M = fmaxf(ma, mb);
        float S = s_sm[tid][0] * __expf(ma - M) + s_sm[tid][1] * __expf(mb - M);
        g_psm[(size_t)(b0 + tid) * 128 + blockIdx.x] = M;
        g_pss[(size_t)(b0 + tid) * 128 + blockIdx.x] = S;
    }
}

// ---------------- K6: combine per-tile softmax partials ----------------
__global__ void pcomb_kernel() {
    __shared__ float rm[4], rs[4];
    int b = blockIdx.x, t = threadIdx.x;   // 128 threads
    int lane = t & 31, w = t >> 5;
    float M = g_psm[(size_t)b * 128 + t];
    float S = g_pss[(size_t)b * 128 + t];
    float m = M;
    #pragma unroll
    for (int o = 16; o; o >>= 1) m = fmaxf(m, __shfl_xor_sync(0xffffffffu, m, o));
    if (!lane) rm[w] = m;
    __syncthreads();
    float Mg = fmaxf(fmaxf(rm[0], rm[1]), fmaxf(rm[2], rm[3]));
    float s = S * __expf(M - Mg);
    #pragma unroll
    for (int o = 16; o; o >>= 1) s += __shfl_xor_sync(0xffffffffu, s, o);
    if (!lane) rs[w] = s;
    __syncthreads();
    if (t == 0) { g_pmx[b] = Mg; g_pinv[b] = 1.f / (rs[0] + rs[1] + rs[2] + rs[3]); }
}

// ---------------- K7: out = softmax(pl) @ mem2 via HMMA hi/lo split ----------------
#define OLS 72
#define O_EH 0
#define O_EL (128 * OLS)
#define O_MH (256 * OLS)
#define O_ML (320 * OLS)
#define O_SMEM (384 * OLS * 2)

__global__ void __launch_bounds__(256, 2)
out_tc_kernel() {
    extern __shared__ __nv_bfloat16 osm[];
    __nv_bfloat16* EH = osm + O_EH;
    __nv_bfloat16* EL = osm + O_EL;
    __nv_bfloat16* MH = osm + O_MH;
    __nv_bfloat16* ML = osm + O_ML;
    int tid = threadIdx.x;
    int lane = tid & 31, wid = tid >> 5;
    int split = blockIdx.x;
    int b0 = blockIdx.y * 128;
    int kbase = split * (NR / NSPLIT);

    int la = tid >> 4, lb = tid & 15;
    float mxv[8], invv[8];
    #pragma unroll
    for (int i = 0; i < 8; ++i) {
        mxv[i]  = g_pmx[b0 + la + 16 * i];
        invv[i] = g_pinv[b0 + la + 16 * i];
    }
    int m_row0 = tid >> 3, m_seg0 = (tid & 7) * 8;
    int m_row1 = (tid + 256) >> 3, m_seg1 = (tid & 7) * 8;

    uint32_t ehb = smem_u32(EH), elb = smem_u32(EL);
    uint32_t mhb = smem_u32(MH), mlb = smem_u32(ML);

    float acc[8][4] = {};
    int a_row = wid * 16 + (lane & 15);
    int a_kof = (lane >> 4) * 8;
    int b_rof = ((lane >> 4) * 8) + (lane & 7);
    int b_kof = ((lane >> 3) & 1) * 8;

    for (int kg = kbase; kg < kbase + NR / NSPLIT; kg += 64) {
        #pragma unroll
        for (int i = 0; i < 8; ++i) {
            int row = la + 16 * i;
            const __half2* lp = (const __half2*)&g_plh[(size_t)(b0 + row) * NR + kg + lb * 4];
            float2 f01 = __half22float2(lp[0]);
            float2 f23 = __half22float2(lp[1]);
            float e0 = __expf(f01.x - mxv[i]) * invv[i];
            float e1 = __expf(f01.y - mxv[i]) * invv[i];
            float e2 = __expf(f23.x - mxv[i]) * invv[i];
            float e3 = __expf(f23.y - mxv[i]) * invv[i];
            __nv_bfloat16 h0 = __float2bfloat16(e0), h1 = __float2bfloat16(e1);
            __nv_bfloat16 h2 = __float2bfloat16(e2), h3 = __float2bfloat16(e3);
            __nv_bfloat16 l0 = __float2bfloat16(e0 - __bfloat162float(h0));
            __nv_bfloat16 l1 = __float2bfloat16(e1 - __bfloat162float(h1));
            __nv_bfloat16 l2 = __float2bfloat16(e2 - __bfloat162float(h2));
            __nv_bfloat16 l3 = __float2bfloat16(e3 - __bfloat162float(h3));
            __nv_bfloat16* eh = &EH[row * OLS + lb * 4];
            __nv_bfloat16* el = &EL[row * OLS + lb * 4];
            eh[0] = h0; eh[1] = h1; eh[2] = h2; eh[3] = h3;
            el[0] = l0; el[1] = l1; el[2] = l2; el[3] = l3;
        }
        *(uint4*)&MH[m_row0 * OLS + m_seg0] = *(const uint4*)&g_m2h[(size_t)m_row0 * NR + kg + m_seg0];
        *(uint4*)&MH[m_row1 * OLS + m_seg1] = *(const uint4*)&g_m2h[(size_t)m_row1 * NR + kg + m_seg1];
        *(uint4*)&ML[m_row0 * OLS + m_seg0] = *(const uint4*)&g_m2l[(size_t)m_row0 * NR + kg + m_seg0];
        *(uint4*)&ML[m_row1 * OLS + m_seg1] = *(const uint4*)&g_m2l[(size_t)m_row1 * NR + kg + m_seg1];
        __syncthreads();

        #pragma unroll
        for (int ks = 0; ks < 4; ++ks) {
            int k0 = ks * 16;
            uint32_t ah[4], al[4];
            {
                uint32_t addr = ehb + (a_row * OLS + k0 + a_kof) * 2;
                ldsm_x4(ah[0], ah[1], ah[2], ah[3], addr);
                addr = elb + (a_row * OLS + k0 + a_kof) * 2;
                ldsm_x4(al[0], al[1], al[2], al[3], addr);
            }
            uint32_t bh[4][4], bl[4][4];
            #pragma unroll
            for (int g = 0; g < 4; ++g) {
                uint32_t addr = mhb + ((g * 16 + b_rof) * OLS + k0 + b_kof) * 2;
                ldsm_x4(bh[g][0], bh[g][1], bh[g][2], bh[g][3], addr);
                addr = mlb + ((g * 16 + b_rof) * OLS + k0 + b_kof) * 2;
                ldsm_x4(bl[g][0], bl[g][1], bl[g][2], bl[g][3], addr);
            }
            #pragma unroll
            for (int g = 0; g < 4; ++g) {
                mma16816(acc[g * 2],     ah, &bh[g][0]);
                mma16816(acc[g * 2 + 1], ah, &bh[g][2]);
                mma16816(acc[g * 2],     al, &bh[g][0]);
                mma16816(acc[g * 2 + 1], al, &bh[g][2]);
                mma16816(acc[g * 2],     ah, &bl[g][0]);
                mma16816(acc[g * 2 + 1], ah, &bl[g][2]);
            }
        }
        __syncthreads();
    }

    int gr = lane >> 2, gc = (lane & 3) * 2;
    int r1 = b0 + wid * 16 + gr;
    #pragma unroll
    for (int j = 0; j < 8; ++j) {
        int c = j * 8 + gc;
        *(float2*)&g_part[(size_t)split * (NB * NW) + (size_t)r1 * NW + c] =
            make_float2(acc[j][0], acc[j][1]);
        *(float2*)&g_part[(size_t)split * (NB * NW) + (size_t)(r1 + 8) * NW + c] =
            make_float2(acc[j][2], acc[j][3]);
    }
}

__global__ void out_reduce(float* __restrict__ out) {
    int i = blockIdx.x * blockDim.x + threadIdx.x;
    float s = 0.f;
    #pragma unroll
    for (int p = 0; p < NSPLIT; ++p) s += g_part[(size_t)p * (NB * NW) + i];
    out[i] = s;
}

// ---------------- launch ----------------
extern "C" void kernel_launch(void* const* d_in, const int* in_sizes, int n_in,
                              void* d_out, int out_size) {
    const float* x   = (const float*)d_in[0];
    const float* Wv  = (const float*)d_in[1];
    const float* bv  = (const float*)d_in[2];
    const float* Wb  = (const float*)d_in[3];
    const float* bb  = (const float*)d_in[4];
    const float* Wg  = (const float*)d_in[5];
    const float* bg  = (const float*)d_in[6];
    const float* Wp  = (const float*)d_in[7];
    const float* bp  = (const float*)d_in[8];
    const float* ck  = (const float*)d_in[9];
    const float* cbv = (const float*)d_in[10];
    const float* mem = (const float*)d_in[11];
    float* out = (float*)d_out;
    (void)in_sizes; (void)n_in; (void)out_size;

    cudaFuncSetAttribute(wa_kernel, cudaFuncAttributeMaxDynamicSharedMemorySize, NR * 4);
    cudaFuncSetAttribute(pl_mma_kernel, cudaFuncAttributeMaxDynamicSharedMemorySize, PL_SMEM);
    cudaFuncSetAttribute(out_tc_kernel, cudaFuncAttributeMaxDynamicSharedMemorySize, O_SMEM);

    // order chosen so pl_mma_kernel is launch index 3 (ncu capture slot)
    xh_kernel<<<NB * ND / 4 / 256, 256>>>(x);
    wt_kernel<<<dim3(NR / 32, ND / 32), dim3(32, 8)>>>(Wp);
    heads_kernel<<<NB, 64>>>(x, Wv, bv, Wb, bb, Wg, bg);
    pl_mma_kernel<<<dim3(NR / 128, NB / 128), 256, PL_SMEM>>>(bp);
    pcomb_kernel<<<NB, 128>>>();
    mnh_kernel<<<NR / 256, 256>>>(mem);
    sim_tc_kernel<<<dim3(NR / 128, NB / 128), 256>>>();
    wa_kernel<<<NB, 1024, NR * 4>>>(ck, cbv);
    add_tc_kernel<<<NR / 64, 128>>>();
    mem2t_kernel<<<NR / 64, 256>>>(mem);
    out_tc_kernel<<<dim3(NSPLIT, NB / 128), 256, O_SMEM>>>();
    out_reduce<<<NB * NW / 256, 256>>>(out);
}

// round 12
// speedup vs baseline: 1.4625x; 1.0552x over previous
#include <cuda_runtime.h>
#include <cuda_bf16.h>
#include <cuda_fp16.h>
#include <math.h>
#include <cstdint>

#define NB 1024
#define ND 256
#define NR 16384
#define NW 64
#define NSPLIT 32
#define EPSF 1e-16f
#define ESCALE 2048.0f
#define EINV (1.0f / 2048.0f)

// ---------------- scratch (no allocations allowed) ----------------
__device__ __nv_bfloat16 g_simh[(size_t)NB * NR]; // sim logits (bf16), then a (in place)
__device__ __half g_plh[(size_t)NB * NR];         // p logits (fp16)
__device__ float g_v  [NB * NW];
__device__ float g_vn [NB];
__device__ float g_beta[NB];
__device__ float g_gamma[NB];
__device__ float g_mn [NR];
__device__ float g_part[(size_t)NSPLIT * NB * NW];
__device__ float g_add[(size_t)NR * NW];
__device__ float g_er [NR];
__device__ float g_pmx [NB];
__device__ float g_pinv[NB];
__device__ float g_psm[(size_t)NB * 128];         // per (row, n-tile) max
__device__ float g_pss[(size_t)NB * 128];         // per (row, n-tile) sumexp
__device__ __half g_xh[(size_t)NB * ND];          // x in fp16
__device__ __half g_wt[(size_t)NR * ND];          // Wp^T in fp16 [r][k]
__device__ __nv_bfloat16 g_vh  [NB * NW];
__device__ __nv_bfloat16 g_memh[NR * NW];
__device__ __half g_m2h[(size_t)NW * NR];         // mem2^T hi  [w][r] (fp16)
__device__ __half g_m2l[(size_t)NW * NR];         // mem2^T lo  [w][r] (fp16)

__device__ __forceinline__ float softplus_f(float z) {
    return z > 0.f ? z + log1pf(expf(-z)) : log1pf(expf(z));
}
__device__ __forceinline__ uint32_t smem_u32(const void* p) {
    uint32_t a;
    asm("{ .reg .u64 t; cvta.to.shared.u64 t, %1; cvt.u32.u64 %0, t; }" : "=r"(a) : "l"(p));
    return a;
}
__device__ __forceinline__ void ldsm_x4(uint32_t& r0, uint32_t& r1, uint32_t& r2, uint32_t& r3,
                                        uint32_t addr) {
    asm volatile("ldmatrix.sync.aligned.m8n8.x4.shared.b16 {%0, %1, %2, %3}, [%4];"
                 : "=r"(r0), "=r"(r1), "=r"(r2), "=r"(r3) : "r"(addr));
}
__device__ __forceinline__ void ldsm_x4t(uint32_t& r0, uint32_t& r1, uint32_t& r2, uint32_t& r3,
                                         uint32_t addr) {
    asm volatile("ldmatrix.sync.aligned.m8n8.x4.trans.shared.b16 {%0, %1, %2, %3}, [%4];"
                 : "=r"(r0), "=r"(r1), "=r"(r2), "=r"(r3) : "r"(addr));
}
__device__ __forceinline__ void mma16816(float* d, const uint32_t* a, const uint32_t* b) {
    asm volatile(
        "mma.sync.aligned.m16n8k16.row.col.f32.bf16.bf16.f32 "
        "{%0, %1, %2, %3}, {%4, %5, %6, %7}, {%8, %9}, {%0, %1, %2, %3};"
        : "+f"(d[0]), "+f"(d[1]), "+f"(d[2]), "+f"(d[3])
        : "r"(a[0]), "r"(a[1]), "r"(a[2]), "r"(a[3]), "r"(b[0]), "r"(b[1]));
}
__device__ __forceinline__ void mma16816h(float* d, const uint32_t* a, const uint32_t* b) {
    asm volatile(
        "mma.sync.aligned.m16n8k16.row.col.f32.f16.f16.f32 "
        "{%0, %1, %2, %3}, {%4, %5, %6, %7}, {%8, %9}, {%0, %1, %2, %3};"
        : "+f"(d[0]), "+f"(d[1]), "+f"(d[2]), "+f"(d[3])
        : "r"(a[0]), "r"(a[1]), "r"(a[2]), "r"(a[3]), "r"(b[0]), "r"(b[1]));
}
__device__ __forceinline__ void cp_async16(uint32_t saddr, const void* g) {
    asm volatile("cp.async.cg.shared.global [%0], [%1], 16;" :: "r"(saddr), "l"(g));
}
#define CP_COMMIT() asm volatile("cp.async.commit_group;" ::: "memory")
#define CP_WAIT(n)  asm volatile("cp.async.wait_group %0;" :: "n"(n) : "memory")

// block reductions for 1024 threads (32 warps)
__device__ __forceinline__ float blk_max(float v, float* red) {
    int lane = threadIdx.x & 31, w = threadIdx.x >> 5;
    #pragma unroll
    for (int o = 16; o; o >>= 1) v = fmaxf(v, __shfl_xor_sync(0xffffffffu, v, o));
    if (!lane) red[w] = v;
    __syncthreads();
    if (w == 0) {
        v = red[lane];
        #pragma unroll
        for (int o = 16; o; o >>= 1) v = fmaxf(v, __shfl_xor_sync(0xffffffffu, v, o));
        if (!lane) red[0] = v;
    }
    __syncthreads();
    v = red[0];
    __syncthreads();
    return v;
}
__device__ __forceinline__ float blk_sum(float v, float* red) {
    int lane = threadIdx.x & 31, w = threadIdx.x >> 5;
    #pragma unroll
    for (int o = 16; o; o >>= 1) v += __shfl_xor_sync(0xffffffffu, v, o);
    if (!lane) red[w] = v;
    __syncthreads();
    if (w == 0) {
        v = red[lane];
        #pragma unroll
        for (int o = 16; o; o >>= 1) v += __shfl_xor_sync(0xffffffffu, v, o);
        if (!lane) red[0] = v;
    }
    __syncthreads();
    v = red[0];
    __syncthreads();
    return v;
}

// ---------------- K1: controller heads ----------------
__global__ void heads_kernel(const float* __restrict__ x,
                             const float* __restrict__ Wv, const float* __restrict__ bv,
                             const float* __restrict__ Wb, const float* __restrict__ bb,
                             const float* __restrict__ Wg, const float* __restrict__ bg) {
    int b = blockIdx.x, t = threadIdx.x;        // 64 threads
    __shared__ float xs[ND];
    __shared__ float red[64];
    for (int i = t; i < ND; i += 64) xs[i] = x[b * ND + i];
    __syncthreads();

    float acc = 0.f;
    #pragma unroll 8
    for (int d = 0; d < ND; ++d) acc = fmaf(xs[d], Wv[d * NW + t], acc);
    float pb = 0.f, pg = 0.f;
    for (int d = t; d < ND; d += 64) {
        pb = fmaf(xs[d], Wb[d], pb);
        pg = fmaf(xs[d], Wg[d], pg);
    }
    float v = acc + bv[t];
    g_v[b * NW + t] = v;
    g_vh[b * NW + t] = __float2bfloat16(v);

    red[t] = v * v; __syncthreads();
    for (int s = 32; s > 0; s >>= 1) { if (t < s) red[t] += red[t + s]; __syncthreads(); }
    if (t == 0) g_vn[b] = sqrtf(red[0]);
    __syncthreads();

    red[t] = pb; __syncthreads();
    for (int s = 32; s > 0; s >>= 1) { if (t < s) red[t] += red[t + s]; __syncthreads(); }
    if (t == 0) g_beta[b] = softplus_f(red[0] + bb[0]);
    __syncthreads();

    red[t] = pg; __syncthreads();
    for (int s = 32; s > 0; s >>= 1) { if (t < s) red[t] += red[t + s]; __syncthreads(); }
    if (t == 0) g_gamma[b] = 1.f + softplus_f(red[0] + bg[0]);
}

// ---------------- K0: memory row norms + bf16 convert (fused, one pass) --------
__global__ void mnh_kernel(const float* __restrict__ mem) {
    int r = blockIdx.x * blockDim.x + threadIdx.x;
    if (r >= NR) return;
    const float4* m4 = (const float4*)(mem + (size_t)r * NW);
    __nv_bfloat162* h2 = (__nv_bfloat162*)(g_memh + (size_t)r * NW);
    float s = 0.f;
    #pragma unroll
    for (int i = 0; i < NW / 4; ++i) {
        float4 t4 = m4[i];
        s += t4.x * t4.x + t4.y * t4.y + t4.z * t4.z + t4.w * t4.w;
        h2[i * 2]     = __float22bfloat162_rn(make_float2(t4.x, t4.y));
        h2[i * 2 + 1] = __float22bfloat162_rn(make_float2(t4.z, t4.w));
    }
    g_mn[r] = sqrtf(s);
}

// ---------------- K2: sim via HMMA bf16 (bf16 logits out) ----------------
#define SLS 72
__global__ void __launch_bounds__(256, 2)
sim_tc_kernel() {
    __shared__ __nv_bfloat16 As[128][SLS];
    __shared__ __nv_bfloat16 Bs[128][SLS];
    int tid = threadIdx.x;
    int lane = tid & 31, wid = tid >> 5;
    int n0 = blockIdx.x * 128;    // r
    int b0 = blockIdx.y * 128;    // b
    int wm0 = (wid & 1) * 64;
    int wn0 = (wid >> 1) * 32;

    #pragma unroll
    for (int i = 0; i < 4; ++i) {
        int q = tid + i * 256;
        int row = q >> 3, seg = (q & 7) * 8;
        *(uint4*)&As[row][seg] = *(const uint4*)&g_vh[(size_t)(b0 + row) * NW + seg];
        *(uint4*)&Bs[row][seg] = *(const uint4*)&g_memh[(size_t)(n0 + row) * NW + seg];
    }
    __syncthreads();

    float d[4][4][4] = {};
    uint32_t as_base = smem_u32(&As[0][0]);
    uint32_t bs_base = smem_u32(&Bs[0][0]);
    int a_row = wm0 + (lane & 15);
    int a_kof = (lane >> 4) * 8;
    int b_rof = ((lane >> 4) * 8) + (lane & 7);
    int b_kof = ((lane >> 3) & 1) * 8;

    #pragma unroll
    for (int ks = 0; ks < 4; ++ks) {
        int k0 = ks * 16;
        uint32_t a[4][4];
        #pragma unroll
        for (int mi = 0; mi < 4; ++mi) {
            uint32_t addr = as_base + ((a_row + mi * 16) * SLS + k0 + a_kof) * 2;
            ldsm_x4(a[mi][0], a[mi][1], a[mi][2], a[mi][3], addr);
        }
        uint32_t bfr[2][4];
        #pragma unroll
        for (int nj = 0; nj < 2; ++nj) {
            uint32_t addr = bs_base + ((wn0 + nj * 16 + b_rof) * SLS + k0 + b_kof) * 2;
            ldsm_x4(bfr[nj][0], bfr[nj][1], bfr[nj][2], bfr[nj][3], addr);
        }
        #pragma unroll
        for (int mi = 0; mi < 4; ++mi)
            #pragma unroll
            for (int ni = 0; ni < 4; ++ni)
                mma16816(d[mi][ni], a[mi], &bfr[ni >> 1][(ni & 1) * 2]);
    }

    int gr = lane >> 2, gc = (lane & 3) * 2;
    #pragma unroll
    for (int mi = 0; mi < 4; ++mi) {
        int bi0 = b0 + wm0 + mi * 16 + gr;
        float s0 = g_beta[bi0] , n0v = g_vn[bi0];
        float s1 = g_beta[bi0 + 8], n1v = g_vn[bi0 + 8];
        #pragma unroll
        for (int ni = 0; ni < 4; ++ni) {
            int c = n0 + wn0 + ni * 8 + gc;
            float m0 = g_mn[c], m1 = g_mn[c + 1];
            *(__nv_bfloat162*)&g_simh[(size_t)bi0 * NR + c] =
                __float22bfloat162_rn(make_float2(
                    s0 * d[mi][ni][0] / (n0v * m0 + EPSF),
                    s0 * d[mi][ni][1] / (n0v * m1 + EPSF)));
            *(__nv_bfloat162*)&g_simh[(size_t)(bi0 + 8) * NR + c] =
                __float22bfloat162_rn(make_float2(
                    s1 * d[mi][ni][2] / (n1v * m0 + EPSF),
                    s1 * d[mi][ni][3] / (n1v * m1 + EPSF)));
        }
    }
}

// ---------------- K3: softmax -> conv(K=3) -> pow(gamma) -> renorm (bf16 I/O) -------
__global__ void wa_kernel(const float* __restrict__ conv_k, const float* __restrict__ conv_b) {
    extern __shared__ float ws[];
    __shared__ float red[32];
    int b = blockIdx.x, t = threadIdx.x;   // 1024 threads
    __nv_bfloat16* row = g_simh + (size_t)b * NR;

    float loc[16];
    float mx = -1e30f;
    #pragma unroll
    for (int i = 0; i < 2; ++i) {
        uint4 raw = *(const uint4*)&row[i * 8192 + t * 8];
        const __nv_bfloat162* p2 = (const __nv_bfloat162*)&raw;
        #pragma unroll
        for (int k = 0; k < 4; ++k) {
            float2 f = __bfloat1622float2(p2[k]);
            loc[i * 8 + 2 * k]     = f.x;
            loc[i * 8 + 2 * k + 1] = f.y;
            mx = fmaxf(mx, fmaxf(f.x, f.y));
        }
    }
    mx = blk_max(mx, red);

    float sum = 0.f;
    #pragma unroll
    for (int i = 0; i < 2; ++i)
        #pragma unroll
        for (int k = 0; k < 8; ++k) {
            float e = __expf(loc[i * 8 + k] - mx);
            ws[i * 8192 + t * 8 + k] = e;
            sum += e;
        }
    sum = blk_sum(sum, red);
    float inv = 1.f / sum;

    float c0 = conv_k[0], c1 = conv_k[1], c2 = conv_k[2], cb = conv_b[0];
    float gam = g_gamma[b];
    float la[16];
    float asum = 0.f;
    #pragma unroll
    for (int i = 0; i < 2; ++i)
        #pragma unroll
        for (int k = 0; k < 8; ++k) {
            int r = i * 8192 + t * 8 + k;
            float wl = (r > 0)      ? ws[r - 1] : 0.f;
            float wr = (r < NR - 1) ? ws[r + 1] : 0.f;
            float wc = fmaf(wl, c0, fmaf(ws[r], c1, wr * c2)) * inv + cb;
            float a = __powf(wc, gam);
            la[i * 8 + k] = a; asum += a;
        }
    asum = blk_sum(asum, red);
    float invd = 1.f / (asum + (float)NR * EPSF);

    #pragma unroll
    for (int i = 0; i < 2; ++i) {
        uint4 raw;
        __nv_bfloat162* p2 = (__nv_bfloat162*)&raw;
        #pragma unroll
        for (int k = 0; k < 4; ++k)
            p2[k] = __float22bfloat162_rn(make_float2(
                la[i * 8 + 2 * k] * invd, la[i * 8 + 2 * k + 1] * invd));
        *(uint4*)&row[i * 8192 + t * 8] = raw;
    }
}

// ---------------- K4a: add/erase via HMMA bf16 (bf16 a input) ----------------
#define ATS 72
__global__ void __launch_bounds__(128, 4)
add_tc_kernel() {
    __shared__ __nv_bfloat16 As[128][ATS];   // [b-local][r-local 64]
    __shared__ __nv_bfloat16 Vs[128][ATS];   // [b-local][w 64]
    int tid = threadIdx.x, lane = tid & 31, wid = tid >> 5;   // 4 warps
    int r0 = blockIdx.x * 64;
    float acc[8][4] = {};
    float acce[4] = {};
    uint32_t onesf[2] = {0x3F803F80u, 0x3F803F80u};
    uint32_t asb = smem_u32(&As[0][0]), vsb = smem_u32(&Vs[0][0]);
    int m0 = wid * 16;
    int lrow = (lane & 7) + ((lane & 16) >> 1);
    int lcol = lane & 8;

    for (int kb = 0; kb < NB; kb += 128) {
        #pragma unroll
        for (int i = 0; i < 8; ++i) {
            int q = tid + i * 128;
            int kk = q >> 3, c = (q & 7) * 8;
            *(uint4*)&As[kk][c] = *(const uint4*)&g_simh[(size_t)(kb + kk) * NR + r0 + c];
            *(uint4*)&Vs[kk][c] = *(const uint4*)&g_vh[(kb + kk) * NW + c];
        }
        __syncthreads();

        #pragma unroll
        for (int ks = 0; ks < 8; ++ks) {
            int k0 = ks * 16;
            uint32_t a[4];
            ldsm_x4t(a[0], a[1], a[2], a[3],
                     asb + ((k0 + lrow) * ATS + m0 + lcol) * 2);
            uint32_t bfr[4][4];
            #pragma unroll
            for (int nj = 0; nj < 4; ++nj)
                ldsm_x4t(bfr[nj][0], bfr[nj][1], bfr[nj][2], bfr[nj][3],
                         vsb + ((k0 + lrow) * ATS + nj * 16 + lcol) * 2);
            #pragma unroll
            for (int nj = 0; nj < 4; ++nj) {
                uint32_t f1[2] = {bfr[nj][0], bfr[nj][2]};
                uint32_t f2[2] = {bfr[nj][1], bfr[nj][3]};
                mma16816(acc[nj * 2],     a, f1);
                mma16816(acc[nj * 2 + 1], a, f2);
            }
            mma16816(acce, a, onesf);
        }
        __syncthreads();
    }

    int gr = lane >> 2, gc = (lane & 3) * 2;
    int r = r0 + m0 + gr;
    #pragma unroll
    for (int nj = 0; nj < 8; ++nj) {
        int w = nj * 8 + gc;
        *(float2*)&g_add[(size_t)r * NW + w]       = make_float2(acc[nj][0], acc[nj][1]);
        *(float2*)&g_add[(size_t)(r + 8) * NW + w] = make_float2(acc[nj][2], acc[nj][3]);
    }
    if ((lane & 3) == 0) { g_er[r] = acce[0]; g_er[r + 8] = acce[2]; }
}

// ---------------- K4b: mem2 = mem*(1-er/B) + add/B, transpose + fp16 hi/lo ----------
__global__ void mem2t_kernel(const float* __restrict__ mem) {
    __shared__ float t[64][65];
    __shared__ float ev[64];
    int r0 = blockIdx.x * 64;
    int tid = threadIdx.x;
    const float invB = 1.f / (float)NB;

    if (tid < 64) ev[tid] = 1.f - g_er[r0 + tid] * invB;
    __syncthreads();

    #pragma unroll
    for (int i = 0; i < 16; ++i) {
        int q = tid + i * 256;
        int r = q >> 6, w = q & 63;
        t[r][w] = mem[(size_t)(r0 + r) * NW + w] * ev[r] + g_add[(size_t)(r0 + r) * NW + w] * invB;
    }
    __syncthreads();

    #pragma unroll
    for (int i = 0; i < 16; ++i) {
        int q = tid + i * 256;
        int w = q >> 6, r = q & 63;
        float f = t[r][w];
        __half h = __float2half(f);
        __half l = __float2half(f - __half2float(h));
        g_m2h[(size_t)w * NR + r0 + r] = h;
        g_m2l[(size_t)w * NR + r0 + r] = l;
    }
}

// ---------------- prep: x -> fp16 ----------------
__global__ void xh_kernel(const float* __restrict__ x) {
    int i = blockIdx.x * 256 + threadIdx.x;    // over NB*ND/4 float4 slots
    float4 f = *(const float4*)&x[(size_t)i * 4];
    __half2 h0 = __floats2half2_rn(f.x, f.y);
    __half2 h1 = __floats2half2_rn(f.z, f.w);
    *(__half2*)&g_xh[(size_t)i * 4]     = h0;
    *(__half2*)&g_xh[(size_t)i * 4 + 2] = h1;
}

// ---------------- prep: Wp^T -> fp16 [r][k] ----------------
__global__ void wt_kernel(const float* __restrict__ Wp) {
    __shared__ float t[32][33];
    int n0 = blockIdx.x * 32, k0 = blockIdx.y * 32;
    int tx = threadIdx.x, ty = threadIdx.y;   // (32, 8)
    #pragma unroll
    for (int i = 0; i < 4; ++i)
        t[ty + 8 * i][tx] = Wp[(size_t)(k0 + ty + 8 * i) * NR + n0 + tx];
    __syncthreads();
    #pragma unroll
    for (int i = 0; i < 4; ++i) {
        int row = ty + 8 * i;
        g_wt[(size_t)(n0 + row) * ND + k0 + tx] = __float2half(t[tx][row]);
    }
}

// ---------------- K5: p logits (fp16 HMMA, K=256) + fused per-tile softmax stats -----
#define PLS 40
#define PLK (ND / 32)
#define PSTG 3
#define PL_BUF (128 * PLS)
#define PL_SMEM (2 * PSTG * PL_BUF * 2)

__global__ void __launch_bounds__(256, 2)
pl_mma_kernel(const float* __restrict__ bp) {
    extern __shared__ __half plsm[];
    __half* As = plsm;                    // [PSTG][128][PLS]
    __half* Bs = plsm + PSTG * PL_BUF;    // [PSTG][128][PLS]
    __shared__ float s_mx[128][2];
    __shared__ float s_sm[128][2];
    int tid = threadIdx.x;
    int lane = tid & 31, wid = tid >> 5;          // 8 warps
    int n0 = blockIdx.x * 128;
    int b0 = blockIdx.y * 128;
    int wm0 = (wid & 3) * 32;
    int wn0 = (wid >> 2) * 64;
    int half_id = wid >> 2;

    uint32_t asb = smem_u32(As), bsb = smem_u32(Bs);
    const uint32_t bufB = PL_BUF * 2;

    int row0 = tid >> 2, seg0 = (tid & 3) * 8;
    int row1 = (tid + 256) >> 2, seg1 = (tid & 3) * 8;

    uint32_t a_sa0 = asb + (row0 * PLS + seg0) * 2;
    uint32_t a_sa1 = asb + (row1 * PLS + seg1) * 2;
    uint32_t b_sa0 = bsb + (row0 * PLS + seg0) * 2;
    uint32_t b_sa1 = bsb + (row1 * PLS + seg1) * 2;
    const __half* a_g0 = &g_xh[(size_t)(b0 + row0) * ND + seg0];
    const __half* a_g1 = &g_xh[(size_t)(b0 + row1) * ND + seg1];
    const __half* b_g0 = &g_wt[(size_t)(n0 + row0) * ND + seg0];
    const __half* b_g1 = &g_wt[(size_t)(n0 + row1) * ND + seg1];

    #pragma unroll
    for (int s = 0; s < 2; ++s) {
        cp_async16(a_sa0 + s * bufB, a_g0 + s * 32);
        cp_async16(a_sa1 + s * bufB, a_g1 + s * 32);
        cp_async16(b_sa0 + s * bufB, b_g0 + s * 32);
        cp_async16(b_sa1 + s * bufB, b_g1 + s * 32);
        CP_COMMIT();
    }

    float acc[2][8][4] = {};
    int a_row = wm0 + (lane & 15);
    int a_kof = (lane >> 4) * 8;
    int b_rof = ((lane >> 4) * 8) + (lane & 7);
    int b_kof = ((lane >> 3) & 1) * 8;

    for (int kc = 0; kc < PLK; ++kc) {
        int cur = kc % PSTG;
        if (kc + 1 < PLK) CP_WAIT(1); else CP_WAIT(0);
        __syncthreads();

        if (kc + 2 < PLK) {
            int nxt = (kc + 2) % PSTG;
            int ko = (kc + 2) * 32;
            cp_async16(a_sa0 + nxt * bufB, a_g0 + ko);
            cp_async16(a_sa1 + nxt * bufB, a_g1 + ko);
            cp_async16(b_sa0 + nxt * bufB, b_g0 + ko);
            cp_async16(b_sa1 + nxt * bufB, b_g1 + ko);
            CP_COMMIT();
        }

        uint32_t abase = asb + cur * bufB;
        uint32_t bbase = bsb + cur * bufB;

        uint32_t a[2][2][4], bfr[2][4][4];
        #pragma unroll
        for (int mi = 0; mi < 2; ++mi)
            ldsm_x4(a[0][mi][0], a[0][mi][1], a[0][mi][2], a[0][mi][3],
                    abase + ((a_row + mi * 16) * PLS + a_kof) * 2);
        #pragma unroll
        for (int nj = 0; nj < 4; ++nj)
            ldsm_x4(bfr[0][nj][0], bfr[0][nj][1], bfr[0][nj][2], bfr[0][nj][3],
                    bbase + ((wn0 + nj * 16 + b_rof) * PLS + b_kof) * 2);

        #pragma unroll
        for (int ks = 0; ks < 2; ++ks) {
            int c = ks & 1, n = c ^ 1;
            if (ks + 1 < 2) {
                int k0 = (ks + 1) * 16;
                #pragma unroll
                for (int mi = 0; mi < 2; ++mi)
                    ldsm_x4(a[n][mi][0], a[n][mi][1], a[n][mi][2], a[n][mi][3],
                            abase + ((a_row + mi * 16) * PLS + k0 + a_kof) * 2);
                #pragma unroll
                for (int nj = 0; nj < 4; ++nj)
                    ldsm_x4(bfr[n][nj][0], bfr[n][nj][1], bfr[n][nj][2], bfr[n][nj][3],
                            bbase + ((wn0 + nj * 16 + b_rof) * PLS + k0 + b_kof) * 2);
            }
            #pragma unroll
            for (int mi = 0; mi < 2; ++mi)
                #pragma unroll
                for (int nj = 0; nj < 4; ++nj) {
                    mma16816h(acc[mi][nj * 2],     a[c][mi], &bfr[c][nj][0]);
                    mma16816h(acc[mi][nj * 2 + 1], a[c][mi], &bfr[c][nj][2]);
                }
        }
    }

    // epilogue: bias, fp16 logit store, per-tile softmax partials
    int gr = lane >> 2, gc = (lane & 3) * 2;
    float bpv[8][2];
    #pragma unroll
    for (int j = 0; j < 8; ++j) {
        int c = n0 + wn0 + j * 8 + gc;
        bpv[j][0] = bp[c]; bpv[j][1] = bp[c + 1];
    }
    #pragma unroll
    for (int mi = 0; mi < 2; ++mi) {
        int rl = wm0 + mi * 16 + gr;
        int r1 = b0 + rl;
        float m0 = -1e30f, m1 = -1e30f;
        #pragma unroll
        for (int j = 0; j < 8; ++j) {
            float v0 = acc[mi][j][0] + bpv[j][0];
            float v1 = acc[mi][j][1] + bpv[j][1];
            float v2 = acc[mi][j][2] + bpv[j][0];
            float v3 = acc[mi][j][3] + bpv[j][1];
            acc[mi][j][0] = v0; acc[mi][j][1] = v1;
            acc[mi][j][2] = v2; acc[mi][j][3] = v3;
            int c = n0 + wn0 + j * 8 + gc;
            *(__half2*)&g_plh[(size_t)r1 * NR + c]       = __floats2half2_rn(v0, v1);
            *(__half2*)&g_plh[(size_t)(r1 + 8) * NR + c] = __floats2half2_rn(v2, v3);
            m0 = fmaxf(m0, fmaxf(v0, v1));
            m1 = fmaxf(m1, fmaxf(v2, v3));
        }
        #pragma unroll
        for (int o = 1; o <= 2; o <<= 1) {
            m0 = fmaxf(m0, __shfl_xor_sync(0xffffffffu, m0, o));
            m1 = fmaxf(m1, __shfl_xor_sync(0xffffffffu, m1, o));
        }
        float s0 = 0.f, s1 = 0.f;
        #pragma unroll
        for (int j = 0; j < 8; ++j) {
            s0 += __expf(acc[mi][j][0] - m0) + __expf(acc[mi][j][1] - m0);
            s1 += __expf(acc[mi][j][2] - m1) + __expf(acc[mi][j][3] - m1);
        }
        #pragma unroll
        for (int o = 1; o <= 2; o <<= 1) {
            s0 += __shfl_xor_sync(0xffffffffu, s0, o);
            s1 += __shfl_xor_sync(0xffffffffu, s1, o);
        }
        if ((lane & 3) == 0) {
            s_mx[rl][half_id] = m0; s_sm[rl][half_id] = s0;
            s_mx[rl + 8][half_id] = m1; s_sm[rl + 8][half_id] = s1;
        }
    }
    __syncthreads();
    if (tid < 128) {
        float ma = s_mx[tid][0], mb = s_mx[tid][1];
        float M = fmaxf(ma, mb);
        float S = s_sm[tid][0] * __expf(ma - M) + s_sm[tid][1] * __expf(mb - M);
        g_psm[(size_t)(b0 + tid) * 128 + blockIdx.x] = M;
        g_pss[(size_t)(b0 + tid) * 128 + blockIdx.x] = S;
    }
}

// ---------------- K6: combine per-tile softmax partials ----------------
__global__ void pcomb_kernel() {
    __shared__ float rm[4], rs[4];
    int b = blockIdx.x, t = threadIdx.x;   // 128 threads
    int lane = t & 31, w = t >> 5;
    float M = g_psm[(size_t)b * 128 + t];
    float S = g_pss[(size_t)b * 128 + t];
    float m = M;
    #pragma unroll
    for (int o = 16; o; o >>= 1) m = fmaxf(m, __shfl_xor_sync(0xffffffffu, m, o));
    if (!lane) rm[w] = m;
    __syncthreads();
    float Mg = fmaxf(fmaxf(rm[0], rm[1]), fmaxf(rm[2], rm[3]));
    float s = S * __expf(M - Mg);
    #pragma unroll
    for (int o = 16; o; o >>= 1) s += __shfl_xor_sync(0xffffffffu, s, o);
    if (!lane) rs[w] = s;
    __syncthreads();
    if (t == 0) { g_pmx[b] = Mg; g_pinv[b] = 1.f / (rs[0] + rs[1] + rs[2] + rs[3]); }
}

// ---------------- K7: out = softmax(pl) @ mem2, scaled-fp16 e, fp16 hi/lo m2 --------
#define OLS 72
#define O_E  0
#define O_MH (128 * OLS)
#define O_ML (192 * OLS)
#define O_SMEM (256 * OLS * 2)

__global__ void __launch_bounds__(256, 2)
out_tc_kernel() {
    extern __shared__ __half osm[];
    __half* E  = osm + O_E;
    __half* MH = osm + O_MH;
    __half* ML = osm + O_ML;
    int tid = threadIdx.x;
    int lane = tid & 31, wid = tid >> 5;
    int split = blockIdx.x;
    int b0 = blockIdx.y * 128;
    int kbase = split * (NR / NSPLIT);

    int la = tid >> 4, lb = tid & 15;
    float mxv[8], invv[8];
    #pragma unroll
    for (int i = 0; i < 8; ++i) {
        mxv[i]  = g_pmx[b0 + la + 16 * i];
        invv[i] = g_pinv[b0 + la + 16 * i] * ESCALE;
    }
    int m_row0 = tid >> 3, m_seg0 = (tid & 7) * 8;
    int m_row1 = (tid + 256) >> 3, m_seg1 = (tid & 7) * 8;

    uint32_t eb = smem_u32(E);
    uint32_t mhb = smem_u32(MH), mlb = smem_u32(ML);

    float acc[8][4] = {};
    int a_row = wid * 16 + (lane & 15);
    int a_kof = (lane >> 4) * 8;
    int b_rof = ((lane >> 4) * 8) + (lane & 7);
    int b_kof = ((lane >> 3) & 1) * 8;

    for (int kg = kbase; kg < kbase + NR / NSPLIT; kg += 64) {
        #pragma unroll
        for (int i = 0; i < 8; ++i) {
            int row = la + 16 * i;
            const __half2* lp = (const __half2*)&g_plh[(size_t)(b0 + row) * NR + kg + lb * 4];
            float2 f01 = __half22float2(lp[0]);
            float2 f23 = __half22float2(lp[1]);
            float e0 = __expf(f01.x - mxv[i]) * invv[i];
            float e1 = __expf(f01.y - mxv[i]) * invv[i];
            float e2 = __expf(f23.x - mxv[i]) * invv[i];
            float e3 = __expf(f23.y - mxv[i]) * invv[i];
            __half2* ep = (__half2*)&E[row * OLS + lb * 4];
            ep[0] = __floats2half2_rn(e0, e1);
            ep[1] = __floats2half2_rn(e2, e3);
        }
        *(uint4*)&MH[m_row0 * OLS + m_seg0] = *(const uint4*)&g_m2h[(size_t)m_row0 * NR + kg + m_seg0];
        *(uint4*)&MH[m_row1 * OLS + m_seg1] = *(const uint4*)&g_m2h[(size_t)m_row1 * NR + kg + m_seg1];
        *(uint4*)&ML[m_row0 * OLS + m_seg0] = *(const uint4*)&g_m2l[(size_t)m_row0 * NR + kg + m_seg0];
        *(uint4*)&ML[m_row1 * OLS + m_seg1] = *(const uint4*)&g_m2l[(size_t)m_row1 * NR + kg + m_seg1];
        __syncthreads();

        #pragma unroll
        for (int ks = 0; ks < 4; ++ks) {
            int k0 = ks * 16;
            uint32_t a[4];
            ldsm_x4(a[0], a[1], a[2], a[3], eb + (a_row * OLS + k0 + a_kof) * 2);
            uint32_t bh[4][4], bl[4][4];
            #pragma unroll
            for (int g = 0; g < 4; ++g) {
                uint32_t addr = mhb + ((g * 16 + b_rof) * OLS + k0 + b_kof) * 2;
                ldsm_x4(bh[g][0], bh[g][1], bh[g][2], bh[g][3], addr);
                addr = mlb + ((g * 16 + b_rof) * OLS + k0 + b_kof) * 2;
                ldsm_x4(bl[g][0], bl[g][1], bl[g][2], bl[g][3], addr);
            }
            #pragma unroll
            for (int g = 0; g < 4; ++g) {
                mma16816h(acc[g * 2],     a, &bh[g][0]);
                mma16816h(acc[g * 2 + 1], a, &bh[g][2]);
                mma16816h(acc[g * 2],     a, &bl[g][0]);
                mma16816h(acc[g * 2 + 1], a, &bl[g][2]);
            }
        }
        __syncthreads();
    }

    int gr = lane >> 2, gc = (lane & 3) * 2;
    int r1 = b0 + wid * 16 + gr;
    #pragma unroll
    for (int j = 0; j < 8; ++j) {
        int c = j * 8 + gc;
        *(float2*)&g_part[(size_t)split * (NB * NW) + (size_t)r1 * NW + c] =
            make_float2(acc[j][0], acc[j][1]);
        *(float2*)&g_part[(size_t)split * (NB * NW) + (size_t)(r1 + 8) * NW + c] =
            make_float2(acc[j][2], acc[j][3]);
    }
}

__global__ void out_reduce(float* __restrict__ out) {
    int i = blockIdx.x * blockDim.x + threadIdx.x;
    float s = 0.f;
    #pragma unroll
    for (int p = 0; p < NSPLIT; ++p) s += g_part[(size_t)p * (NB * NW) + i];
    out[i] = s * EINV;
}

// ---------------- launch ----------------
extern "C" void kernel_launch(void* const* d_in, const int* in_sizes, int n_in,
                              void* d_out, int out_size) {
    const float* x   = (const float*)d_in[0];
    const float* Wv  = (const float*)d_in[1];
    const float* bv  = (const float*)d_in[2];
    const float* Wb  = (const float*)d_in[3];
    const float* bb  = (const float*)d_in[4];
    const float* Wg  = (const float*)d_in[5];
    const float* bg  = (const float*)d_in[6];
    const float* Wp  = (const float*)d_in[7];
    const float* bp  = (const float*)d_in[8];
    const float* ck  = (const float*)d_in[9];
    const float* cbv = (const float*)d_in[10];
    const float* mem = (const float*)d_in[11];
    float* out = (float*)d_out;
    (void)in_sizes; (void)n_in; (void)out_size;

    cudaFuncSetAttribute(wa_kernel, cudaFuncAttributeMaxDynamicSharedMemorySize, NR * 4);
    cudaFuncSetAttribute(pl_mma_kernel, cudaFuncAttributeMaxDynamicSharedMemorySize, PL_SMEM);
    cudaFuncSetAttribute(out_tc_kernel, cudaFuncAttributeMaxDynamicSharedMemorySize, O_SMEM);

    // order chosen so wa_kernel is launch index 3 (ncu capture slot)
    mnh_kernel<<<NR / 256, 256>>>(mem);
    heads_kernel<<<NB, 64>>>(x, Wv, bv, Wb, bb, Wg, bg);
    sim_tc_kernel<<<dim3(NR / 128, NB / 128), 256>>>();
    wa_kernel<<<NB, 1024, NR * 4>>>(ck, cbv);
    xh_kernel<<<NB * ND / 4 / 256, 256>>>(x);
    wt_kernel<<<dim3(NR / 32, ND / 32), dim3(32, 8)>>>(Wp);
    pl_mma_kernel<<<dim3(NR / 128, NB / 128), 256, PL_SMEM>>>(bp);
    pcomb_kernel<<<NB, 128>>>();
    add_tc_kernel<<<NR / 64, 128>>>();
    mem2t_kernel<<<NR / 64, 256>>>(mem);
    out_tc_kernel<<<dim3(NSPLIT, NB / 128), 256, O_SMEM>>>();
    out_reduce<<<NB * NW / 256, 256>>>(out);
}

// round 13
// speedup vs baseline: 1.5203x; 1.0395x over previous
#include <cuda_runtime.h>
#include <cuda_bf16.h>
#include <cuda_fp16.h>
#include <math.h>
#include <cstdint>

#define NB 1024
#define ND 256
#define NR 16384
#define NW 64
#define NSPLIT 32
#define EPSF 1e-16f
#define ESCALE 2048.0f
#define EINV (1.0f / 2048.0f)

// ---------------- scratch (no allocations allowed) ----------------
__device__ __nv_bfloat16 g_simh[(size_t)NB * NR]; // sim logits (bf16), then a (in place)
__device__ __half g_plh[(size_t)NB * NR];         // p logits (fp16)
__device__ float g_v  [NB * NW];
__device__ float g_vn [NB];
__device__ float g_beta[NB];
__device__ float g_gamma[NB];
__device__ float g_mn [NR];
__device__ float g_part[(size_t)NSPLIT * NB * NW];
__device__ float g_pmx [NB];
__device__ float g_pinv[NB];
__device__ float g_psm[(size_t)NB * 128];         // per (row, n-tile) max
__device__ float g_pss[(size_t)NB * 128];         // per (row, n-tile) sumexp
__device__ __half g_xh[(size_t)NB * ND];          // x in fp16
__device__ __half g_wt[(size_t)NR * ND];          // Wp^T in fp16 [r][k]
__device__ __nv_bfloat16 g_vh  [NB * NW];
__device__ __nv_bfloat16 g_memh[NR * NW];
__device__ __half g_m2h[(size_t)NW * NR];         // mem2^T hi  [w][r] (fp16)
__device__ __half g_m2l[(size_t)NW * NR];         // mem2^T lo  [w][r] (fp16)

__device__ __forceinline__ float softplus_f(float z) {
    return z > 0.f ? z + log1pf(expf(-z)) : log1pf(expf(z));
}
__device__ __forceinline__ uint32_t smem_u32(const void* p) {
    uint32_t a;
    asm("{ .reg .u64 t; cvta.to.shared.u64 t, %1; cvt.u32.u64 %0, t; }" : "=r"(a) : "l"(p));
    return a;
}
__device__ __forceinline__ void ldsm_x4(uint32_t& r0, uint32_t& r1, uint32_t& r2, uint32_t& r3,
                                        uint32_t addr) {
    asm volatile("ldmatrix.sync.aligned.m8n8.x4.shared.b16 {%0, %1, %2, %3}, [%4];"
                 : "=r"(r0), "=r"(r1), "=r"(r2), "=r"(r3) : "r"(addr));
}
__device__ __forceinline__ void ldsm_x4t(uint32_t& r0, uint32_t& r1, uint32_t& r2, uint32_t& r3,
                                         uint32_t addr) {
    asm volatile("ldmatrix.sync.aligned.m8n8.x4.trans.shared.b16 {%0, %1, %2, %3}, [%4];"
                 : "=r"(r0), "=r"(r1), "=r"(r2), "=r"(r3) : "r"(addr));
}
__device__ __forceinline__ void mma16816(float* d, const uint32_t* a, const uint32_t* b) {
    asm volatile(
        "mma.sync.aligned.m16n8k16.row.col.f32.bf16.bf16.f32 "
        "{%0, %1, %2, %3}, {%4, %5, %6, %7}, {%8, %9}, {%0, %1, %2, %3};"
        : "+f"(d[0]), "+f"(d[1]), "+f"(d[2]), "+f"(d[3])
        : "r"(a[0]), "r"(a[1]), "r"(a[2]), "r"(a[3]), "r"(b[0]), "r"(b[1]));
}
__device__ __forceinline__ void mma16816h(float* d, const uint32_t* a, const uint32_t* b) {
    asm volatile(
        "mma.sync.aligned.m16n8k16.row.col.f32.f16.f16.f32 "
        "{%0, %1, %2, %3}, {%4, %5, %6, %7}, {%8, %9}, {%0, %1, %2, %3};"
        : "+f"(d[0]), "+f"(d[1]), "+f"(d[2]), "+f"(d[3])
        : "r"(a[0]), "r"(a[1]), "r"(a[2]), "r"(a[3]), "r"(b[0]), "r"(b[1]));
}
__device__ __forceinline__ void cp_async16(uint32_t saddr, const void* g) {
    asm volatile("cp.async.cg.shared.global [%0], [%1], 16;" :: "r"(saddr), "l"(g));
}
#define CP_COMMIT() asm volatile("cp.async.commit_group;" ::: "memory")
#define CP_WAIT(n)  asm volatile("cp.async.wait_group %0;" :: "n"(n) : "memory")

// block reductions for 1024 threads (32 warps)
__device__ __forceinline__ float blk_max(float v, float* red) {
    int lane = threadIdx.x & 31, w = threadIdx.x >> 5;
    #pragma unroll
    for (int o = 16; o; o >>= 1) v = fmaxf(v, __shfl_xor_sync(0xffffffffu, v, o));
    if (!lane) red[w] = v;
    __syncthreads();
    if (w == 0) {
        v = red[lane];
        #pragma unroll
        for (int o = 16; o; o >>= 1) v = fmaxf(v, __shfl_xor_sync(0xffffffffu, v, o));
        if (!lane) red[0] = v;
    }
    __syncthreads();
    v = red[0];
    __syncthreads();
    return v;
}
__device__ __forceinline__ float blk_sum(float v, float* red) {
    int lane = threadIdx.x & 31, w = threadIdx.x >> 5;
    #pragma unroll
    for (int o = 16; o; o >>= 1) v += __shfl_xor_sync(0xffffffffu, v, o);
    if (!lane) red[w] = v;
    __syncthreads();
    if (w == 0) {
        v = red[lane];
        #pragma unroll
        for (int o = 16; o; o >>= 1) v += __shfl_xor_sync(0xffffffffu, v, o);
        if (!lane) red[0] = v;
    }
    __syncthreads();
    v = red[0];
    __syncthreads();
    return v;
}

// ---------------- K1: controller heads ----------------
__global__ void heads_kernel(const float* __restrict__ x,
                             const float* __restrict__ Wv, const float* __restrict__ bv,
                             const float* __restrict__ Wb, const float* __restrict__ bb,
                             const float* __restrict__ Wg, const float* __restrict__ bg) {
    int b = blockIdx.x, t = threadIdx.x;        // 64 threads
    __shared__ float xs[ND];
    __shared__ float red[64];
    for (int i = t; i < ND; i += 64) xs[i] = x[b * ND + i];
    __syncthreads();

    float acc = 0.f;
    #pragma unroll 8
    for (int d = 0; d < ND; ++d) acc = fmaf(xs[d], Wv[d * NW + t], acc);
    float pb = 0.f, pg = 0.f;
    for (int d = t; d < ND; d += 64) {
        pb = fmaf(xs[d], Wb[d], pb);
        pg = fmaf(xs[d], Wg[d], pg);
    }
    float v = acc + bv[t];
    g_v[b * NW + t] = v;
    g_vh[b * NW + t] = __float2bfloat16(v);

    red[t] = v * v; __syncthreads();
    for (int s = 32; s > 0; s >>= 1) { if (t < s) red[t] += red[t + s]; __syncthreads(); }
    if (t == 0) g_vn[b] = sqrtf(red[0]);
    __syncthreads();

    red[t] = pb; __syncthreads();
    for (int s = 32; s > 0; s >>= 1) { if (t < s) red[t] += red[t + s]; __syncthreads(); }
    if (t == 0) g_beta[b] = softplus_f(red[0] + bb[0]);
    __syncthreads();

    red[t] = pg; __syncthreads();
    for (int s = 32; s > 0; s >>= 1) { if (t < s) red[t] += red[t + s]; __syncthreads(); }
    if (t == 0) g_gamma[b] = 1.f + softplus_f(red[0] + bg[0]);
}

// ---------------- K0: memory row norms + bf16 convert (fused, one pass) --------
__global__ void mnh_kernel(const float* __restrict__ mem) {
    int r = blockIdx.x * blockDim.x + threadIdx.x;
    if (r >= NR) return;
    const float4* m4 = (const float4*)(mem + (size_t)r * NW);
    __nv_bfloat162* h2 = (__nv_bfloat162*)(g_memh + (size_t)r * NW);
    float s = 0.f;
    #pragma unroll
    for (int i = 0; i < NW / 4; ++i) {
        float4 t4 = m4[i];
        s += t4.x * t4.x + t4.y * t4.y + t4.z * t4.z + t4.w * t4.w;
        h2[i * 2]     = __float22bfloat162_rn(make_float2(t4.x, t4.y));
        h2[i * 2 + 1] = __float22bfloat162_rn(make_float2(t4.z, t4.w));
    }
    g_mn[r] = sqrtf(s);
}

// ---------------- K2: sim via HMMA bf16 (bf16 logits out) ----------------
#define SLS 72
__global__ void __launch_bounds__(256, 2)
sim_tc_kernel() {
    __shared__ __nv_bfloat16 As[128][SLS];
    __shared__ __nv_bfloat16 Bs[128][SLS];
    int tid = threadIdx.x;
    int lane = tid & 31, wid = tid >> 5;
    int n0 = blockIdx.x * 128;    // r
    int b0 = blockIdx.y * 128;    // b
    int wm0 = (wid & 1) * 64;
    int wn0 = (wid >> 1) * 32;

    #pragma unroll
    for (int i = 0; i < 4; ++i) {
        int q = tid + i * 256;
        int row = q >> 3, seg = (q & 7) * 8;
        *(uint4*)&As[row][seg] = *(const uint4*)&g_vh[(size_t)(b0 + row) * NW + seg];
        *(uint4*)&Bs[row][seg] = *(const uint4*)&g_memh[(size_t)(n0 + row) * NW + seg];
    }
    __syncthreads();

    float d[4][4][4] = {};
    uint32_t as_base = smem_u32(&As[0][0]);
    uint32_t bs_base = smem_u32(&Bs[0][0]);
    int a_row = wm0 + (lane & 15);
    int a_kof = (lane >> 4) * 8;
    int b_rof = ((lane >> 4) * 8) + (lane & 7);
    int b_kof = ((lane >> 3) & 1) * 8;

    #pragma unroll
    for (int ks = 0; ks < 4; ++ks) {
        int k0 = ks * 16;
        uint32_t a[4][4];
        #pragma unroll
        for (int mi = 0; mi < 4; ++mi) {
            uint32_t addr = as_base + ((a_row + mi * 16) * SLS + k0 + a_kof) * 2;
            ldsm_x4(a[mi][0], a[mi][1], a[mi][2], a[mi][3], addr);
        }
        uint32_t bfr[2][4];
        #pragma unroll
        for (int nj = 0; nj < 2; ++nj) {
            uint32_t addr = bs_base + ((wn0 + nj * 16 + b_rof) * SLS + k0 + b_kof) * 2;
            ldsm_x4(bfr[nj][0], bfr[nj][1], bfr[nj][2], bfr[nj][3], addr);
        }
        #pragma unroll
        for (int mi = 0; mi < 4; ++mi)
            #pragma unroll
            for (int ni = 0; ni < 4; ++ni)
                mma16816(d[mi][ni], a[mi], &bfr[ni >> 1][(ni & 1) * 2]);
    }

    int gr = lane >> 2, gc = (lane & 3) * 2;
    #pragma unroll
    for (int mi = 0; mi < 4; ++mi) {
        int bi0 = b0 + wm0 + mi * 16 + gr;
        float s0 = g_beta[bi0] , n0v = g_vn[bi0];
        float s1 = g_beta[bi0 + 8], n1v = g_vn[bi0 + 8];
        #pragma unroll
        for (int ni = 0; ni < 4; ++ni) {
            int c = n0 + wn0 + ni * 8 + gc;
            float m0 = g_mn[c], m1 = g_mn[c + 1];
            *(__nv_bfloat162*)&g_simh[(size_t)bi0 * NR + c] =
                __float22bfloat162_rn(make_float2(
                    s0 * d[mi][ni][0] / (n0v * m0 + EPSF),
                    s0 * d[mi][ni][1] / (n0v * m1 + EPSF)));
            *(__nv_bfloat162*)&g_simh[(size_t)(bi0 + 8) * NR + c] =
                __float22bfloat162_rn(make_float2(
                    s1 * d[mi][ni][2] / (n1v * m0 + EPSF),
                    s1 * d[mi][ni][3] / (n1v * m1 + EPSF)));
        }
    }
}

// ---------------- K3: softmax -> conv(K=3) -> pow(gamma) -> renorm (register conv) ---
__global__ void __launch_bounds__(1024, 2)
wa_kernel(const float* __restrict__ conv_k, const float* __restrict__ conv_b) {
    __shared__ float eL[2][1024];
    __shared__ float eR[2][1024];
    __shared__ float red[32];
    int b = blockIdx.x, t = threadIdx.x;   // 1024 threads, 2x8 contiguous elems each
    __nv_bfloat16* row = g_simh + (size_t)b * NR;

    float e[16];
    float mx = -1e30f;
    #pragma unroll
    for (int i = 0; i < 2; ++i) {
        uint4 raw = *(const uint4*)&row[i * 8192 + t * 8];
        const __nv_bfloat162* p2 = (const __nv_bfloat162*)&raw;
        #pragma unroll
        for (int k = 0; k < 4; ++k) {
            float2 f = __bfloat1622float2(p2[k]);
            e[i * 8 + 2 * k]     = f.x;
            e[i * 8 + 2 * k + 1] = f.y;
            mx = fmaxf(mx, fmaxf(f.x, f.y));
        }
    }
    mx = blk_max(mx, red);

    float sum = 0.f;
    #pragma unroll
    for (int k = 0; k < 16; ++k) {
        e[k] = __expf(e[k] - mx);
        sum += e[k];
    }
    eL[0][t] = e[0]; eR[0][t] = e[7];
    eL[1][t] = e[8]; eR[1][t] = e[15];
    sum = blk_sum(sum, red);   // contains __syncthreads -> edges visible
    float inv = 1.f / sum;

    float c0 = conv_k[0], c1 = conv_k[1], c2 = conv_k[2], cb = conv_b[0];
    float gam = g_gamma[b];
    float la[16];
    float asum = 0.f;
    #pragma unroll
    for (int i = 0; i < 2; ++i) {
        #pragma unroll
        for (int k = 0; k < 8; ++k) {
            int idx = i * 8 + k;
            float wl, wr;
            if (k > 0) wl = e[idx - 1];
            else if (i == 0) wl = (t > 0) ? eR[0][t - 1] : 0.f;
            else             wl = (t > 0) ? eR[1][t - 1] : eR[0][1023];
            if (k < 7) wr = e[idx + 1];
            else if (i == 0) wr = (t < 1023) ? eL[0][t + 1] : eL[1][0];
            else             wr = (t < 1023) ? eL[1][t + 1] : 0.f;
            float wc = fmaf(wl, c0, fmaf(e[idx], c1, wr * c2)) * inv + cb;
            float a = __powf(wc, gam);
            la[idx] = a; asum += a;
        }
    }
    asum = blk_sum(asum, red);
    float invd = 1.f / (asum + (float)NR * EPSF);

    #pragma unroll
    for (int i = 0; i < 2; ++i) {
        uint4 raw;
        __nv_bfloat162* p2 = (__nv_bfloat162*)&raw;
        #pragma unroll
        for (int k = 0; k < 4; ++k)
            p2[k] = __float22bfloat162_rn(make_float2(
                la[i * 8 + 2 * k] * invd, la[i * 8 + 2 * k + 1] * invd));
        *(uint4*)&row[i * 8192 + t * 8] = raw;
    }
}

// ---------------- K4: add/erase HMMA + fused mem2 build (transposed fp16 hi/lo) ------
#define ATS 72
__global__ void __launch_bounds__(128, 4)
addm2_kernel(const float* __restrict__ mem) {
    __shared__ __align__(16) __nv_bfloat16 As[128][ATS];   // overlaid with fp32 tile later
    __shared__ __nv_bfloat16 Vs[128][ATS];
    int tid = threadIdx.x, lane = tid & 31, wid = tid >> 5;   // 4 warps
    int r0 = blockIdx.x * 64;
    float acc[8][4] = {};
    float acce[4] = {};
    uint32_t onesf[2] = {0x3F803F80u, 0x3F803F80u};
    uint32_t asb = smem_u32(&As[0][0]), vsb = smem_u32(&Vs[0][0]);
    int m0 = wid * 16;
    int lrow = (lane & 7) + ((lane & 16) >> 1);
    int lcol = lane & 8;

    for (int kb = 0; kb < NB; kb += 128) {
        #pragma unroll
        for (int i = 0; i < 8; ++i) {
            int q = tid + i * 128;
            int kk = q >> 3, c = (q & 7) * 8;
            *(uint4*)&As[kk][c] = *(const uint4*)&g_simh[(size_t)(kb + kk) * NR + r0 + c];
            *(uint4*)&Vs[kk][c] = *(const uint4*)&g_vh[(kb + kk) * NW + c];
        }
        __syncthreads();

        #pragma unroll
        for (int ks = 0; ks < 8; ++ks) {
            int k0 = ks * 16;
            uint32_t a[4];
            ldsm_x4t(a[0], a[1], a[2], a[3],
                     asb + ((k0 + lrow) * ATS + m0 + lcol) * 2);
            uint32_t bfr[4][4];
            #pragma unroll
            for (int nj = 0; nj < 4; ++nj)
                ldsm_x4t(bfr[nj][0], bfr[nj][1], bfr[nj][2], bfr[nj][3],
                         vsb + ((k0 + lrow) * ATS + nj * 16 + lcol) * 2);
            #pragma unroll
            for (int nj = 0; nj < 4; ++nj) {
                uint32_t f1[2] = {bfr[nj][0], bfr[nj][2]};
                uint32_t f2[2] = {bfr[nj][1], bfr[nj][3]};
                mma16816(acc[nj * 2],     a, f1);
                mma16816(acc[nj * 2 + 1], a, f2);
            }
            mma16816(acce, a, onesf);
        }
        __syncthreads();
    }

    // fused mem2: every lane holds the row-sums (erase) for its two rows
    const float invB = 1.f / (float)NB;
    float ev0 = 1.f - acce[0] * invB;   // row m0+gr
    float ev1 = 1.f - acce[2] * invB;   // row m0+gr+8
    int gr = lane >> 2, gc = (lane & 3) * 2;
    int rA = m0 + gr, rB = m0 + gr + 8;

    float (*tbuf)[65] = (float(*)[65])&As[0][0];   // 64x65 fp32 = 16.6KB < As region
    #pragma unroll
    for (int nj = 0; nj < 8; ++nj) {
        int w = nj * 8 + gc;
        float2 ma = *(const float2*)&mem[(size_t)(r0 + rA) * NW + w];
        float2 mb = *(const float2*)&mem[(size_t)(r0 + rB) * NW + w];
        tbuf[rA][w]     = ma.x * ev0 + acc[nj][0] * invB;
        tbuf[rA][w + 1] = ma.y * ev0 + acc[nj][1] * invB;
        tbuf[rB][w]     = mb.x * ev1 + acc[nj][2] * invB;
        tbuf[rB][w + 1] = mb.y * ev1 + acc[nj][3] * invB;
    }
    __syncthreads();

    #pragma unroll
    for (int i = 0; i < 32; ++i) {
        int q = tid + i * 128;          // 0..4095
        int w = q >> 6, r = q & 63;
        float f = tbuf[r][w];
        __half h = __float2half(f);
        __half l = __float2half(f - __half2float(h));
        g_m2h[(size_t)w * NR + r0 + r] = h;
        g_m2l[(size_t)w * NR + r0 + r] = l;
    }
}

// ---------------- prep: x -> fp16 ----------------
__global__ void xh_kernel(const float* __restrict__ x) {
    int i = blockIdx.x * 256 + threadIdx.x;    // over NB*ND/4 float4 slots
    float4 f = *(const float4*)&x[(size_t)i * 4];
    __half2 h0 = __floats2half2_rn(f.x, f.y);
    __half2 h1 = __floats2half2_rn(f.z, f.w);
    *(__half2*)&g_xh[(size_t)i * 4]     = h0;
    *(__half2*)&g_xh[(size_t)i * 4 + 2] = h1;
}

// ---------------- prep: Wp^T -> fp16 [r][k] ----------------
__global__ void wt_kernel(const float* __restrict__ Wp) {
    __shared__ float t[32][33];
    int n0 = blockIdx.x * 32, k0 = blockIdx.y * 32;
    int tx = threadIdx.x, ty = threadIdx.y;   // (32, 8)
    #pragma unroll
    for (int i = 0; i < 4; ++i)
        t[ty + 8 * i][tx] = Wp[(size_t)(k0 + ty + 8 * i) * NR + n0 + tx];
    __syncthreads();
    #pragma unroll
    for (int i = 0; i < 4; ++i) {
        int row = ty + 8 * i;
        g_wt[(size_t)(n0 + row) * ND + k0 + tx] = __float2half(t[tx][row]);
    }
}

// ---------------- K5: p logits (fp16 HMMA, K=256) + fused per-tile softmax stats -----
#define PLS 40
#define PLK (ND / 32)
#define PSTG 3
#define PL_BUF (128 * PLS)
#define PL_SMEM (2 * PSTG * PL_BUF * 2)

__global__ void __launch_bounds__(256, 2)
pl_mma_kernel(const float* __restrict__ bp) {
    extern __shared__ __half plsm[];
    __half* As = plsm;                    // [PSTG][128][PLS]
    __half* Bs = plsm + PSTG * PL_BUF;    // [PSTG][128][PLS]
    __shared__ float s_mx[128][2];
    __shared__ float s_sm[128][2];
    int tid = threadIdx.x;
    int lane = tid & 31, wid = tid >> 5;          // 8 warps
    int n0 = blockIdx.x * 128;
    int b0 = blockIdx.y * 128;
    int wm0 = (wid & 3) * 32;
    int wn0 = (wid >> 2) * 64;
    int half_id = wid >> 2;

    uint32_t asb = smem_u32(As), bsb = smem_u32(Bs);
    const uint32_t bufB = PL_BUF * 2;

    int row0 = tid >> 2, seg0 = (tid & 3) * 8;
    int row1 = (tid + 256) >> 2, seg1 = (tid & 3) * 8;

    uint32_t a_sa0 = asb + (row0 * PLS + seg0) * 2;
    uint32_t a_sa1 = asb + (row1 * PLS + seg1) * 2;
    uint32_t b_sa0 = bsb + (row0 * PLS + seg0) * 2;
    uint32_t b_sa1 = bsb + (row1 * PLS + seg1) * 2;
    const __half* a_g0 = &g_xh[(size_t)(b0 + row0) * ND + seg0];
    const __half* a_g1 = &g_xh[(size_t)(b0 + row1) * ND + seg1];
    const __half* b_g0 = &g_wt[(size_t)(n0 + row0) * ND + seg0];
    const __half* b_g1 = &g_wt[(size_t)(n0 + row1) * ND + seg1];

    #pragma unroll
    for (int s = 0; s < 2; ++s) {
        cp_async16(a_sa0 + s * bufB, a_g0 + s * 32);
        cp_async16(a_sa1 + s * bufB, a_g1 + s * 32);
        cp_async16(b_sa0 + s * bufB, b_g0 + s * 32);
        cp_async16(b_sa1 + s * bufB, b_g1 + s * 32);
        CP_COMMIT();
    }

    float acc[2][8][4] = {};
    int a_row = wm0 + (lane & 15);
    int a_kof = (lane >> 4) * 8;
    int b_rof = ((lane >> 4) * 8) + (lane & 7);
    int b_kof = ((lane >> 3) & 1) * 8;

    for (int kc = 0; kc < PLK; ++kc) {
        int cur = kc % PSTG;
        if (kc + 1 < PLK) CP_WAIT(1); else CP_WAIT(0);
        __syncthreads();

        if (kc + 2 < PLK) {
            int nxt = (kc + 2) % PSTG;
            int ko = (kc + 2) * 32;
            cp_async16(a_sa0 + nxt * bufB, a_g0 + ko);
            cp_async16(a_sa1 + nxt * bufB, a_g1 + ko);
            cp_async16(b_sa0 + nxt * bufB, b_g0 + ko);
            cp_async16(b_sa1 + nxt * bufB, b_g1 + ko);
            CP_COMMIT();
        }

        uint32_t abase = asb + cur * bufB;
        uint32_t bbase = bsb + cur * bufB;

        uint32_t a[2][2][4], bfr[2][4][4];
        #pragma unroll
        for (int mi = 0; mi < 2; ++mi)
            ldsm_x4(a[0][mi][0], a[0][mi][1], a[0][mi][2], a[0][mi][3],
                    abase + ((a_row + mi * 16) * PLS + a_kof) * 2);
        #pragma unroll
        for (int nj = 0; nj < 4; ++nj)
            ldsm_x4(bfr[0][nj][0], bfr[0][nj][1], bfr[0][nj][2], bfr[0][nj][3],
                    bbase + ((wn0 + nj * 16 + b_rof) * PLS + b_kof) * 2);

        #pragma unroll
        for (int ks = 0; ks < 2; ++ks) {
            int c = ks & 1, n = c ^ 1;
            if (ks + 1 < 2) {
                int k0 = (ks + 1) * 16;
                #pragma unroll
                for (int mi = 0; mi < 2; ++mi)
                    ldsm_x4(a[n][mi][0], a[n][mi][1], a[n][mi][2], a[n][mi][3],
                            abase + ((a_row + mi * 16) * PLS + k0 + a_kof) * 2);
                #pragma unroll
                for (int nj = 0; nj < 4; ++nj)
                    ldsm_x4(bfr[n][nj][0], bfr[n][nj][1], bfr[n][nj][2], bfr[n][nj][3],
                            bbase + ((wn0 + nj * 16 + b_rof) * PLS + k0 + b_kof) * 2);
            }
            #pragma unroll
            for (int mi = 0; mi < 2; ++mi)
                #pragma unroll
                for (int nj = 0; nj < 4; ++nj) {
                    mma16816h(acc[mi][nj * 2],     a[c][mi], &bfr[c][nj][0]);
                    mma16816h(acc[mi][nj * 2 + 1], a[c][mi], &bfr[c][nj][2]);
                }
        }
    }

    // epilogue: bias, fp16 logit store, per-tile softmax partials
    int gr = lane >> 2, gc = (lane & 3) * 2;
    float bpv[8][2];
    #pragma unroll
    for (int j = 0; j < 8; ++j) {
        int c = n0 + wn0 + j * 8 + gc;
        bpv[j][0] = bp[c]; bpv[j][1] = bp[c + 1];
    }
    #pragma unroll
    for (int mi = 0; mi < 2; ++mi) {
        int rl = wm0 + mi * 16 + gr;
        int r1 = b0 + rl;
        float m0 = -1e30f, m1 = -1e30f;
        #pragma unroll
        for (int j = 0; j < 8; ++j) {
            float v0 = acc[mi][j][0] + bpv[j][0];
            float v1 = acc[mi][j][1] + bpv[j][1];
            float v2 = acc[mi][j][2] + bpv[j][0];
            float v3 = acc[mi][j][3] + bpv[j][1];
            acc[mi][j][0] = v0; acc[mi][j][1] = v1;
            acc[mi][j][2] = v2; acc[mi][j][3] = v3;
            int c = n0 + wn0 + j * 8 + gc;
            *(__half2*)&g_plh[(size_t)r1 * NR + c]       = __floats2half2_rn(v0, v1);
            *(__half2*)&g_plh[(size_t)(r1 + 8) * NR + c] = __floats2half2_rn(v2, v3);
            m0 = fmaxf(m0, fmaxf(v0, v1));
            m1 = fmaxf(m1, fmaxf(v2, v3));
        }
        #pragma unroll
        for (int o = 1; o <= 2; o <<= 1) {
            m0 = fmaxf(m0, __shfl_xor_sync(0xffffffffu, m0, o));
            m1 = fmaxf(m1, __shfl_xor_sync(0xffffffffu, m1, o));
        }
        float s0 = 0.f, s1 = 0.f;
        #pragma unroll
        for (int j = 0; j < 8; ++j) {
            s0 += __expf(acc[mi][j][0] - m0) + __expf(acc[mi][j][1] - m0);
            s1 += __expf(acc[mi][j][2] - m1) + __expf(acc[mi][j][3] - m1);
        }
        #pragma unroll
        for (int o = 1; o <= 2; o <<= 1) {
            s0 += __shfl_xor_sync(0xffffffffu, s0, o);
            s1 += __shfl_xor_sync(0xffffffffu, s1, o);
        }
        if ((lane & 3) == 0) {
            s_mx[rl][half_id] = m0; s_sm[rl][half_id] = s0;
            s_mx[rl + 8][half_id] = m1; s_sm[rl + 8][half_id] = s1;
        }
    }
    __syncthreads();
    if (tid < 128) {
        float ma = s_mx[tid][0], mb = s_mx[tid][1];
        float M = fmaxf(ma, mb);
        float S = s_sm[tid][0] * __expf(ma - M) + s_sm[tid][1] * __expf(mb - M);
        g_psm[(size_t)(b0 + tid) * 128 + blockIdx.x] = M;
        g_pss[(size_t)(b0 + tid) * 128 + blockIdx.x] = S;
    }
}

// ---------------- K6: combine per-tile softmax partials ----------------
__global__ void pcomb_kernel() {
    __shared__ float rm[4], rs[4];
    int b = blockIdx.x, t = threadIdx.x;   // 128 threads
    int lane = t & 31, w = t >> 5;
    float M = g_psm[(size_t)b * 128 + t];
    float S = g_pss[(size_t)b * 128 + t];
    float m = M;
    #pragma unroll
    for (int o = 16; o; o >>= 1) m = fmaxf(m, __shfl_xor_sync(0xffffffffu, m, o));
    if (!lane) rm[w] = m;
    __syncthreads();
    float Mg = fmaxf(fmaxf(rm[0], rm[1]), fmaxf(rm[2], rm[3]));
    float s = S * __expf(M - Mg);
    #pragma unroll
    for (int o = 16; o; o >>= 1) s += __shfl_xor_sync(0xffffffffu, s, o);
    if (!lane) rs[w] = s;
    __syncthreads();
    if (t == 0) { g_pmx[b] = Mg; g_pinv[b] = 1.f / (rs[0] + rs[1] + rs[2] + rs[3]); }
}

// ---------------- K7: out = softmax(pl) @ mem2, scaled-fp16 e, fp16 hi/lo m2 --------
#define OLS 72
#define O_E  0
#define O_MH (128 * OLS)
#define O_ML (192 * OLS)
#define O_SMEM (256 * OLS * 2)

__global__ void __launch_bounds__(256, 2)
out_tc_kernel() {
    extern __shared__ __half osm[];
    __half* E  = osm + O_E;
    __half* MH = osm + O_MH;
    __half* ML = osm + O_ML;
    int tid = threadIdx.x;
    int lane = tid & 31, wid = tid >> 5;
    int split = blockIdx.x;
    int b0 = blockIdx.y * 128;
    int kbase = split * (NR / NSPLIT);

    int la = tid >> 4, lb = tid & 15;
    float mxv[8], invv[8];
    #pragma unroll
    for (int i = 0; i < 8; ++i) {
        mxv[i]  = g_pmx[b0 + la + 16 * i];
        invv[i] = g_pinv[b0 + la + 16 * i] * ESCALE;
    }
    int m_row0 = tid >> 3, m_seg0 = (tid & 7) * 8;
    int m_row1 = (tid + 256) >> 3, m_seg1 = (tid & 7) * 8;

    uint32_t eb = smem_u32(E);
    uint32_t mhb = smem_u32(MH), mlb = smem_u32(ML);

    float acc[8][4] = {};
    int a_row = wid * 16 + (lane & 15);
    int a_kof = (lane >> 4) * 8;
    int b_rof = ((lane >> 4) * 8) + (lane & 7);
    int b_kof = ((lane >> 3) & 1) * 8;

    for (int kg = kbase; kg < kbase + NR / NSPLIT; kg += 64) {
        #pragma unroll
        for (int i = 0; i < 8; ++i) {
            int row = la + 16 * i;
            const __half2* lp = (const __half2*)&g_plh[(size_t)(b0 + row) * NR + kg + lb * 4];
            float2 f01 = __half22float2(lp[0]);
            float2 f23 = __half22float2(lp[1]);
            float e0 = __expf(f01.x - mxv[i]) * invv[i];
            float e1 = __expf(f01.y - mxv[i]) * invv[i];
            float e2 = __expf(f23.x - mxv[i]) * invv[i];
            float e3 = __expf(f23.y - mxv[i]) * invv[i];
            __half2* ep = (__half2*)&E[row * OLS + lb * 4];
            ep[0] = __floats2half2_rn(e0, e1);
            ep[1] = __floats2half2_rn(e2, e3);
        }
        *(uint4*)&MH[m_row0 * OLS + m_seg0] = *(const uint4*)&g_m2h[(size_t)m_row0 * NR + kg + m_seg0];
        *(uint4*)&MH[m_row1 * OLS + m_seg1] = *(const uint4*)&g_m2h[(size_t)m_row1 * NR + kg + m_seg1];
        *(uint4*)&ML[m_row0 * OLS + m_seg0] = *(const uint4*)&g_m2l[(size_t)m_row0 * NR + kg + m_seg0];
        *(uint4*)&ML[m_row1 * OLS + m_seg1] = *(const uint4*)&g_m2l[(size_t)m_row1 * NR + kg + m_seg1];
        __syncthreads();

        #pragma unroll
        for (int ks = 0; ks < 4; ++ks) {
            int k0 = ks * 16;
            uint32_t a[4];
            ldsm_x4(a[0], a[1], a[2], a[3], eb + (a_row * OLS + k0 + a_kof) * 2);
            uint32_t bh[4][4], bl[4][4];
            #pragma unroll
            for (int g = 0; g < 4; ++g) {
                uint32_t addr = mhb + ((g * 16 + b_rof) * OLS + k0 + b_kof) * 2;
                ldsm_x4(bh[g][0], bh[g][1], bh[g][2], bh[g][3], addr);
                addr = mlb + ((g * 16 + b_rof) * OLS + k0 + b_kof) * 2;
                ldsm_x4(bl[g][0], bl[g][1], bl[g][2], bl[g][3], addr);
            }
            #pragma unroll
            for (int g = 0; g < 4; ++g) {
                mma16816h(acc[g * 2],     a, &bh[g][0]);
                mma16816h(acc[g * 2 + 1], a, &bh[g][2]);
                mma16816h(acc[g * 2],     a, &bl[g][0]);
                mma16816h(acc[g * 2 + 1], a, &bl[g][2]);
            }
        }
        __syncthreads();
    }

    int gr = lane >> 2, gc = (lane & 3) * 2;
    int r1 = b0 + wid * 16 + gr;
    #pragma unroll
    for (int j = 0; j < 8; ++j) {
        int c = j * 8 + gc;
        *(float2*)&g_part[(size_t)split * (NB * NW) + (size_t)r1 * NW + c] =
            make_float2(acc[j][0], acc[j][1]);
        *(float2*)&g_part[(size_t)split * (NB * NW) + (size_t)(r1 + 8) * NW + c] =
            make_float2(acc[j][2], acc[j][3]);
    }
}

__global__ void out_reduce(float* __restrict__ out) {
    int i = blockIdx.x * blockDim.x + threadIdx.x;
    float s = 0.f;
    #pragma unroll
    for (int p = 0; p < NSPLIT; ++p) s += g_part[(size_t)p * (NB * NW) + i];
    out[i] = s * EINV;
}

// ---------------- launch ----------------
extern "C" void kernel_launch(void* const* d_in, const int* in_sizes, int n_in,
                              void* d_out, int out_size) {
    const float* x   = (const float*)d_in[0];
    const float* Wv  = (const float*)d_in[1];
    const float* bv  = (const float*)d_in[2];
    const float* Wb  = (const float*)d_in[3];
    const float* bb  = (const float*)d_in[4];
    const float* Wg  = (const float*)d_in[5];
    const float* bg  = (const float*)d_in[6];
    const float* Wp  = (const float*)d_in[7];
    const float* bp  = (const float*)d_in[8];
    const float* ck  = (const float*)d_in[9];
    const float* cbv = (const float*)d_in[10];
    const float* mem = (const float*)d_in[11];
    float* out = (float*)d_out;
    (void)in_sizes; (void)n_in; (void)out_size;

    cudaFuncSetAttribute(pl_mma_kernel, cudaFuncAttributeMaxDynamicSharedMemorySize, PL_SMEM);
    cudaFuncSetAttribute(out_tc_kernel, cudaFuncAttributeMaxDynamicSharedMemorySize, O_SMEM);

    // order chosen so wa_kernel is launch index 3 (ncu capture slot)
    mnh_kernel<<<NR / 256, 256>>>(mem);
    heads_kernel<<<NB, 64>>>(x, Wv, bv, Wb, bb, Wg, bg);
    sim_tc_kernel<<<dim3(NR / 128, NB / 128), 256>>>();
    wa_kernel<<<NB, 1024>>>(ck, cbv);
    xh_kernel<<<NB * ND / 4 / 256, 256>>>(x);
    wt_kernel<<<dim3(NR / 32, ND / 32), dim3(32, 8)>>>(Wp);
    pl_mma_kernel<<<dim3(NR / 128, NB / 128), 256, PL_SMEM>>>(bp);
    pcomb_kernel<<<NB, 128>>>();
    addm2_kernel<<<NR / 64, 128>>>(mem);
    out_tc_kernel<<<dim3(NSPLIT, NB / 128), 256, O_SMEM>>>();
    out_reduce<<<NB * NW / 256, 256>>>(out);
}

// round 14
// speedup vs baseline: 1.5886x; 1.0449x over previous
#include <cuda_runtime.h>
#include <cuda_bf16.h>
#include <cuda_fp16.h>
#include <math.h>
#include <cstdint>

#define NB 1024
#define ND 256
#define NR 16384
#define NW 64
#define NSPLIT 32
#define EPSF 1e-16f
#define ESCALE 2048.0f
#define EINV (1.0f / 2048.0f)

// ---------------- scratch (no allocations allowed) ----------------
__device__ __nv_bfloat16 g_simh[(size_t)NB * NR]; // sim logits (bf16), then a (in place)
__device__ __half g_plh[(size_t)NB * NR];         // p logits (fp16)
__device__ float g_gamma[NB];
__device__ float g_bvn[NB];                       // beta / ||v||
__device__ float g_imn[NR];                       // 1 / ||mem_r||
__device__ float g_part[(size_t)NSPLIT * NB * NW];
__device__ float g_pmx [NB];
__device__ float g_pinv[NB];
__device__ float g_psm[(size_t)NB * 128];         // per (row, n-tile) max
__device__ float g_pss[(size_t)NB * 128];         // per (row, n-tile) sumexp
__device__ __half g_xh[(size_t)NB * ND];          // x in fp16
__device__ __half g_wt[(size_t)NR * ND];          // Wp^T in fp16 [r][k]
__device__ __nv_bfloat16 g_vh  [NB * NW];
__device__ __nv_bfloat16 g_memh[NR * NW];
__device__ __half g_m2h[(size_t)NW * NR];         // mem2^T hi  [w][r] (fp16)
__device__ __half g_m2l[(size_t)NW * NR];         // mem2^T lo  [w][r] (fp16)

__device__ __forceinline__ float softplus_f(float z) {
    return z > 0.f ? z + log1pf(expf(-z)) : log1pf(expf(z));
}
__device__ __forceinline__ uint32_t smem_u32(const void* p) {
    uint32_t a;
    asm("{ .reg .u64 t; cvta.to.shared.u64 t, %1; cvt.u32.u64 %0, t; }" : "=r"(a) : "l"(p));
    return a;
}
__device__ __forceinline__ void ldsm_x4(uint32_t& r0, uint32_t& r1, uint32_t& r2, uint32_t& r3,
                                        uint32_t addr) {
    asm volatile("ldmatrix.sync.aligned.m8n8.x4.shared.b16 {%0, %1, %2, %3}, [%4];"
                 : "=r"(r0), "=r"(r1), "=r"(r2), "=r"(r3) : "r"(addr));
}
__device__ __forceinline__ void ldsm_x4t(uint32_t& r0, uint32_t& r1, uint32_t& r2, uint32_t& r3,
                                         uint32_t addr) {
    asm volatile("ldmatrix.sync.aligned.m8n8.x4.trans.shared.b16 {%0, %1, %2, %3}, [%4];"
                 : "=r"(r0), "=r"(r1), "=r"(r2), "=r"(r3) : "r"(addr));
}
__device__ __forceinline__ void mma16816(float* d, const uint32_t* a, const uint32_t* b) {
    asm volatile(
        "mma.sync.aligned.m16n8k16.row.col.f32.bf16.bf16.f32 "
        "{%0, %1, %2, %3}, {%4, %5, %6, %7}, {%8, %9}, {%0, %1, %2, %3};"
        : "+f"(d[0]), "+f"(d[1]), "+f"(d[2]), "+f"(d[3])
        : "r"(a[0]), "r"(a[1]), "r"(a[2]), "r"(a[3]), "r"(b[0]), "r"(b[1]));
}
__device__ __forceinline__ void mma16816h(float* d, const uint32_t* a, const uint32_t* b) {
    asm volatile(
        "mma.sync.aligned.m16n8k16.row.col.f32.f16.f16.f32 "
        "{%0, %1, %2, %3}, {%4, %5, %6, %7}, {%8, %9}, {%0, %1, %2, %3};"
        : "+f"(d[0]), "+f"(d[1]), "+f"(d[2]), "+f"(d[3])
        : "r"(a[0]), "r"(a[1]), "r"(a[2]), "r"(a[3]), "r"(b[0]), "r"(b[1]));
}
__device__ __forceinline__ void cp_async16(uint32_t saddr, const void* g) {
    asm volatile("cp.async.cg.shared.global [%0], [%1], 16;" :: "r"(saddr), "l"(g));
}
#define CP_COMMIT() asm volatile("cp.async.commit_group;" ::: "memory")
#define CP_WAIT(n)  asm volatile("cp.async.wait_group %0;" :: "n"(n) : "memory")

// block sum for 1024 threads (32 warps)
__device__ __forceinline__ float blk_sum(float v, float* red) {
    int lane = threadIdx.x & 31, w = threadIdx.x >> 5;
    #pragma unroll
    for (int o = 16; o; o >>= 1) v += __shfl_xor_sync(0xffffffffu, v, o);
    if (!lane) red[w] = v;
    __syncthreads();
    if (w == 0) {
        v = red[lane];
        #pragma unroll
        for (int o = 16; o; o >>= 1) v += __shfl_xor_sync(0xffffffffu, v, o);
        if (!lane) red[0] = v;
    }
    __syncthreads();
    v = red[0];
    __syncthreads();
    return v;
}

// ---------------- K1: controller heads ----------------
__global__ void heads_kernel(const float* __restrict__ x,
                             const float* __restrict__ Wv, const float* __restrict__ bv,
                             const float* __restrict__ Wb, const float* __restrict__ bb,
                             const float* __restrict__ Wg, const float* __restrict__ bg) {
    int b = blockIdx.x, t = threadIdx.x;        // 64 threads
    __shared__ float xs[ND];
    __shared__ float red[64];
    for (int i = t; i < ND; i += 64) xs[i] = x[b * ND + i];
    __syncthreads();

    float acc = 0.f;
    #pragma unroll 8
    for (int d = 0; d < ND; ++d) acc = fmaf(xs[d], Wv[d * NW + t], acc);
    float pb = 0.f, pg = 0.f;
    for (int d = t; d < ND; d += 64) {
        pb = fmaf(xs[d], Wb[d], pb);
        pg = fmaf(xs[d], Wg[d], pg);
    }
    float v = acc + bv[t];
    g_vh[b * NW + t] = __float2bfloat16(v);

    red[t] = v * v; __syncthreads();
    for (int s = 32; s > 0; s >>= 1) { if (t < s) red[t] += red[t + s]; __syncthreads(); }
    float vn = sqrtf(red[0]);
    __syncthreads();

    red[t] = pb; __syncthreads();
    for (int s = 32; s > 0; s >>= 1) { if (t < s) red[t] += red[t + s]; __syncthreads(); }
    if (t == 0) g_bvn[b] = softplus_f(red[0] + bb[0]) / (vn + EPSF);
    __syncthreads();

    red[t] = pg; __syncthreads();
    for (int s = 32; s > 0; s >>= 1) { if (t < s) red[t] += red[t + s]; __syncthreads(); }
    if (t == 0) g_gamma[b] = 1.f + softplus_f(red[0] + bg[0]);
}

// ---------------- K0: memory row inverse norms + bf16 convert (fused) --------
__global__ void mnh_kernel(const float* __restrict__ mem) {
    int r = blockIdx.x * blockDim.x + threadIdx.x;
    if (r >= NR) return;
    const float4* m4 = (const float4*)(mem + (size_t)r * NW);
    __nv_bfloat162* h2 = (__nv_bfloat162*)(g_memh + (size_t)r * NW);
    float s = 0.f;
    #pragma unroll
    for (int i = 0; i < NW / 4; ++i) {
        float4 t4 = m4[i];
        s += t4.x * t4.x + t4.y * t4.y + t4.z * t4.z + t4.w * t4.w;
        h2[i * 2]     = __float22bfloat162_rn(make_float2(t4.x, t4.y));
        h2[i * 2 + 1] = __float22bfloat162_rn(make_float2(t4.z, t4.w));
    }
    g_imn[r] = 1.f / (sqrtf(s) + EPSF);
}

// ---------------- K2: sim via HMMA bf16 (multiply-only epilogue) ----------------
#define SLS 72
__global__ void __launch_bounds__(256, 2)
sim_tc_kernel() {
    __shared__ __nv_bfloat16 As[128][SLS];
    __shared__ __nv_bfloat16 Bs[128][SLS];
    int tid = threadIdx.x;
    int lane = tid & 31, wid = tid >> 5;
    int n0 = blockIdx.x * 128;    // r
    int b0 = blockIdx.y * 128;    // b
    int wm0 = (wid & 1) * 64;
    int wn0 = (wid >> 1) * 32;

    #pragma unroll
    for (int i = 0; i < 4; ++i) {
        int q = tid + i * 256;
        int row = q >> 3, seg = (q & 7) * 8;
        *(uint4*)&As[row][seg] = *(const uint4*)&g_vh[(size_t)(b0 + row) * NW + seg];
        *(uint4*)&Bs[row][seg] = *(const uint4*)&g_memh[(size_t)(n0 + row) * NW + seg];
    }
    __syncthreads();

    float d[4][4][4] = {};
    uint32_t as_base = smem_u32(&As[0][0]);
    uint32_t bs_base = smem_u32(&Bs[0][0]);
    int a_row = wm0 + (lane & 15);
    int a_kof = (lane >> 4) * 8;
    int b_rof = ((lane >> 4) * 8) + (lane & 7);
    int b_kof = ((lane >> 3) & 1) * 8;

    #pragma unroll
    for (int ks = 0; ks < 4; ++ks) {
        int k0 = ks * 16;
        uint32_t a[4][4];
        #pragma unroll
        for (int mi = 0; mi < 4; ++mi) {
            uint32_t addr = as_base + ((a_row + mi * 16) * SLS + k0 + a_kof) * 2;
            ldsm_x4(a[mi][0], a[mi][1], a[mi][2], a[mi][3], addr);
        }
        uint32_t bfr[2][4];
        #pragma unroll
        for (int nj = 0; nj < 2; ++nj) {
            uint32_t addr = bs_base + ((wn0 + nj * 16 + b_rof) * SLS + k0 + b_kof) * 2;
            ldsm_x4(bfr[nj][0], bfr[nj][1], bfr[nj][2], bfr[nj][3], addr);
        }
        #pragma unroll
        for (int mi = 0; mi < 4; ++mi)
            #pragma unroll
            for (int ni = 0; ni < 4; ++ni)
                mma16816(d[mi][ni], a[mi], &bfr[ni >> 1][(ni & 1) * 2]);
    }

    int gr = lane >> 2, gc = (lane & 3) * 2;
    #pragma unroll
    for (int mi = 0; mi < 4; ++mi) {
        int bi0 = b0 + wm0 + mi * 16 + gr;
        float s0 = g_bvn[bi0];
        float s1 = g_bvn[bi0 + 8];
        #pragma unroll
        for (int ni = 0; ni < 4; ++ni) {
            int c = n0 + wn0 + ni * 8 + gc;
            float im0 = g_imn[c], im1 = g_imn[c + 1];
            *(__nv_bfloat162*)&g_simh[(size_t)bi0 * NR + c] =
                __float22bfloat162_rn(make_float2(
                    s0 * d[mi][ni][0] * im0, s0 * d[mi][ni][1] * im1));
            *(__nv_bfloat162*)&g_simh[(size_t)(bi0 + 8) * NR + c] =
                __float22bfloat162_rn(make_float2(
                    s1 * d[mi][ni][2] * im0, s1 * d[mi][ni][3] * im1));
        }
    }
}

// ---------------- K3: softmax (no-max; logits bounded) -> conv -> pow -> renorm -----
__global__ void __launch_bounds__(1024, 2)
wa_kernel(const float* __restrict__ conv_k, const float* __restrict__ conv_b) {
    __shared__ float eL[2][1024];
    __shared__ float eR[2][1024];
    __shared__ float red[32];
    int b = blockIdx.x, t = threadIdx.x;   // 1024 threads, 2x8 contiguous elems each
    __nv_bfloat16* row = g_simh + (size_t)b * NR;

    float e[16];
    float sum = 0.f;
    #pragma unroll
    for (int i = 0; i < 2; ++i) {
        uint4 raw = *(const uint4*)&row[i * 8192 + t * 8];
        const __nv_bfloat162* p2 = (const __nv_bfloat162*)&raw;
        #pragma unroll
        for (int k = 0; k < 4; ++k) {
            float2 f = __bfloat1622float2(p2[k]);
            float e0 = __expf(f.x);
            float e1 = __expf(f.y);
            e[i * 8 + 2 * k]     = e0;
            e[i * 8 + 2 * k + 1] = e1;
            sum += e0 + e1;
        }
    }
    eL[0][t] = e[0]; eR[0][t] = e[7];
    eL[1][t] = e[8]; eR[1][t] = e[15];
    sum = blk_sum(sum, red);   // contains __syncthreads -> edges visible
    float inv = 1.f / sum;

    float c0 = conv_k[0], c1 = conv_k[1], c2 = conv_k[2], cb = conv_b[0];
    float gam = g_gamma[b];
    float la[16];
    float asum = 0.f;
    #pragma unroll
    for (int i = 0; i < 2; ++i) {
        #pragma unroll
        for (int k = 0; k < 8; ++k) {
            int idx = i * 8 + k;
            float wl, wr;
            if (k > 0) wl = e[idx - 1];
            else if (i == 0) wl = (t > 0) ? eR[0][t - 1] : 0.f;
            else             wl = (t > 0) ? eR[1][t - 1] : eR[0][1023];
            if (k < 7) wr = e[idx + 1];
            else if (i == 0) wr = (t < 1023) ? eL[0][t + 1] : eL[1][0];
            else             wr = (t < 1023) ? eL[1][t + 1] : 0.f;
            float wc = fmaf(wl, c0, fmaf(e[idx], c1, wr * c2)) * inv + cb;
            float a = __powf(wc, gam);
            la[idx] = a; asum += a;
        }
    }
    asum = blk_sum(asum, red);
    float invd = 1.f / (asum + (float)NR * EPSF);

    #pragma unroll
    for (int i = 0; i < 2; ++i) {
        uint4 raw;
        __nv_bfloat162* p2 = (__nv_bfloat162*)&raw;
        #pragma unroll
        for (int k = 0; k < 4; ++k)
            p2[k] = __float22bfloat162_rn(make_float2(
                la[i * 8 + 2 * k] * invd, la[i * 8 + 2 * k + 1] * invd));
        *(uint4*)&row[i * 8192 + t * 8] = raw;
    }
}

// ---------------- K4: add/erase HMMA + fused mem2 build (transposed fp16 hi/lo) ------
#define ATS 72
__global__ void __launch_bounds__(128, 4)
addm2_kernel(const float* __restrict__ mem) {
    __shared__ __align__(16) __nv_bfloat16 As[128][ATS];   // overlaid with fp32 tile later
    __shared__ __nv_bfloat16 Vs[128][ATS];
    int tid = threadIdx.x, lane = tid & 31, wid = tid >> 5;   // 4 warps
    int r0 = blockIdx.x * 64;
    float acc[8][4] = {};
    float acce[4] = {};
    uint32_t onesf[2] = {0x3F803F80u, 0x3F803F80u};
    uint32_t asb = smem_u32(&As[0][0]), vsb = smem_u32(&Vs[0][0]);
    int m0 = wid * 16;
    int lrow = (lane & 7) + ((lane & 16) >> 1);
    int lcol = lane & 8;

    for (int kb = 0; kb < NB; kb += 128) {
        #pragma unroll
        for (int i = 0; i < 8; ++i) {
            int q = tid + i * 128;
            int kk = q >> 3, c = (q & 7) * 8;
            *(uint4*)&As[kk][c] = *(const uint4*)&g_simh[(size_t)(kb + kk) * NR + r0 + c];
            *(uint4*)&Vs[kk][c] = *(const uint4*)&g_vh[(kb + kk) * NW + c];
        }
        __syncthreads();

        #pragma unroll
        for (int ks = 0; ks < 8; ++ks) {
            int k0 = ks * 16;
            uint32_t a[4];
            ldsm_x4t(a[0], a[1], a[2], a[3],
                     asb + ((k0 + lrow) * ATS + m0 + lcol) * 2);
            uint32_t bfr[4][4];
            #pragma unroll
            for (int nj = 0; nj < 4; ++nj)
                ldsm_x4t(bfr[nj][0], bfr[nj][1], bfr[nj][2], bfr[nj][3],
                         vsb + ((k0 + lrow) * ATS + nj * 16 + lcol) * 2);
            #pragma unroll
            for (int nj = 0; nj < 4; ++nj) {
                uint32_t f1[2] = {bfr[nj][0], bfr[nj][2]};
                uint32_t f2[2] = {bfr[nj][1], bfr[nj][3]};
                mma16816(acc[nj * 2],     a, f1);
                mma16816(acc[nj * 2 + 1], a, f2);
            }
            mma16816(acce, a, onesf);
        }
        __syncthreads();
    }

    // fused mem2: every lane holds the row-sums (erase) for its two rows
    const float invB = 1.f / (float)NB;
    float ev0 = 1.f - acce[0] * invB;   // row m0+gr
    float ev1 = 1.f - acce[2] * invB;   // row m0+gr+8
    int gr = lane >> 2, gc = (lane & 3) * 2;
    int rA = m0 + gr, rB = m0 + gr + 8;

    float (*tbuf)[65] = (float(*)[65])&As[0][0];   // 64x65 fp32 = 16.6KB < As region
    #pragma unroll
    for (int nj = 0; nj < 8; ++nj) {
        int w = nj * 8 + gc;
        float2 ma = *(const float2*)&mem[(size_t)(r0 + rA) * NW + w];
        float2 mb = *(const float2*)&mem[(size_t)(r0 + rB) * NW + w];
        tbuf[rA][w]     = ma.x * ev0 + acc[nj][0] * invB;
        tbuf[rA][w + 1] = ma.y * ev0 + acc[nj][1] * invB;
        tbuf[rB][w]     = mb.x * ev1 + acc[nj][2] * invB;
        tbuf[rB][w + 1] = mb.y * ev1 + acc[nj][3] * invB;
    }
    __syncthreads();

    #pragma unroll
    for (int i = 0; i < 32; ++i) {
        int q = tid + i * 128;          // 0..4095
        int w = q >> 6, r = q & 63;
        float f = tbuf[r][w];
        __half h = __float2half(f);
        __half l = __float2half(f - __half2float(h));
        g_m2h[(size_t)w * NR + r0 + r] = h;
        g_m2l[(size_t)w * NR + r0 + r] = l;
    }
}

// ---------------- prep: x -> fp16 ----------------
__global__ void xh_kernel(const float* __restrict__ x) {
    int i = blockIdx.x * 256 + threadIdx.x;    // over NB*ND/4 float4 slots
    float4 f = *(const float4*)&x[(size_t)i * 4];
    __half2 h0 = __floats2half2_rn(f.x, f.y);
    __half2 h1 = __floats2half2_rn(f.z, f.w);
    *(__half2*)&g_xh[(size_t)i * 4]     = h0;
    *(__half2*)&g_xh[(size_t)i * 4 + 2] = h1;
}

// ---------------- prep: Wp^T -> fp16 [r][k] ----------------
__global__ void wt_kernel(const float* __restrict__ Wp) {
    __shared__ float t[32][33];
    int n0 = blockIdx.x * 32, k0 = blockIdx.y * 32;
    int tx = threadIdx.x, ty = threadIdx.y;   // (32, 8)
    #pragma unroll
    for (int i = 0; i < 4; ++i)
        t[ty + 8 * i][tx] = Wp[(size_t)(k0 + ty + 8 * i) * NR + n0 + tx];
    __syncthreads();
    #pragma unroll
    for (int i = 0; i < 4; ++i) {
        int row = ty + 8 * i;
        g_wt[(size_t)(n0 + row) * ND + k0 + tx] = __float2half(t[tx][row]);
    }
}

// ---------------- K5: p logits (fp16 HMMA, K=256) + fused per-tile softmax stats -----
#define PLS 40
#define PLK (ND / 32)
#define PSTG 3
#define PL_BUF (128 * PLS)
#define PL_SMEM (2 * PSTG * PL_BUF * 2)

__global__ void __launch_bounds__(256, 2)
pl_mma_kernel(const float* __restrict__ bp) {
    extern __shared__ __half plsm[];
    __half* As = plsm;                    // [PSTG][128][PLS]
    __half* Bs = plsm + PSTG * PL_BUF;    // [PSTG][128][PLS]
    __shared__ float s_mx[128][2];
    __shared__ float s_sm[128][2];
    int tid = threadIdx.x;
    int lane = tid & 31, wid = tid >> 5;          // 8 warps
    int n0 = blockIdx.x * 128;
    int b0 = blockIdx.y * 128;
    int wm0 = (wid & 3) * 32;
    int wn0 = (wid >> 2) * 64;
    int half_id = wid >> 2;

    uint32_t asb = smem_u32(As), bsb = smem_u32(Bs);
    const uint32_t bufB = PL_BUF * 2;

    int row0 = tid >> 2, seg0 = (tid & 3) * 8;
    int row1 = (tid + 256) >> 2, seg1 = (tid & 3) * 8;

    uint32_t a_sa0 = asb + (row0 * PLS + seg0) * 2;
    uint32_t a_sa1 = asb + (row1 * PLS + seg1) * 2;
    uint32_t b_sa0 = bsb + (row0 * PLS + seg0) * 2;
    uint32_t b_sa1 = bsb + (row1 * PLS + seg1) * 2;
    const __half* a_g0 = &g_xh[(size_t)(b0 + row0) * ND + seg0];
    const __half* a_g1 = &g_xh[(size_t)(b0 + row1) * ND + seg1];
    const __half* b_g0 = &g_wt[(size_t)(n0 + row0) * ND + seg0];
    const __half* b_g1 = &g_wt[(size_t)(n0 + row1) * ND + seg1];

    #pragma unroll
    for (int s = 0; s < 2; ++s) {
        cp_async16(a_sa0 + s * bufB, a_g0 + s * 32);
        cp_async16(a_sa1 + s * bufB, a_g1 + s * 32);
        cp_async16(b_sa0 + s * bufB, b_g0 + s * 32);
        cp_async16(b_sa1 + s * bufB, b_g1 + s * 32);
        CP_COMMIT();
    }

    float acc[2][8][4] = {};
    int a_row = wm0 + (lane & 15);
    int a_kof = (lane >> 4) * 8;
    int b_rof = ((lane >> 4) * 8) + (lane & 7);
    int b_kof = ((lane >> 3) & 1) * 8;

    for (int kc = 0; kc < PLK; ++kc) {
        int cur = kc % PSTG;
        if (kc + 1 < PLK) CP_WAIT(1); else CP_WAIT(0);
        __syncthreads();

        if (kc + 2 < PLK) {
            int nxt = (kc + 2) % PSTG;
            int ko = (kc + 2) * 32;
            cp_async16(a_sa0 + nxt * bufB, a_g0 + ko);
            cp_async16(a_sa1 + nxt * bufB, a_g1 + ko);
            cp_async16(b_sa0 + nxt * bufB, b_g0 + ko);
            cp_async16(b_sa1 + nxt * bufB, b_g1 + ko);
            CP_COMMIT();
        }

        uint32_t abase = asb + cur * bufB;
        uint32_t bbase = bsb + cur * bufB;

        uint32_t a[2][2][4], bfr[2][4][4];
        #pragma unroll
        for (int mi = 0; mi < 2; ++mi)
            ldsm_x4(a[0][mi][0], a[0][mi][1], a[0][mi][2], a[0][mi][3],
                    abase + ((a_row + mi * 16) * PLS + a_kof) * 2);
        #pragma unroll
        for (int nj = 0; nj < 4; ++nj)
            ldsm_x4(bfr[0][nj][0], bfr[0][nj][1], bfr[0][nj][2], bfr[0][nj][3],
                    bbase + ((wn0 + nj * 16 + b_rof) * PLS + b_kof) * 2);

        #pragma unroll
        for (int ks = 0; ks < 2; ++ks) {
            int c = ks & 1, n = c ^ 1;
            if (ks + 1 < 2) {
                int k0 = (ks + 1) * 16;
                #pragma unroll
                for (int mi = 0; mi < 2; ++mi)
                    ldsm_x4(a[n][mi][0], a[n][mi][1], a[n][mi][2], a[n][mi][3],
                            abase + ((a_row + mi * 16) * PLS + k0 + a_kof) * 2);
                #pragma unroll
                for (int nj = 0; nj < 4; ++nj)
                    ldsm_x4(bfr[n][nj][0], bfr[n][nj][1], bfr[n][nj][2], bfr[n][nj][3],
                            bbase + ((wn0 + nj * 16 + b_rof) * PLS + k0 + b_kof) * 2);
            }
            #pragma unroll
            for (int mi = 0; mi < 2; ++mi)
                #pragma unroll
                for (int nj = 0; nj < 4; ++nj) {
                    mma16816h(acc[mi][nj * 2],     a[c][mi], &bfr[c][nj][0]);
                    mma16816h(acc[mi][nj * 2 + 1], a[c][mi], &bfr[c][nj][2]);
                }
        }
    }

    // epilogue: bias, fp16 logit store, per-tile softmax partials
    int gr = lane >> 2, gc = (lane & 3) * 2;
    float bpv[8][2];
    #pragma unroll
    for (int j = 0; j < 8; ++j) {
        int c = n0 + wn0 + j * 8 + gc;
        bpv[j][0] = bp[c]; bpv[j][1] = bp[c + 1];
    }
    #pragma unroll
    for (int mi = 0; mi < 2; ++mi) {
        int rl = wm0 + mi * 16 + gr;
        int r1 = b0 + rl;
        float m0 = -1e30f, m1 = -1e30f;
        #pragma unroll
        for (int j = 0; j < 8; ++j) {
            float v0 = acc[mi][j][0] + bpv[j][0];
            float v1 = acc[mi][j][1] + bpv[j][1];
            float v2 = acc[mi][j][2] + bpv[j][0];
            float v3 = acc[mi][j][3] + bpv[j][1];
            acc[mi][j][0] = v0; acc[mi][j][1] = v1;
            acc[mi][j][2] = v2; acc[mi][j][3] = v3;
            int c = n0 + wn0 + j * 8 + gc;
            *(__half2*)&g_plh[(size_t)r1 * NR + c]       = __floats2half2_rn(v0, v1);
            *(__half2*)&g_plh[(size_t)(r1 + 8) * NR + c] = __floats2half2_rn(v2, v3);
            m0 = fmaxf(m0, fmaxf(v0, v1));
            m1 = fmaxf(m1, fmaxf(v2, v3));
        }
        #pragma unroll
        for (int o = 1; o <= 2; o <<= 1) {
            m0 = fmaxf(m0, __shfl_xor_sync(0xffffffffu, m0, o));
            m1 = fmaxf(m1, __shfl_xor_sync(0xffffffffu, m1, o));
        }
        float s0 = 0.f, s1 = 0.f;
        #pragma unroll
        for (int j = 0; j < 8; ++j) {
            s0 += __expf(acc[mi][j][0] - m0) + __expf(acc[mi][j][1] - m0);
            s1 += __expf(acc[mi][j][2] - m1) + __expf(acc[mi][j][3] - m1);
        }
        #pragma unroll
        for (int o = 1; o <= 2; o <<= 1) {
            s0 += __shfl_xor_sync(0xffffffffu, s0, o);
            s1 += __shfl_xor_sync(0xffffffffu, s1, o);
        }
        if ((lane & 3) == 0) {
            s_mx[rl][half_id] = m0; s_sm[rl][half_id] = s0;
            s_mx[rl + 8][half_id] = m1; s_sm[rl + 8][half_id] = s1;
        }
    }
    __syncthreads();
    if (tid < 128) {
        float ma = s_mx[tid][0], mb = s_mx[tid][1];
        float M = fmaxf(ma, mb);
        float S = s_sm[tid][0] * __expf(ma - M) + s_sm[tid][1] * __expf(mb - M);
        g_psm[(size_t)(b0 + tid) * 128 + blockIdx.x] = M;
        g_pss[(size_t)(b0 + tid) * 128 + blockIdx.x] = S;
    }
}

// ---------------- K6: combine per-tile softmax partials ----------------
__global__ void pcomb_kernel() {
    __shared__ float rm[4], rs[4];
    int b = blockIdx.x, t = threadIdx.x;   // 128 threads
    int lane = t & 31, w = t >> 5;
    float M = g_psm[(size_t)b * 128 + t];
    float S = g_pss[(size_t)b * 128 + t];
    float m = M;
    #pragma unroll
    for (int o = 16; o; o >>= 1) m = fmaxf(m, __shfl_xor_sync(0xffffffffu, m, o));
    if (!lane) rm[w] = m;
    __syncthreads();
    float Mg = fmaxf(fmaxf(rm[0], rm[1]), fmaxf(rm[2], rm[3]));
    float s = S * __expf(M - Mg);
    #pragma unroll
    for (int o = 16; o; o >>= 1) s += __shfl_xor_sync(0xffffffffu, s, o);
    if (!lane) rs[w] = s;
    __syncthreads();
    if (t == 0) { g_pmx[b] = Mg; g_pinv[b] = 1.f / (rs[0] + rs[1] + rs[2] + rs[3]); }
}

// ---------------- K7: out = softmax(pl) @ mem2, scaled-fp16 e, fp16 hi/lo m2 --------
#define OLS 72
#define O_E  0
#define O_MH (128 * OLS)
#define O_ML (192 * OLS)
#define O_SMEM (256 * OLS * 2)

__global__ void __launch_bounds__(256, 2)
out_tc_kernel() {
    extern __shared__ __half osm[];
    __half* E  = osm + O_E;
    __half* MH = osm + O_MH;
    __half* ML = osm + O_ML;
    int tid = threadIdx.x;
    int lane = tid & 31, wid = tid >> 5;
    int split = blockIdx.x;
    int b0 = blockIdx.y * 128;
    int kbase = split * (NR / NSPLIT);

    int la = tid >> 4, lb = tid & 15;
    float mxv[8], invv[8];
    #pragma unroll
    for (int i = 0; i < 8; ++i) {
        mxv[i]  = g_pmx[b0 + la + 16 * i];
        invv[i] = g_pinv[b0 + la + 16 * i] * ESCALE;
    }
    int m_row0 = tid >> 3, m_seg0 = (tid & 7) * 8;
    int m_row1 = (tid + 256) >> 3, m_seg1 = (tid & 7) * 8;

    uint32_t eb = smem_u32(E);
    uint32_t mhb = smem_u32(MH), mlb = smem_u32(ML);

    float acc[8][4] = {};
    int a_row = wid * 16 + (lane & 15);
    int a_kof = (lane >> 4) * 8;
    int b_rof = ((lane >> 4) * 8) + (lane & 7);
    int b_kof = ((lane >> 3) & 1) * 8;

    for (int kg = kbase; kg < kbase + NR / NSPLIT; kg += 64) {
        #pragma unroll
        for (int i = 0; i < 8; ++i) {
            int row = la + 16 * i;
            const __half2* lp = (const __half2*)&g_plh[(size_t)(b0 + row) * NR + kg + lb * 4];
            float2 f01 = __half22float2(lp[0]);
            float2 f23 = __half22float2(lp[1]);
            float e0 = __expf(f01.x - mxv[i]) * invv[i];
            float e1 = __expf(f01.y - mxv[i]) * invv[i];
            float e2 = __expf(f23.x - mxv[i]) * invv[i];
            float e3 = __expf(f23.y - mxv[i]) * invv[i];
            __half2* ep = (__half2*)&E[row * OLS + lb * 4];
            ep[0] = __floats2half2_rn(e0, e1);
            ep[1] = __floats2half2_rn(e2, e3);
        }
        *(uint4*)&MH[m_row0 * OLS + m_seg0] = *(const uint4*)&g_m2h[(size_t)m_row0 * NR + kg + m_seg0];
        *(uint4*)&MH[m_row1 * OLS + m_seg1] = *(const uint4*)&g_m2h[(size_t)m_row1 * NR + kg + m_seg1];
        *(uint4*)&ML[m_row0 * OLS + m_seg0] = *(const uint4*)&g_m2l[(size_t)m_row0 * NR + kg + m_seg0];
        *(uint4*)&ML[m_row1 * OLS + m_seg1] = *(const uint4*)&g_m2l[(size_t)m_row1 * NR + kg + m_seg1];
        __syncthreads();

        #pragma unroll
        for (int ks = 0; ks < 4; ++ks) {
            int k0 = ks * 16;
            uint32_t a[4];
            ldsm_x4(a[0], a[1], a[2], a[3], eb + (a_row * OLS + k0 + a_kof) * 2);
            uint32_t bh[4][4], bl[4][4];
            #pragma unroll
            for (int g = 0; g < 4; ++g) {
                uint32_t addr = mhb + ((g * 16 + b_rof) * OLS + k0 + b_kof) * 2;
                ldsm_x4(bh[g][0], bh[g][1], bh[g][2], bh[g][3], addr);
                addr = mlb + ((g * 16 + b_rof) * OLS + k0 + b_kof) * 2;
                ldsm_x4(bl[g][0], bl[g][1], bl[g][2], bl[g][3], addr);
            }
            #pragma unroll
            for (int g = 0; g < 4; ++g) {
                mma16816h(acc[g * 2],     a, &bh[g][0]);
                mma16816h(acc[g * 2 + 1], a, &bh[g][2]);
                mma16816h(acc[g * 2],     a, &bl[g][0]);
                mma16816h(acc[g * 2 + 1], a, &bl[g][2]);
            }
        }
        __syncthreads();
    }

    int gr = lane >> 2, gc = (lane & 3) * 2;
    int r1 = b0 + wid * 16 + gr;
    #pragma unroll
    for (int j = 0; j < 8; ++j) {
        int c = j * 8 + gc;
        *(float2*)&g_part[(size_t)split * (NB * NW) + (size_t)r1 * NW + c] =
            make_float2(acc[j][0], acc[j][1]);
        *(float2*)&g_part[(size_t)split * (NB * NW) + (size_t)(r1 + 8) * NW + c] =
            make_float2(acc[j][2], acc[j][3]);
    }
}

__global__ void out_reduce(float* __restrict__ out) {
    int i = blockIdx.x * blockDim.x + threadIdx.x;
    float s = 0.f;
    #pragma unroll
    for (int p = 0; p < NSPLIT; ++p) s += g_part[(size_t)p * (NB * NW) + i];
    out[i] = s * EINV;
}

// ---------------- launch ----------------
extern "C" void kernel_launch(void* const* d_in, const int* in_sizes, int n_in,
                              void* d_out, int out_size) {
    const float* x   = (const float*)d_in[0];
    const float* Wv  = (const float*)d_in[1];
    const float* bv  = (const float*)d_in[2];
    const float* Wb  = (const float*)d_in[3];
    const float* bb  = (const float*)d_in[4];
    const float* Wg  = (const float*)d_in[5];
    const float* bg  = (const float*)d_in[6];
    const float* Wp  = (const float*)d_in[7];
    const float* bp  = (const float*)d_in[8];
    const float* ck  = (const float*)d_in[9];
    const float* cbv = (const float*)d_in[10];
    const float* mem = (const float*)d_in[11];
    float* out = (float*)d_out;
    (void)in_sizes; (void)n_in; (void)out_size;

    cudaFuncSetAttribute(pl_mma_kernel, cudaFuncAttributeMaxDynamicSharedMemorySize, PL_SMEM);
    cudaFuncSetAttribute(out_tc_kernel, cudaFuncAttributeMaxDynamicSharedMemorySize, O_SMEM);

    // order chosen so wa_kernel is launch index 3 (ncu capture slot)
    mnh_kernel<<<NR / 256, 256>>>(mem);
    heads_kernel<<<NB, 64>>>(x, Wv, bv, Wb, bb, Wg, bg);
    sim_tc_kernel<<<dim3(NR / 128, NB / 128), 256>>>();
    wa_kernel<<<NB, 1024>>>(ck, cbv);
    xh_kernel<<<NB * ND / 4 / 256, 256>>>(x);
    wt_kernel<<<dim3(NR / 32, ND / 32), dim3(32, 8)>>>(Wp);
    pl_mma_kernel<<<dim3(NR / 128, NB / 128), 256, PL_SMEM>>>(bp);
    pcomb_kernel<<<NB, 128>>>();
    addm2_kernel<<<NR / 64, 128>>>(mem);
    out_tc_kernel<<<dim3(NSPLIT, NB / 128), 256, O_SMEM>>>();
    out_reduce<<<NB * NW / 256, 256>>>(out);
}

// round 15
// speedup vs baseline: 1.6708x; 1.0517x over previous
#include <cuda_runtime.h>
#include <cuda_bf16.h>
#include <cuda_fp16.h>
#include <math.h>
#include <cstdint>

#define NB 1024
#define ND 256
#define NR 16384
#define NW 64
#define NSPLIT 32
#define EPSF 1e-16f
#define ESCALE 2048.0f
#define EINV (1.0f / 2048.0f)

// ---------------- scratch (no allocations allowed) ----------------
__device__ __nv_bfloat16 g_simh[(size_t)NB * NR]; // sim logits (bf16), then a (in place)
__device__ __half g_plh[(size_t)NB * NR];         // p logits (fp16)
__device__ float g_gamma[NB];
__device__ float g_bvn[NB];                       // beta / ||v||
__device__ float g_imn[NR];                       // 1 / ||mem_r||
__device__ float g_part[(size_t)NSPLIT * NB * NW];
__device__ float g_pmx [NB];
__device__ float g_pinv[NB];
__device__ float g_psm[(size_t)NB * 128];         // per (row, n-tile) max
__device__ float g_pss[(size_t)NB * 128];         // per (row, n-tile) sumexp
__device__ __half g_xh[(size_t)NB * ND];          // x in fp16
__device__ __half g_wt[(size_t)NR * ND];          // Wp^T in fp16 [r][k]
__device__ __nv_bfloat16 g_vh  [NB * NW];
__device__ __nv_bfloat16 g_memh[NR * NW];
__device__ __half g_m2h[(size_t)NW * NR];         // mem2^T (fp16) [w][r]

__device__ __forceinline__ float softplus_f(float z) {
    return z > 0.f ? z + log1pf(expf(-z)) : log1pf(expf(z));
}
__device__ __forceinline__ uint32_t smem_u32(const void* p) {
    uint32_t a;
    asm("{ .reg .u64 t; cvta.to.shared.u64 t, %1; cvt.u32.u64 %0, t; }" : "=r"(a) : "l"(p));
    return a;
}
__device__ __forceinline__ void ldsm_x4(uint32_t& r0, uint32_t& r1, uint32_t& r2, uint32_t& r3,
                                        uint32_t addr) {
    asm volatile("ldmatrix.sync.aligned.m8n8.x4.shared.b16 {%0, %1, %2, %3}, [%4];"
                 : "=r"(r0), "=r"(r1), "=r"(r2), "=r"(r3) : "r"(addr));
}
__device__ __forceinline__ void ldsm_x4t(uint32_t& r0, uint32_t& r1, uint32_t& r2, uint32_t& r3,
                                         uint32_t addr) {
    asm volatile("ldmatrix.sync.aligned.m8n8.x4.trans.shared.b16 {%0, %1, %2, %3}, [%4];"
                 : "=r"(r0), "=r"(r1), "=r"(r2), "=r"(r3) : "r"(addr));
}
__device__ __forceinline__ void mma16816(float* d, const uint32_t* a, const uint32_t* b) {
    asm volatile(
        "mma.sync.aligned.m16n8k16.row.col.f32.bf16.bf16.f32 "
        "{%0, %1, %2, %3}, {%4, %5, %6, %7}, {%8, %9}, {%0, %1, %2, %3};"
        : "+f"(d[0]), "+f"(d[1]), "+f"(d[2]), "+f"(d[3])
        : "r"(a[0]), "r"(a[1]), "r"(a[2]), "r"(a[3]), "r"(b[0]), "r"(b[1]));
}
__device__ __forceinline__ void mma16816h(float* d, const uint32_t* a, const uint32_t* b) {
    asm volatile(
        "mma.sync.aligned.m16n8k16.row.col.f32.f16.f16.f32 "
        "{%0, %1, %2, %3}, {%4, %5, %6, %7}, {%8, %9}, {%0, %1, %2, %3};"
        : "+f"(d[0]), "+f"(d[1]), "+f"(d[2]), "+f"(d[3])
        : "r"(a[0]), "r"(a[1]), "r"(a[2]), "r"(a[3]), "r"(b[0]), "r"(b[1]));
}
__device__ __forceinline__ void cp_async16(uint32_t saddr, const void* g) {
    asm volatile("cp.async.cg.shared.global [%0], [%1], 16;" :: "r"(saddr), "l"(g));
}
#define CP_COMMIT() asm volatile("cp.async.commit_group;" ::: "memory")
#define CP_WAIT(n)  asm volatile("cp.async.wait_group %0;" :: "n"(n) : "memory")

// block sum for 1024 threads (32 warps)
__device__ __forceinline__ float blk_sum(float v, float* red) {
    int lane = threadIdx.x & 31, w = threadIdx.x >> 5;
    #pragma unroll
    for (int o = 16; o; o >>= 1) v += __shfl_xor_sync(0xffffffffu, v, o);
    if (!lane) red[w] = v;
    __syncthreads();
    if (w == 0) {
        v = red[lane];
        #pragma unroll
        for (int o = 16; o; o >>= 1) v += __shfl_xor_sync(0xffffffffu, v, o);
        if (!lane) red[0] = v;
    }
    __syncthreads();
    v = red[0];
    __syncthreads();
    return v;
}

// ---------------- K1: controller heads (+ fused x->fp16) ----------------
__global__ void heads_kernel(const float* __restrict__ x,
                             const float* __restrict__ Wv, const float* __restrict__ bv,
                             const float* __restrict__ Wb, const float* __restrict__ bb,
                             const float* __restrict__ Wg, const float* __restrict__ bg) {
    int b = blockIdx.x, t = threadIdx.x;        // 64 threads
    __shared__ float xs[ND];
    __shared__ float red[64];
    for (int i = t; i < ND; i += 64) xs[i] = x[b * ND + i];
    __syncthreads();

    // fused: x -> fp16
    #pragma unroll
    for (int i = 0; i < ND / 64; ++i)
        g_xh[(size_t)b * ND + t + i * 64] = __float2half(xs[t + i * 64]);

    float acc = 0.f;
    #pragma unroll 8
    for (int d = 0; d < ND; ++d) acc = fmaf(xs[d], Wv[d * NW + t], acc);
    float pb = 0.f, pg = 0.f;
    for (int d = t; d < ND; d += 64) {
        pb = fmaf(xs[d], Wb[d], pb);
        pg = fmaf(xs[d], Wg[d], pg);
    }
    float v = acc + bv[t];
    g_vh[b * NW + t] = __float2bfloat16(v);

    red[t] = v * v; __syncthreads();
    for (int s = 32; s > 0; s >>= 1) { if (t < s) red[t] += red[t + s]; __syncthreads(); }
    float vn = sqrtf(red[0]);
    __syncthreads();

    red[t] = pb; __syncthreads();
    for (int s = 32; s > 0; s >>= 1) { if (t < s) red[t] += red[t + s]; __syncthreads(); }
    if (t == 0) g_bvn[b] = softplus_f(red[0] + bb[0]) / (vn + EPSF);
    __syncthreads();

    red[t] = pg; __syncthreads();
    for (int s = 32; s > 0; s >>= 1) { if (t < s) red[t] += red[t + s]; __syncthreads(); }
    if (t == 0) g_gamma[b] = 1.f + softplus_f(red[0] + bg[0]);
}

// ---------------- K0: memory row inverse norms + bf16 convert (fused) --------
__global__ void mnh_kernel(const float* __restrict__ mem) {
    int r = blockIdx.x * blockDim.x + threadIdx.x;
    if (r >= NR) return;
    const float4* m4 = (const float4*)(mem + (size_t)r * NW);
    __nv_bfloat162* h2 = (__nv_bfloat162*)(g_memh + (size_t)r * NW);
    float s = 0.f;
    #pragma unroll
    for (int i = 0; i < NW / 4; ++i) {
        float4 t4 = m4[i];
        s += t4.x * t4.x + t4.y * t4.y + t4.z * t4.z + t4.w * t4.w;
        h2[i * 2]     = __float22bfloat162_rn(make_float2(t4.x, t4.y));
        h2[i * 2 + 1] = __float22bfloat162_rn(make_float2(t4.z, t4.w));
    }
    g_imn[r] = 1.f / (sqrtf(s) + EPSF);
}

// ---------------- K2: sim via HMMA bf16 (multiply-only epilogue) ----------------
#define SLS 72
__global__ void __launch_bounds__(256, 2)
sim_tc_kernel() {
    __shared__ __nv_bfloat16 As[128][SLS];
    __shared__ __nv_bfloat16 Bs[128][SLS];
    int tid = threadIdx.x;
    int lane = tid & 31, wid = tid >> 5;
    int n0 = blockIdx.x * 128;    // r
    int b0 = blockIdx.y * 128;    // b
    int wm0 = (wid & 1) * 64;
    int wn0 = (wid >> 1) * 32;

    #pragma unroll
    for (int i = 0; i < 4; ++i) {
        int q = tid + i * 256;
        int row = q >> 3, seg = (q & 7) * 8;
        *(uint4*)&As[row][seg] = *(const uint4*)&g_vh[(size_t)(b0 + row) * NW + seg];
        *(uint4*)&Bs[row][seg] = *(const uint4*)&g_memh[(size_t)(n0 + row) * NW + seg];
    }
    __syncthreads();

    float d[4][4][4] = {};
    uint32_t as_base = smem_u32(&As[0][0]);
    uint32_t bs_base = smem_u32(&Bs[0][0]);
    int a_row = wm0 + (lane & 15);
    int a_kof = (lane >> 4) * 8;
    int b_rof = ((lane >> 4) * 8) + (lane & 7);
    int b_kof = ((lane >> 3) & 1) * 8;

    #pragma unroll
    for (int ks = 0; ks < 4; ++ks) {
        int k0 = ks * 16;
        uint32_t a[4][4];
        #pragma unroll
        for (int mi = 0; mi < 4; ++mi) {
            uint32_t addr = as_base + ((a_row + mi * 16) * SLS + k0 + a_kof) * 2;
            ldsm_x4(a[mi][0], a[mi][1], a[mi][2], a[mi][3], addr);
        }
        uint32_t bfr[2][4];
        #pragma unroll
        for (int nj = 0; nj < 2; ++nj) {
            uint32_t addr = bs_base + ((wn0 + nj * 16 + b_rof) * SLS + k0 + b_kof) * 2;
            ldsm_x4(bfr[nj][0], bfr[nj][1], bfr[nj][2], bfr[nj][3], addr);
        }
        #pragma unroll
        for (int mi = 0; mi < 4; ++mi)
            #pragma unroll
            for (int ni = 0; ni < 4; ++ni)
                mma16816(d[mi][ni], a[mi], &bfr[ni >> 1][(ni & 1) * 2]);
    }

    int gr = lane >> 2, gc = (lane & 3) * 2;
    #pragma unroll
    for (int mi = 0; mi < 4; ++mi) {
        int bi0 = b0 + wm0 + mi * 16 + gr;
        float s0 = g_bvn[bi0];
        float s1 = g_bvn[bi0 + 8];
        #pragma unroll
        for (int ni = 0; ni < 4; ++ni) {
            int c = n0 + wn0 + ni * 8 + gc;
            float im0 = g_imn[c], im1 = g_imn[c + 1];
            *(__nv_bfloat162*)&g_simh[(size_t)bi0 * NR + c] =
                __float22bfloat162_rn(make_float2(
                    s0 * d[mi][ni][0] * im0, s0 * d[mi][ni][1] * im1));
            *(__nv_bfloat162*)&g_simh[(size_t)(bi0 + 8) * NR + c] =
                __float22bfloat162_rn(make_float2(
                    s1 * d[mi][ni][2] * im0, s1 * d[mi][ni][3] * im1));
        }
    }
}

// ---------------- K3: softmax -> conv -> pow -> renorm (rolling regs, no spills) ----
__global__ void __launch_bounds__(1024, 2)
wa_kernel(const float* __restrict__ conv_k, const float* __restrict__ conv_b) {
    __shared__ float eL[2][1024];
    __shared__ float eR[2][1024];
    __shared__ float red[32];
    int b = blockIdx.x, t = threadIdx.x;   // 1024 threads, 2x8 contiguous elems each
    __nv_bfloat16* row = g_simh + (size_t)b * NR;

    float e[16];
    float sum = 0.f;
    #pragma unroll
    for (int i = 0; i < 2; ++i) {
        uint4 raw = *(const uint4*)&row[i * 8192 + t * 8];
        const __nv_bfloat162* p2 = (const __nv_bfloat162*)&raw;
        #pragma unroll
        for (int k = 0; k < 4; ++k) {
            float2 f = __bfloat1622float2(p2[k]);
            float e0 = __expf(f.x);
            float e1 = __expf(f.y);
            e[i * 8 + 2 * k]     = e0;
            e[i * 8 + 2 * k + 1] = e1;
            sum += e0 + e1;
        }
    }
    eL[0][t] = e[0]; eR[0][t] = e[7];
    eL[1][t] = e[8]; eR[1][t] = e[15];
    sum = blk_sum(sum, red);   // contains __syncthreads -> edges visible
    float inv = 1.f / sum;

    float c0 = conv_k[0], c1 = conv_k[1], c2 = conv_k[2], cb = conv_b[0];
    float gam = g_gamma[b];
    float asum = 0.f;
    // rolling overwrite: e[idx] becomes the sharpened value after use
    #pragma unroll
    for (int i = 0; i < 2; ++i) {
        float prev;   // ORIGINAL value of e[idx-1]
        if (i == 0) prev = (t > 0) ? eR[0][t - 1] : 0.f;
        else        prev = (t > 0) ? eR[1][t - 1] : eR[0][1023];
        #pragma unroll
        for (int k = 0; k < 8; ++k) {
            int idx = i * 8 + k;
            float cur = e[idx];
            float wr;
            if (k < 7) wr = e[idx + 1];
            else if (i == 0) wr = (t < 1023) ? eL[0][t + 1] : eL[1][0];
            else             wr = (t < 1023) ? eL[1][t + 1] : 0.f;
            float wc = fmaf(prev, c0, fmaf(cur, c1, wr * c2)) * inv + cb;
            float a = __powf(wc, gam);
            e[idx] = a; asum += a;
            prev = cur;
        }
    }
    asum = blk_sum(asum, red);
    float invd = 1.f / (asum + (float)NR * EPSF);

    #pragma unroll
    for (int i = 0; i < 2; ++i) {
        uint4 raw;
        __nv_bfloat162* p2 = (__nv_bfloat162*)&raw;
        #pragma unroll
        for (int k = 0; k < 4; ++k)
            p2[k] = __float22bfloat162_rn(make_float2(
                e[i * 8 + 2 * k] * invd, e[i * 8 + 2 * k + 1] * invd));
        *(uint4*)&row[i * 8192 + t * 8] = raw;
    }
}

// ---------------- K4: add/erase HMMA + fused mem2 build (transposed fp16) ------
#define ATS 72
__global__ void __launch_bounds__(128, 4)
addm2_kernel(const float* __restrict__ mem) {
    __shared__ __align__(16) __nv_bfloat16 As[128][ATS];   // overlaid with fp32 tile later
    __shared__ __nv_bfloat16 Vs[128][ATS];
    int tid = threadIdx.x, lane = tid & 31, wid = tid >> 5;   // 4 warps
    int r0 = blockIdx.x * 64;
    float acc[8][4] = {};
    float acce[4] = {};
    uint32_t onesf[2] = {0x3F803F80u, 0x3F803F80u};
    uint32_t asb = smem_u32(&As[0][0]), vsb = smem_u32(&Vs[0][0]);
    int m0 = wid * 16;
    int lrow = (lane & 7) + ((lane & 16) >> 1);
    int lcol = lane & 8;

    for (int kb = 0; kb < NB; kb += 128) {
        #pragma unroll
        for (int i = 0; i < 8; ++i) {
            int q = tid + i * 128;
            int kk = q >> 3, c = (q & 7) * 8;
            *(uint4*)&As[kk][c] = *(const uint4*)&g_simh[(size_t)(kb + kk) * NR + r0 + c];
            *(uint4*)&Vs[kk][c] = *(const uint4*)&g_vh[(kb + kk) * NW + c];
        }
        __syncthreads();

        #pragma unroll
        for (int ks = 0; ks < 8; ++ks) {
            int k0 = ks * 16;
            uint32_t a[4];
            ldsm_x4t(a[0], a[1], a[2], a[3],
                     asb + ((k0 + lrow) * ATS + m0 + lcol) * 2);
            uint32_t bfr[4][4];
            #pragma unroll
            for (int nj = 0; nj < 4; ++nj)
                ldsm_x4t(bfr[nj][0], bfr[nj][1], bfr[nj][2], bfr[nj][3],
                         vsb + ((k0 + lrow) * ATS + nj * 16 + lcol) * 2);
            #pragma unroll
            for (int nj = 0; nj < 4; ++nj) {
                uint32_t f1[2] = {bfr[nj][0], bfr[nj][2]};
                uint32_t f2[2] = {bfr[nj][1], bfr[nj][3]};
                mma16816(acc[nj * 2],     a, f1);
                mma16816(acc[nj * 2 + 1], a, f2);
            }
            mma16816(acce, a, onesf);
        }
        __syncthreads();
    }

    // fused mem2: every lane holds the row-sums (erase) for its two rows
    const float invB = 1.f / (float)NB;
    float ev0 = 1.f - acce[0] * invB;   // row m0+gr
    float ev1 = 1.f - acce[2] * invB;   // row m0+gr+8
    int gr = lane >> 2, gc = (lane & 3) * 2;
    int rA = m0 + gr, rB = m0 + gr + 8;

    float (*tbuf)[65] = (float(*)[65])&As[0][0];   // 64x65 fp32 = 16.6KB < As region
    #pragma unroll
    for (int nj = 0; nj < 8; ++nj) {
        int w = nj * 8 + gc;
        float2 ma = *(const float2*)&mem[(size_t)(r0 + rA) * NW + w];
        float2 mb = *(const float2*)&mem[(size_t)(r0 + rB) * NW + w];
        tbuf[rA][w]     = ma.x * ev0 + acc[nj][0] * invB;
        tbuf[rA][w + 1] = ma.y * ev0 + acc[nj][1] * invB;
        tbuf[rB][w]     = mb.x * ev1 + acc[nj][2] * invB;
        tbuf[rB][w + 1] = mb.y * ev1 + acc[nj][3] * invB;
    }
    __syncthreads();

    #pragma unroll
    for (int i = 0; i < 32; ++i) {
        int q = tid + i * 128;          // 0..4095
        int w = q >> 6, r = q & 63;
        g_m2h[(size_t)w * NR + r0 + r] = __float2half(tbuf[r][w]);
    }
}

// ---------------- prep: Wp^T -> fp16 [r][k] ----------------
__global__ void wt_kernel(const float* __restrict__ Wp) {
    __shared__ float t[32][33];
    int n0 = blockIdx.x * 32, k0 = blockIdx.y * 32;
    int tx = threadIdx.x, ty = threadIdx.y;   // (32, 8)
    #pragma unroll
    for (int i = 0; i < 4; ++i)
        t[ty + 8 * i][tx] = Wp[(size_t)(k0 + ty + 8 * i) * NR + n0 + tx];
    __syncthreads();
    #pragma unroll
    for (int i = 0; i < 4; ++i) {
        int row = ty + 8 * i;
        g_wt[(size_t)(n0 + row) * ND + k0 + tx] = __float2half(t[tx][row]);
    }
}

// ---------------- K5: p logits (fp16 HMMA, K=256) + fused per-tile softmax stats -----
#define PLS 40
#define PLK (ND / 32)
#define PSTG 3
#define PL_BUF (128 * PLS)
#define PL_SMEM (2 * PSTG * PL_BUF * 2)

__global__ void __launch_bounds__(256, 2)
pl_mma_kernel(const float* __restrict__ bp) {
    extern __shared__ __half plsm[];
    __half* As = plsm;                    // [PSTG][128][PLS]
    __half* Bs = plsm + PSTG * PL_BUF;    // [PSTG][128][PLS]
    __shared__ float s_mx[128][2];
    __shared__ float s_sm[128][2];
    int tid = threadIdx.x;
    int lane = tid & 31, wid = tid >> 5;          // 8 warps
    int n0 = blockIdx.x * 128;
    int b0 = blockIdx.y * 128;
    int wm0 = (wid & 3) * 32;
    int wn0 = (wid >> 2) * 64;
    int half_id = wid >> 2;

    uint32_t asb = smem_u32(As), bsb = smem_u32(Bs);
    const uint32_t bufB = PL_BUF * 2;

    int row0 = tid >> 2, seg0 = (tid & 3) * 8;
    int row1 = (tid + 256) >> 2, seg1 = (tid & 3) * 8;

    uint32_t a_sa0 = asb + (row0 * PLS + seg0) * 2;
    uint32_t a_sa1 = asb + (row1 * PLS + seg1) * 2;
    uint32_t b_sa0 = bsb + (row0 * PLS + seg0) * 2;
    uint32_t b_sa1 = bsb + (row1 * PLS + seg1) * 2;
    const __half* a_g0 = &g_xh[(size_t)(b0 + row0) * ND + seg0];
    const __half* a_g1 = &g_xh[(size_t)(b0 + row1) * ND + seg1];
    const __half* b_g0 = &g_wt[(size_t)(n0 + row0) * ND + seg0];
    const __half* b_g1 = &g_wt[(size_t)(n0 + row1) * ND + seg1];

    #pragma unroll
    for (int s = 0; s < 2; ++s) {
        cp_async16(a_sa0 + s * bufB, a_g0 + s * 32);
        cp_async16(a_sa1 + s * bufB, a_g1 + s * 32);
        cp_async16(b_sa0 + s * bufB, b_g0 + s * 32);
        cp_async16(b_sa1 + s * bufB, b_g1 + s * 32);
        CP_COMMIT();
    }

    float acc[2][8][4] = {};
    int a_row = wm0 + (lane & 15);
    int a_kof = (lane >> 4) * 8;
    int b_rof = ((lane >> 4) * 8) + (lane & 7);
    int b_kof = ((lane >> 3) & 1) * 8;

    for (int kc = 0; kc < PLK; ++kc) {
        int cur = kc % PSTG;
        if (kc + 1 < PLK) CP_WAIT(1); else CP_WAIT(0);
        __syncthreads();

        if (kc + 2 < PLK) {
            int nxt = (kc + 2) % PSTG;
            int ko = (kc + 2) * 32;
            cp_async16(a_sa0 + nxt * bufB, a_g0 + ko);
            cp_async16(a_sa1 + nxt * bufB, a_g1 + ko);
            cp_async16(b_sa0 + nxt * bufB, b_g0 + ko);
            cp_async16(b_sa1 + nxt * bufB, b_g1 + ko);
            CP_COMMIT();
        }

        uint32_t abase = asb + cur * bufB;
        uint32_t bbase = bsb + cur * bufB;

        uint32_t a[2][2][4], bfr[2][4][4];
        #pragma unroll
        for (int mi = 0; mi < 2; ++mi)
            ldsm_x4(a[0][mi][0], a[0][mi][1], a[0][mi][2], a[0][mi][3],
                    abase + ((a_row + mi * 16) * PLS + a_kof) * 2);
        #pragma unroll
        for (int nj = 0; nj < 4; ++nj)
            ldsm_x4(bfr[0][nj][0], bfr[0][nj][1], bfr[0][nj][2], bfr[0][nj][3],
                    bbase + ((wn0 + nj * 16 + b_rof) * PLS + b_kof) * 2);

        #pragma unroll
        for (int ks = 0; ks < 2; ++ks) {
            int c = ks & 1, n = c ^ 1;
            if (ks + 1 < 2) {
                int k0 = (ks + 1) * 16;
                #pragma unroll
                for (int mi = 0; mi < 2; ++mi)
                    ldsm_x4(a[n][mi][0], a[n][mi][1], a[n][mi][2], a[n][mi][3],
                            abase + ((a_row + mi * 16) * PLS + k0 + a_kof) * 2);
                #pragma unroll
                for (int nj = 0; nj < 4; ++nj)
                    ldsm_x4(bfr[n][nj][0], bfr[n][nj][1], bfr[n][nj][2], bfr[n][nj][3],
                            bbase + ((wn0 + nj * 16 + b_rof) * PLS + k0 + b_kof) * 2);
            }
            #pragma unroll
            for (int mi = 0; mi < 2; ++mi)
                #pragma unroll
                for (int nj = 0; nj < 4; ++nj) {
                    mma16816h(acc[mi][nj * 2],     a[c][mi], &bfr[c][nj][0]);
                    mma16816h(acc[mi][nj * 2 + 1], a[c][mi], &bfr[c][nj][2]);
                }
        }
    }

    // epilogue: bias, fp16 logit store, per-tile softmax partials
    int gr = lane >> 2, gc = (lane & 3) * 2;
    float bpv[8][2];
    #pragma unroll
    for (int j = 0; j < 8; ++j) {
        int c = n0 + wn0 + j * 8 + gc;
        bpv[j][0] = bp[c]; bpv[j][1] = bp[c + 1];
    }
    #pragma unroll
    for (int mi = 0; mi < 2; ++mi) {
        int rl = wm0 + mi * 16 + gr;
        int r1 = b0 + rl;
        float m0 = -1e30f, m1 = -1e30f;
        #pragma unroll
        for (int j = 0; j < 8; ++j) {
            float v0 = acc[mi][j][0] + bpv[j][0];
            float v1 = acc[mi][j][1] + bpv[j][1];
            float v2 = acc[mi][j][2] + bpv[j][0];
            float v3 = acc[mi][j][3] + bpv[j][1];
            acc[mi][j][0] = v0; acc[mi][j][1] = v1;
            acc[mi][j][2] = v2; acc[mi][j][3] = v3;
            int c = n0 + wn0 + j * 8 + gc;
            *(__half2*)&g_plh[(size_t)r1 * NR + c]       = __floats2half2_rn(v0, v1);
            *(__half2*)&g_plh[(size_t)(r1 + 8) * NR + c] = __floats2half2_rn(v2, v3);
            m0 = fmaxf(m0, fmaxf(v0, v1));
            m1 = fmaxf(m1, fmaxf(v2, v3));
        }
        #pragma unroll
        for (int o = 1; o <= 2; o <<= 1) {
            m0 = fmaxf(m0, __shfl_xor_sync(0xffffffffu, m0, o));
            m1 = fmaxf(m1, __shfl_xor_sync(0xffffffffu, m1, o));
        }
        float s0 = 0.f, s1 = 0.f;
        #pragma unroll
        for (int j = 0; j < 8; ++j) {
            s0 += __expf(acc[mi][j][0] - m0) + __expf(acc[mi][j][1] - m0);
            s1 += __expf(acc[mi][j][2] - m1) + __expf(acc[mi][j][3] - m1);
        }
        #pragma unroll
        for (int o = 1; o <= 2; o <<= 1) {
            s0 += __shfl_xor_sync(0xffffffffu, s0, o);
            s1 += __shfl_xor_sync(0xffffffffu, s1, o);
        }
        if ((lane & 3) == 0) {
            s_mx[rl][half_id] = m0; s_sm[rl][half_id] = s0;
            s_mx[rl + 8][half_id] = m1; s_sm[rl + 8][half_id] = s1;
        }
    }
    __syncthreads();
    if (tid < 128) {
        float ma = s_mx[tid][0], mb = s_mx[tid][1];
        float M = fmaxf(ma, mb);
        float S = s_sm[tid][0] * __expf(ma - M) + s_sm[tid][1] * __expf(mb - M);
        g_psm[(size_t)(b0 + tid) * 128 + blockIdx.x] = M;
        g_pss[(size_t)(b0 + tid) * 128 + blockIdx.x] = S;
    }
}

// ---------------- K6: combine per-tile softmax partials ----------------
__global__ void pcomb_kernel() {
    __shared__ float rm[4], rs[4];
    int b = blockIdx.x, t = threadIdx.x;   // 128 threads
    int lane = t & 31, w = t >> 5;
    float M = g_psm[(size_t)b * 128 + t];
    float S = g_pss[(size_t)b * 128 + t];
    float m = M;
    #pragma unroll
    for (int o = 16; o; o >>= 1) m = fmaxf(m, __shfl_xor_sync(0xffffffffu, m, o));
    if (!lane) rm[w] = m;
    __syncthreads();
    float Mg = fmaxf(fmaxf(rm[0], rm[1]), fmaxf(rm[2], rm[3]));
    float s = S * __expf(M - Mg);
    #pragma unroll
    for (int o = 16; o; o >>= 1) s += __shfl_xor_sync(0xffffffffu, s, o);
    if (!lane) rs[w] = s;
    __syncthreads();
    if (t == 0) { g_pmx[b] = Mg; g_pinv[b] = 1.f / (rs[0] + rs[1] + rs[2] + rs[3]); }
}

// ---------------- K7: out = softmax(pl) @ mem2, scaled-fp16 e, fp16 m2 --------
#define OLS 72
#define O_E  0
#define O_MH (128 * OLS)
#define O_SMEM (192 * OLS * 2)

__global__ void __launch_bounds__(256, 2)
out_tc_kernel() {
    extern __shared__ __half osm[];
    __half* E  = osm + O_E;
    __half* MH = osm + O_MH;
    int tid = threadIdx.x;
    int lane = tid & 31, wid = tid >> 5;
    int split = blockIdx.x;
    int b0 = blockIdx.y * 128;
    int kbase = split * (NR / NSPLIT);

    int la = tid >> 4, lb = tid & 15;
    float mxv[8], invv[8];
    #pragma unroll
    for (int i = 0; i < 8; ++i) {
        mxv[i]  = g_pmx[b0 + la + 16 * i];
        invv[i] = g_pinv[b0 + la + 16 * i] * ESCALE;
    }
    int m_row0 = tid >> 3, m_seg0 = (tid & 7) * 8;
    int m_row1 = (tid + 256) >> 3, m_seg1 = (tid & 7) * 8;

    uint32_t eb = smem_u32(E);
    uint32_t mhb = smem_u32(MH);

    float acc[8][4] = {};
    int a_row = wid * 16 + (lane & 15);
    int a_kof = (lane >> 4) * 8;
    int b_rof = ((lane >> 4) * 8) + (lane & 7);
    int b_kof = ((lane >> 3) & 1) * 8;

    for (int kg = kbase; kg < kbase + NR / NSPLIT; kg += 64) {
        #pragma unroll
        for (int i = 0; i < 8; ++i) {
            int row = la + 16 * i;
            const __half2* lp = (const __half2*)&g_plh[(size_t)(b0 + row) * NR + kg + lb * 4];
            float2 f01 = __half22float2(lp[0]);
            float2 f23 = __half22float2(lp[1]);
            float e0 = __expf(f01.x - mxv[i]) * invv[i];
            float e1 = __expf(f01.y - mxv[i]) * invv[i];
            float e2 = __expf(f23.x - mxv[i]) * invv[i];
            float e3 = __expf(f23.y - mxv[i]) * invv[i];
            __half2* ep = (__half2*)&E[row * OLS + lb * 4];
            ep[0] = __floats2half2_rn(e0, e1);
            ep[1] = __floats2half2_rn(e2, e3);
        }
        *(uint4*)&MH[m_row0 * OLS + m_seg0] = *(const uint4*)&g_m2h[(size_t)m_row0 * NR + kg + m_seg0];
        *(uint4*)&MH[m_row1 * OLS + m_seg1] = *(const uint4*)&g_m2h[(size_t)m_row1 * NR + kg + m_seg1];
        __syncthreads();

        #pragma unroll
        for (int ks = 0; ks < 4; ++ks) {
            int k0 = ks * 16;
            uint32_t a[4];
            ldsm_x4(a[0], a[1], a[2], a[3], eb + (a_row * OLS + k0 + a_kof) * 2);
            uint32_t bh[4][4];
            #pragma unroll
            for (int g = 0; g < 4; ++g) {
                uint32_t addr = mhb + ((g * 16 + b_rof) * OLS + k0 + b_kof) * 2;
                ldsm_x4(bh[g][0], bh[g][1], bh[g][2], bh[g][3], addr);
            }
            #pragma unroll
            for (int g = 0; g < 4; ++g) {
                mma16816h(acc[g * 2],     a, &bh[g][0]);
                mma16816h(acc[g * 2 + 1], a, &bh[g][2]);
            }
        }
        __syncthreads();
    }

    int gr = lane >> 2, gc = (lane & 3) * 2;
    int r1 = b0 + wid * 16 + gr;
    #pragma unroll
    for (int j = 0; j < 8; ++j) {
        int c = j * 8 + gc;
        *(float2*)&g_part[(size_t)split * (NB * NW) + (size_t)r1 * NW + c] =
            make_float2(acc[j][0], acc[j][1]);
        *(float2*)&g_part[(size_t)split * (NB * NW) + (size_t)(r1 + 8) * NW + c] =
            make_float2(acc[j][2], acc[j][3]);
    }
}

__global__ void out_reduce(float* __restrict__ out) {
    int i = blockIdx.x * blockDim.x + threadIdx.x;
    float s = 0.f;
    #pragma unroll
    for (int p = 0; p < NSPLIT; ++p) s += g_part[(size_t)p * (NB * NW) + i];
    out[i] = s * EINV;
}

// ---------------- launch ----------------
extern "C" void kernel_launch(void* const* d_in, const int* in_sizes, int n_in,
                              void* d_out, int out_size) {
    const float* x   = (const float*)d_in[0];
    const float* Wv  = (const float*)d_in[1];
    const float* bv  = (const float*)d_in[2];
    const float* Wb  = (const float*)d_in[3];
    const float* bb  = (const float*)d_in[4];
    const float* Wg  = (const float*)d_in[5];
    const float* bg  = (const float*)d_in[6];
    const float* Wp  = (const float*)d_in[7];
    const float* bp  = (const float*)d_in[8];
    const float* ck  = (const float*)d_in[9];
    const float* cbv = (const float*)d_in[10];
    const float* mem = (const float*)d_in[11];
    float* out = (float*)d_out;
    (void)in_sizes; (void)n_in; (void)out_size;

    cudaFuncSetAttribute(pl_mma_kernel, cudaFuncAttributeMaxDynamicSharedMemorySize, PL_SMEM);
    cudaFuncSetAttribute(out_tc_kernel, cudaFuncAttributeMaxDynamicSharedMemorySize, O_SMEM);

    // order chosen so wa_kernel is launch index 3 (ncu capture slot)
    mnh_kernel<<<NR / 256, 256>>>(mem);
    heads_kernel<<<NB, 64>>>(x, Wv, bv, Wb, bb, Wg, bg);
    sim_tc_kernel<<<dim3(NR / 128, NB / 128), 256>>>();
    wa_kernel<<<NB, 1024>>>(ck, cbv);
    wt_kernel<<<dim3(NR / 32, ND / 32), dim3(32, 8)>>>(Wp);
    pl_mma_kernel<<<dim3(NR / 128, NB / 128), 256, PL_SMEM>>>(bp);
    pcomb_kernel<<<NB, 128>>>();
    addm2_kernel<<<NR / 64, 128>>>(mem);
    out_tc_kernel<<<dim3(NSPLIT, NB / 128), 256, O_SMEM>>>();
    out_reduce<<<NB * NW / 256, 256>>>(out);
}

// round 16
// speedup vs baseline: 1.7223x; 1.0308x over previous
#include <cuda_runtime.h>
#include <cuda_bf16.h>
#include <cuda_fp16.h>
#include <math.h>
#include <cstdint>

#define NB 1024
#define ND 256
#define NR 16384
#define NW 64
#define NSPLIT 32
#define EPSF 1e-16f

// ---------------- scratch (no allocations allowed) ----------------
__device__ __nv_bfloat16 g_simh[(size_t)NB * NR]; // sim logits (bf16), then a (in place)
__device__ __half g_plh[(size_t)NB * NR];         // exp(p logits) (fp16, unnormalized)
__device__ float g_gamma[NB];
__device__ float g_bvn[NB];                       // beta / ||v||
__device__ float g_imn[NR];                       // 1 / ||mem_r||
__device__ float g_part[(size_t)NSPLIT * NB * NW];
__device__ float g_pinv[NB];
__device__ float g_pss[(size_t)NB * 128];         // per (row, n-tile) sumexp
__device__ __half g_xh[(size_t)NB * ND];          // x in fp16
__device__ __half g_wt[(size_t)NR * ND];          // Wp^T in fp16 [r][k]
__device__ __nv_bfloat16 g_vh  [NB * NW];
__device__ __nv_bfloat16 g_memh[NR * NW];
__device__ __half g_m2h[(size_t)NW * NR];         // mem2^T (fp16) [w][r]

__device__ __forceinline__ float softplus_f(float z) {
    return z > 0.f ? z + log1pf(expf(-z)) : log1pf(expf(z));
}
__device__ __forceinline__ uint32_t smem_u32(const void* p) {
    uint32_t a;
    asm("{ .reg .u64 t; cvta.to.shared.u64 t, %1; cvt.u32.u64 %0, t; }" : "=r"(a) : "l"(p));
    return a;
}
__device__ __forceinline__ void ldsm_x4(uint32_t& r0, uint32_t& r1, uint32_t& r2, uint32_t& r3,
                                        uint32_t addr) {
    asm volatile("ldmatrix.sync.aligned.m8n8.x4.shared.b16 {%0, %1, %2, %3}, [%4];"
                 : "=r"(r0), "=r"(r1), "=r"(r2), "=r"(r3) : "r"(addr));
}
__device__ __forceinline__ void ldsm_x4t(uint32_t& r0, uint32_t& r1, uint32_t& r2, uint32_t& r3,
                                         uint32_t addr) {
    asm volatile("ldmatrix.sync.aligned.m8n8.x4.trans.shared.b16 {%0, %1, %2, %3}, [%4];"
                 : "=r"(r0), "=r"(r1), "=r"(r2), "=r"(r3) : "r"(addr));
}
__device__ __forceinline__ void mma16816(float* d, const uint32_t* a, const uint32_t* b) {
    asm volatile(
        "mma.sync.aligned.m16n8k16.row.col.f32.bf16.bf16.f32 "
        "{%0, %1, %2, %3}, {%4, %5, %6, %7}, {%8, %9}, {%0, %1, %2, %3};"
        : "+f"(d[0]), "+f"(d[1]), "+f"(d[2]), "+f"(d[3])
        : "r"(a[0]), "r"(a[1]), "r"(a[2]), "r"(a[3]), "r"(b[0]), "r"(b[1]));
}
__device__ __forceinline__ void mma16816h(float* d, const uint32_t* a, const uint32_t* b) {
    asm volatile(
        "mma.sync.aligned.m16n8k16.row.col.f32.f16.f16.f32 "
        "{%0, %1, %2, %3}, {%4, %5, %6, %7}, {%8, %9}, {%0, %1, %2, %3};"
        : "+f"(d[0]), "+f"(d[1]), "+f"(d[2]), "+f"(d[3])
        : "r"(a[0]), "r"(a[1]), "r"(a[2]), "r"(a[3]), "r"(b[0]), "r"(b[1]));
}
__device__ __forceinline__ void cp_async16(uint32_t saddr, const void* g) {
    asm volatile("cp.async.cg.shared.global [%0], [%1], 16;" :: "r"(saddr), "l"(g));
}
#define CP_COMMIT() asm volatile("cp.async.commit_group;" ::: "memory")
#define CP_WAIT(n)  asm volatile("cp.async.wait_group %0;" :: "n"(n) : "memory")

// block sum for 1024 threads (32 warps)
__device__ __forceinline__ float blk_sum(float v, float* red) {
    int lane = threadIdx.x & 31, w = threadIdx.x >> 5;
    #pragma unroll
    for (int o = 16; o; o >>= 1) v += __shfl_xor_sync(0xffffffffu, v, o);
    if (!lane) red[w] = v;
    __syncthreads();
    if (w == 0) {
        v = red[lane];
        #pragma unroll
        for (int o = 16; o; o >>= 1) v += __shfl_xor_sync(0xffffffffu, v, o);
        if (!lane) red[0] = v;
    }
    __syncthreads();
    v = red[0];
    __syncthreads();
    return v;
}

// ---------------- K1: controller heads (+ fused x->fp16) ----------------
__global__ void heads_kernel(const float* __restrict__ x,
                             const float* __restrict__ Wv, const float* __restrict__ bv,
                             const float* __restrict__ Wb, const float* __restrict__ bb,
                             const float* __restrict__ Wg, const float* __restrict__ bg) {
    int b = blockIdx.x, t = threadIdx.x;        // 64 threads
    __shared__ float xs[ND];
    __shared__ float red[64];
    for (int i = t; i < ND; i += 64) xs[i] = x[b * ND + i];
    __syncthreads();

    #pragma unroll
    for (int i = 0; i < ND / 64; ++i)
        g_xh[(size_t)b * ND + t + i * 64] = __float2half(xs[t + i * 64]);

    float acc = 0.f;
    #pragma unroll 8
    for (int d = 0; d < ND; ++d) acc = fmaf(xs[d], Wv[d * NW + t], acc);
    float pb = 0.f, pg = 0.f;
    for (int d = t; d < ND; d += 64) {
        pb = fmaf(xs[d], Wb[d], pb);
        pg = fmaf(xs[d], Wg[d], pg);
    }
    float v = acc + bv[t];
    g_vh[b * NW + t] = __float2bfloat16(v);

    red[t] = v * v; __syncthreads();
    for (int s = 32; s > 0; s >>= 1) { if (t < s) red[t] += red[t + s]; __syncthreads(); }
    float vn = sqrtf(red[0]);
    __syncthreads();

    red[t] = pb; __syncthreads();
    for (int s = 32; s > 0; s >>= 1) { if (t < s) red[t] += red[t + s]; __syncthreads(); }
    if (t == 0) g_bvn[b] = softplus_f(red[0] + bb[0]) / (vn + EPSF);
    __syncthreads();

    red[t] = pg; __syncthreads();
    for (int s = 32; s > 0; s >>= 1) { if (t < s) red[t] += red[t + s]; __syncthreads(); }
    if (t == 0) g_gamma[b] = 1.f + softplus_f(red[0] + bg[0]);
}

// ---------------- K0: memory row inverse norms + bf16 convert (fused) --------
__global__ void mnh_kernel(const float* __restrict__ mem) {
    int r = blockIdx.x * blockDim.x + threadIdx.x;
    if (r >= NR) return;
    const float4* m4 = (const float4*)(mem + (size_t)r * NW);
    __nv_bfloat162* h2 = (__nv_bfloat162*)(g_memh + (size_t)r * NW);
    float s = 0.f;
    #pragma unroll
    for (int i = 0; i < NW / 4; ++i) {
        float4 t4 = m4[i];
        s += t4.x * t4.x + t4.y * t4.y + t4.z * t4.z + t4.w * t4.w;
        h2[i * 2]     = __float22bfloat162_rn(make_float2(t4.x, t4.y));
        h2[i * 2 + 1] = __float22bfloat162_rn(make_float2(t4.z, t4.w));
    }
    g_imn[r] = 1.f / (sqrtf(s) + EPSF);
}

// ---------------- K2: sim via HMMA bf16 (multiply-only epilogue) ----------------
#define SLS 72
__global__ void __launch_bounds__(256, 2)
sim_tc_kernel() {
    __shared__ __nv_bfloat16 As[128][SLS];
    __shared__ __nv_bfloat16 Bs[128][SLS];
    int tid = threadIdx.x;
    int lane = tid & 31, wid = tid >> 5;
    int n0 = blockIdx.x * 128;    // r
    int b0 = blockIdx.y * 128;    // b
    int wm0 = (wid & 1) * 64;
    int wn0 = (wid >> 1) * 32;

    #pragma unroll
    for (int i = 0; i < 4; ++i) {
        int q = tid + i * 256;
        int row = q >> 3, seg = (q & 7) * 8;
        *(uint4*)&As[row][seg] = *(const uint4*)&g_vh[(size_t)(b0 + row) * NW + seg];
        *(uint4*)&Bs[row][seg] = *(const uint4*)&g_memh[(size_t)(n0 + row) * NW + seg];
    }
    __syncthreads();

    float d[4][4][4] = {};
    uint32_t as_base = smem_u32(&As[0][0]);
    uint32_t bs_base = smem_u32(&Bs[0][0]);
    int a_row = wm0 + (lane & 15);
    int a_kof = (lane >> 4) * 8;
    int b_rof = ((lane >> 4) * 8) + (lane & 7);
    int b_kof = ((lane >> 3) & 1) * 8;

    #pragma unroll
    for (int ks = 0; ks < 4; ++ks) {
        int k0 = ks * 16;
        uint32_t a[4][4];
        #pragma unroll
        for (int mi = 0; mi < 4; ++mi) {
            uint32_t addr = as_base + ((a_row + mi * 16) * SLS + k0 + a_kof) * 2;
            ldsm_x4(a[mi][0], a[mi][1], a[mi][2], a[mi][3], addr);
        }
        uint32_t bfr[2][4];
        #pragma unroll
        for (int nj = 0; nj < 2; ++nj) {
            uint32_t addr = bs_base + ((wn0 + nj * 16 + b_rof) * SLS + k0 + b_kof) * 2;
            ldsm_x4(bfr[nj][0], bfr[nj][1], bfr[nj][2], bfr[nj][3], addr);
        }
        #pragma unroll
        for (int mi = 0; mi < 4; ++mi)
            #pragma unroll
            for (int ni = 0; ni < 4; ++ni)
                mma16816(d[mi][ni], a[mi], &bfr[ni >> 1][(ni & 1) * 2]);
    }

    int gr = lane >> 2, gc = (lane & 3) * 2;
    #pragma unroll
    for (int mi = 0; mi < 4; ++mi) {
        int bi0 = b0 + wm0 + mi * 16 + gr;
        float s0 = g_bvn[bi0];
        float s1 = g_bvn[bi0 + 8];
        #pragma unroll
        for (int ni = 0; ni < 4; ++ni) {
            int c = n0 + wn0 + ni * 8 + gc;
            float im0 = g_imn[c], im1 = g_imn[c + 1];
            *(__nv_bfloat162*)&g_simh[(size_t)bi0 * NR + c] =
                __float22bfloat162_rn(make_float2(
                    s0 * d[mi][ni][0] * im0, s0 * d[mi][ni][1] * im1));
            *(__nv_bfloat162*)&g_simh[(size_t)(bi0 + 8) * NR + c] =
                __float22bfloat162_rn(make_float2(
                    s1 * d[mi][ni][2] * im0, s1 * d[mi][ni][3] * im1));
        }
    }
}

// ---------------- K3: softmax -> conv -> pow -> renorm (rolling regs) ----
__global__ void __launch_bounds__(1024, 2)
wa_kernel(const float* __restrict__ conv_k, const float* __restrict__ conv_b) {
    __shared__ float eL[2][1024];
    __shared__ float eR[2][1024];
    __shared__ float red[32];
    int b = blockIdx.x, t = threadIdx.x;   // 1024 threads, 2x8 contiguous elems each
    __nv_bfloat16* row = g_simh + (size_t)b * NR;

    float e[16];
    float sum = 0.f;
    #pragma unroll
    for (int i = 0; i < 2; ++i) {
        uint4 raw = *(const uint4*)&row[i * 8192 + t * 8];
        const __nv_bfloat162* p2 = (const __nv_bfloat162*)&raw;
        #pragma unroll
        for (int k = 0; k < 4; ++k) {
            float2 f = __bfloat1622float2(p2[k]);
            float e0 = __expf(f.x);
            float e1 = __expf(f.y);
            e[i * 8 + 2 * k]     = e0;
            e[i * 8 + 2 * k + 1] = e1;
            sum += e0 + e1;
        }
    }
    eL[0][t] = e[0]; eR[0][t] = e[7];
    eL[1][t] = e[8]; eR[1][t] = e[15];
    sum = blk_sum(sum, red);   // contains __syncthreads -> edges visible
    float inv = 1.f / sum;

    float c0 = conv_k[0], c1 = conv_k[1], c2 = conv_k[2], cb = conv_b[0];
    float gam = g_gamma[b];
    float asum = 0.f;
    #pragma unroll
    for (int i = 0; i < 2; ++i) {
        float prev;
        if (i == 0) prev = (t > 0) ? eR[0][t - 1] : 0.f;
        else        prev = (t > 0) ? eR[1][t - 1] : eR[0][1023];
        #pragma unroll
        for (int k = 0; k < 8; ++k) {
            int idx = i * 8 + k;
            float cur = e[idx];
            float wr;
            if (k < 7) wr = e[idx + 1];
            else if (i == 0) wr = (t < 1023) ? eL[0][t + 1] : eL[1][0];
            else             wr = (t < 1023) ? eL[1][t + 1] : 0.f;
            float wc = fmaf(prev, c0, fmaf(cur, c1, wr * c2)) * inv + cb;
            float a = __powf(wc, gam);
            e[idx] = a; asum += a;
            prev = cur;
        }
    }
    asum = blk_sum(asum, red);
    float invd = 1.f / (asum + (float)NR * EPSF);

    #pragma unroll
    for (int i = 0; i < 2; ++i) {
        uint4 raw;
        __nv_bfloat162* p2 = (__nv_bfloat162*)&raw;
        #pragma unroll
        for (int k = 0; k < 4; ++k)
            p2[k] = __float22bfloat162_rn(make_float2(
                e[i * 8 + 2 * k] * invd, e[i * 8 + 2 * k + 1] * invd));
        *(uint4*)&row[i * 8192 + t * 8] = raw;
    }
}

// ---------------- K4: add/erase HMMA + fused mem2 build (transposed fp16) ------
#define ATS 72
__global__ void __launch_bounds__(128, 4)
addm2_kernel(const float* __restrict__ mem) {
    __shared__ __align__(16) __nv_bfloat16 As[128][ATS];
    __shared__ __nv_bfloat16 Vs[128][ATS];
    int tid = threadIdx.x, lane = tid & 31, wid = tid >> 5;   // 4 warps
    int r0 = blockIdx.x * 64;
    float acc[8][4] = {};
    float acce[4] = {};
    uint32_t onesf[2] = {0x3F803F80u, 0x3F803F80u};
    uint32_t asb = smem_u32(&As[0][0]), vsb = smem_u32(&Vs[0][0]);
    int m0 = wid * 16;
    int lrow = (lane & 7) + ((lane & 16) >> 1);
    int lcol = lane & 8;

    for (int kb = 0; kb < NB; kb += 128) {
        #pragma unroll
        for (int i = 0; i < 8; ++i) {
            int q = tid + i * 128;
            int kk = q >> 3, c = (q & 7) * 8;
            *(uint4*)&As[kk][c] = *(const uint4*)&g_simh[(size_t)(kb + kk) * NR + r0 + c];
            *(uint4*)&Vs[kk][c] = *(const uint4*)&g_vh[(kb + kk) * NW + c];
        }
        __syncthreads();

        #pragma unroll
        for (int ks = 0; ks < 8; ++ks) {
            int k0 = ks * 16;
            uint32_t a[4];
            ldsm_x4t(a[0], a[1], a[2], a[3],
                     asb + ((k0 + lrow) * ATS + m0 + lcol) * 2);
            uint32_t bfr[4][4];
            #pragma unroll
            for (int nj = 0; nj < 4; ++nj)
                ldsm_x4t(bfr[nj][0], bfr[nj][1], bfr[nj][2], bfr[nj][3],
                         vsb + ((k0 + lrow) * ATS + nj * 16 + lcol) * 2);
            #pragma unroll
            for (int nj = 0; nj < 4; ++nj) {
                uint32_t f1[2] = {bfr[nj][0], bfr[nj][2]};
                uint32_t f2[2] = {bfr[nj][1], bfr[nj][3]};
                mma16816(acc[nj * 2],     a, f1);
                mma16816(acc[nj * 2 + 1], a, f2);
            }
            mma16816(acce, a, onesf);
        }
        __syncthreads();
    }

    const float invB = 1.f / (float)NB;
    float ev0 = 1.f - acce[0] * invB;
    float ev1 = 1.f - acce[2] * invB;
    int gr = lane >> 2, gc = (lane & 3) * 2;
    int rA = m0 + gr, rB = m0 + gr + 8;

    float (*tbuf)[65] = (float(*)[65])&As[0][0];
    #pragma unroll
    for (int nj = 0; nj < 8; ++nj) {
        int w = nj * 8 + gc;
        float2 ma = *(const float2*)&mem[(size_t)(r0 + rA) * NW + w];
        float2 mb = *(const float2*)&mem[(size_t)(r0 + rB) * NW + w];
        tbuf[rA][w]     = ma.x * ev0 + acc[nj][0] * invB;
        tbuf[rA][w + 1] = ma.y * ev0 + acc[nj][1] * invB;
        tbuf[rB][w]     = mb.x * ev1 + acc[nj][2] * invB;
        tbuf[rB][w + 1] = mb.y * ev1 + acc[nj][3] * invB;
    }
    __syncthreads();

    #pragma unroll
    for (int i = 0; i < 32; ++i) {
        int q = tid + i * 128;
        int w = q >> 6, r = q & 63;
        g_m2h[(size_t)w * NR + r0 + r] = __float2half(tbuf[r][w]);
    }
}

// ---------------- prep: Wp^T -> fp16 [r][k] ----------------
__global__ void wt_kernel(const float* __restrict__ Wp) {
    __shared__ float t[32][33];
    int n0 = blockIdx.x * 32, k0 = blockIdx.y * 32;
    int tx = threadIdx.x, ty = threadIdx.y;   // (32, 8)
    #pragma unroll
    for (int i = 0; i < 4; ++i)
        t[ty + 8 * i][tx] = Wp[(size_t)(k0 + ty + 8 * i) * NR + n0 + tx];
    __syncthreads();
    #pragma unroll
    for (int i = 0; i < 4; ++i) {
        int row = ty + 8 * i;
        g_wt[(size_t)(n0 + row) * ND + k0 + tx] = __float2half(t[tx][row]);
    }
}

// ---------------- K5: exp(p logits) (fp16 HMMA K=256) + per-tile sumexp --------------
#define PLS 40
#define PLK (ND / 32)
#define PSTG 3
#define PL_BUF (128 * PLS)
#define PL_SMEM (2 * PSTG * PL_BUF * 2)

__global__ void __launch_bounds__(256, 2)
pl_mma_kernel(const float* __restrict__ bp) {
    extern __shared__ __half plsm[];
    __half* As = plsm;                    // [PSTG][128][PLS]
    __half* Bs = plsm + PSTG * PL_BUF;    // [PSTG][128][PLS]
    __shared__ float s_sm[128][2];
    int tid = threadIdx.x;
    int lane = tid & 31, wid = tid >> 5;          // 8 warps
    int n0 = blockIdx.x * 128;
    int b0 = blockIdx.y * 128;
    int wm0 = (wid & 3) * 32;
    int wn0 = (wid >> 2) * 64;
    int half_id = wid >> 2;

    uint32_t asb = smem_u32(As), bsb = smem_u32(Bs);
    const uint32_t bufB = PL_BUF * 2;

    int row0 = tid >> 2, seg0 = (tid & 3) * 8;
    int row1 = (tid + 256) >> 2, seg1 = (tid & 3) * 8;

    uint32_t a_sa0 = asb + (row0 * PLS + seg0) * 2;
    uint32_t a_sa1 = asb + (row1 * PLS + seg1) * 2;
    uint32_t b_sa0 = bsb + (row0 * PLS + seg0) * 2;
    uint32_t b_sa1 = bsb + (row1 * PLS + seg1) * 2;
    const __half* a_g0 = &g_xh[(size_t)(b0 + row0) * ND + seg0];
    const __half* a_g1 = &g_xh[(size_t)(b0 + row1) * ND + seg1];
    const __half* b_g0 = &g_wt[(size_t)(n0 + row0) * ND + seg0];
    const __half* b_g1 = &g_wt[(size_t)(n0 + row1) * ND + seg1];

    #pragma unroll
    for (int s = 0; s < 2; ++s) {
        cp_async16(a_sa0 + s * bufB, a_g0 + s * 32);
        cp_async16(a_sa1 + s * bufB, a_g1 + s * 32);
        cp_async16(b_sa0 + s * bufB, b_g0 + s * 32);
        cp_async16(b_sa1 + s * bufB, b_g1 + s * 32);
        CP_COMMIT();
    }

    float acc[2][8][4] = {};
    int a_row = wm0 + (lane & 15);
    int a_kof = (lane >> 4) * 8;
    int b_rof = ((lane >> 4) * 8) + (lane & 7);
    int b_kof = ((lane >> 3) & 1) * 8;

    for (int kc = 0; kc < PLK; ++kc) {
        int cur = kc % PSTG;
        if (kc + 1 < PLK) CP_WAIT(1); else CP_WAIT(0);
        __syncthreads();

        if (kc + 2 < PLK) {
            int nxt = (kc + 2) % PSTG;
            int ko = (kc + 2) * 32;
            cp_async16(a_sa0 + nxt * bufB, a_g0 + ko);
            cp_async16(a_sa1 + nxt * bufB, a_g1 + ko);
            cp_async16(b_sa0 + nxt * bufB, b_g0 + ko);
            cp_async16(b_sa1 + nxt * bufB, b_g1 + ko);
            CP_COMMIT();
        }

        uint32_t abase = asb + cur * bufB;
        uint32_t bbase = bsb + cur * bufB;

        uint32_t a[2][2][4], bfr[2][4][4];
        #pragma unroll
        for (int mi = 0; mi < 2; ++mi)
            ldsm_x4(a[0][mi][0], a[0][mi][1], a[0][mi][2], a[0][mi][3],
                    abase + ((a_row + mi * 16) * PLS + a_kof) * 2);
        #pragma unroll
        for (int nj = 0; nj < 4; ++nj)
            ldsm_x4(bfr[0][nj][0], bfr[0][nj][1], bfr[0][nj][2], bfr[0][nj][3],
                    bbase + ((wn0 + nj * 16 + b_rof) * PLS + b_kof) * 2);

        #pragma unroll
        for (int ks = 0; ks < 2; ++ks) {
            int c = ks & 1, n = c ^ 1;
            if (ks + 1 < 2) {
                int k0 = (ks + 1) * 16;
                #pragma unroll
                for (int mi = 0; mi < 2; ++mi)
                    ldsm_x4(a[n][mi][0], a[n][mi][1], a[n][mi][2], a[n][mi][3],
                            abase + ((a_row + mi * 16) * PLS + k0 + a_kof) * 2);
                #pragma unroll
                for (int nj = 0; nj < 4; ++nj)
                    ldsm_x4(bfr[n][nj][0], bfr[n][nj][1], bfr[n][nj][2], bfr[n][nj][3],
                            bbase + ((wn0 + nj * 16 + b_rof) * PLS + k0 + b_kof) * 2);
            }
            #pragma unroll
            for (int mi = 0; mi < 2; ++mi)
                #pragma unroll
                for (int nj = 0; nj < 4; ++nj) {
                    mma16816h(acc[mi][nj * 2],     a[c][mi], &bfr[c][nj][0]);
                    mma16816h(acc[mi][nj * 2 + 1], a[c][mi], &bfr[c][nj][2]);
                }
        }
    }

    // epilogue: bias, exp, fp16 store, per-tile sumexp partials (no max needed)
    int gr = lane >> 2, gc = (lane & 3) * 2;
    float bpv[8][2];
    #pragma unroll
    for (int j = 0; j < 8; ++j) {
        int c = n0 + wn0 + j * 8 + gc;
        bpv[j][0] = bp[c]; bpv[j][1] = bp[c + 1];
    }
    #pragma unroll
    for (int mi = 0; mi < 2; ++mi) {
        int rl = wm0 + mi * 16 + gr;
        int r1 = b0 + rl;
        float s0 = 0.f, s1 = 0.f;
        #pragma unroll
        for (int j = 0; j < 8; ++j) {
            float e0 = __expf(acc[mi][j][0] + bpv[j][0]);
            float e1 = __expf(acc[mi][j][1] + bpv[j][1]);
            float e2 = __expf(acc[mi][j][2] + bpv[j][0]);
            float e3 = __expf(acc[mi][j][3] + bpv[j][1]);
            int c = n0 + wn0 + j * 8 + gc;
            *(__half2*)&g_plh[(size_t)r1 * NR + c]       = __floats2half2_rn(e0, e1);
            *(__half2*)&g_plh[(size_t)(r1 + 8) * NR + c] = __floats2half2_rn(e2, e3);
            s0 += e0 + e1;
            s1 += e2 + e3;
        }
        #pragma unroll
        for (int o = 1; o <= 2; o <<= 1) {
            s0 += __shfl_xor_sync(0xffffffffu, s0, o);
            s1 += __shfl_xor_sync(0xffffffffu, s1, o);
        }
        if ((lane & 3) == 0) {
            s_sm[rl][half_id] = s0;
            s_sm[rl + 8][half_id] = s1;
        }
    }
    __syncthreads();
    if (tid < 128)
        g_pss[(size_t)(b0 + tid) * 128 + blockIdx.x] = s_sm[tid][0] + s_sm[tid][1];
}

// ---------------- K6: combine per-tile sumexp partials ----------------
__global__ void pcomb_kernel() {
    __shared__ float rs[4];
    int b = blockIdx.x, t = threadIdx.x;   // 128 threads
    int lane = t & 31, w = t >> 5;
    float s = g_pss[(size_t)b * 128 + t];
    #pragma unroll
    for (int o = 16; o; o >>= 1) s += __shfl_xor_sync(0xffffffffu, s, o);
    if (!lane) rs[w] = s;
    __syncthreads();
    if (t == 0) g_pinv[b] = 1.f / (rs[0] + rs[1] + rs[2] + rs[3]);
}

// ---------------- K7: out = E @ m2 (E already exp-domain fp16, pure copy loader) ------
#define OLS 72
#define O_E  0
#define O_MH (128 * OLS)
#define O_SMEM (192 * OLS * 2)

__global__ void __launch_bounds__(256, 2)
out_tc_kernel() {
    extern __shared__ __half osm[];
    __half* E  = osm + O_E;
    __half* MH = osm + O_MH;
    int tid = threadIdx.x;
    int lane = tid & 31, wid = tid >> 5;
    int split = blockIdx.x;
    int b0 = blockIdx.y * 128;
    int kbase = split * (NR / NSPLIT);

    // cp.async slots: E 4/thread (128 rows x 4 segs), MH 2/thread (64 rows x 8 segs)
    int e_row = tid >> 1;                      // used with 2 slots of i
    uint32_t eb = smem_u32(E);
    uint32_t mhb = smem_u32(MH);
    int m_row0 = tid >> 3, m_seg0 = (tid & 7) * 8;
    int m_row1 = (tid + 256) >> 3, m_seg1 = (tid & 7) * 8;

    float acc[8][4] = {};
    int a_row = wid * 16 + (lane & 15);
    int a_kof = (lane >> 4) * 8;
    int b_rof = ((lane >> 4) * 8) + (lane & 7);
    int b_kof = ((lane >> 3) & 1) * 8;

    for (int kg = kbase; kg < kbase + NR / NSPLIT; kg += 64) {
        // E tile: 128 rows x 64 fp16 = 128B/row -> 2 slots per thread (2 segs each... 4 slots)
        #pragma unroll
        for (int i = 0; i < 2; ++i) {
            int q = tid + i * 256;             // 0..511
            int row = q >> 2, seg = (q & 3) * 16;   // seg in halfs (16 halfs = 32B? no)
            // 64 halfs per row = 4 slots of 16 halfs? 16B = 8 halfs -> 8 slots/row.
            // redo: 128 rows x 8 slots = 1024 slots, 4 per thread
            (void)row; (void)seg;
        }
        #pragma unroll
        for (int i = 0; i < 4; ++i) {
            int q = tid + i * 256;             // 0..1023
            int row = q >> 3, seg = (q & 7) * 8;
            cp_async16(eb + (row * OLS + seg) * 2,
                       &g_plh[(size_t)(b0 + row) * NR + kg + seg]);
        }
        cp_async16(mhb + (m_row0 * OLS + m_seg0) * 2,
                   &g_m2h[(size_t)m_row0 * NR + kg + m_seg0]);
        cp_async16(mhb + (m_row1 * OLS + m_seg1) * 2,
                   &g_m2h[(size_t)m_row1 * NR + kg + m_seg1]);
        CP_COMMIT();
        CP_WAIT(0);
        __syncthreads();

        #pragma unroll
        for (int ks = 0; ks < 4; ++ks) {
            int k0 = ks * 16;
            uint32_t a[4];
            ldsm_x4(a[0], a[1], a[2], a[3], eb + (a_row * OLS + k0 + a_kof) * 2);
            uint32_t bh[4][4];
            #pragma unroll
            for (int g = 0; g < 4; ++g) {
                uint32_t addr = mhb + ((g * 16 + b_rof) * OLS + k0 + b_kof) * 2;
                ldsm_x4(bh[g][0], bh[g][1], bh[g][2], bh[g][3], addr);
            }
            #pragma unroll
            for (int g = 0; g < 4; ++g) {
                mma16816h(acc[g * 2],     a, &bh[g][0]);
                mma16816h(acc[g * 2 + 1], a, &bh[g][2]);
            }
        }
        __syncthreads();
    }

    int gr = lane >> 2, gc = (lane & 3) * 2;
    int r1 = b0 + wid * 16 + gr;
    #pragma unroll
    for (int j = 0; j < 8; ++j) {
        int c = j * 8 + gc;
        *(float2*)&g_part[(size_t)split * (NB * NW) + (size_t)r1 * NW + c] =
            make_float2(acc[j][0], acc[j][1]);
        *(float2*)&g_part[(size_t)split * (NB * NW) + (size_t)(r1 + 8) * NW + c] =
            make_float2(acc[j][2], acc[j][3]);
    }
}

__global__ void out_reduce(float* __restrict__ out) {
    int i = blockIdx.x * blockDim.x + threadIdx.x;
    float s = 0.f;
    #pragma unroll
    for (int p = 0; p < NSPLIT; ++p) s += g_part[(size_t)p * (NB * NW) + i];
    out[i] = s * g_pinv[i >> 6];
}

// ---------------- launch ----------------
extern "C" void kernel_launch(void* const* d_in, const int* in_sizes, int n_in,
                              void* d_out, int out_size) {
    const float* x   = (const float*)d_in[0];
    const float* Wv  = (const float*)d_in[1];
    const float* bv  = (const float*)d_in[2];
    const float* Wb  = (const float*)d_in[3];
    const float* bb  = (const float*)d_in[4];
    const float* Wg  = (const float*)d_in[5];
    const float* bg  = (const float*)d_in[6];
    const float* Wp  = (const float*)d_in[7];
    const float* bp  = (const float*)d_in[8];
    const float* ck  = (const float*)d_in[9];
    const float* cbv = (const float*)d_in[10];
    const float* mem = (const float*)d_in[11];
    float* out = (float*)d_out;
    (void)in_sizes; (void)n_in; (void)out_size;

    cudaFuncSetAttribute(pl_mma_kernel, cudaFuncAttributeMaxDynamicSharedMemorySize, PL_SMEM);
    cudaFuncSetAttribute(out_tc_kernel, cudaFuncAttributeMaxDynamicSharedMemorySize, O_SMEM);

    // order chosen so wa_kernel is launch index 3 (ncu capture slot)
    mnh_kernel<<<NR / 256, 256>>>(mem);
    heads_kernel<<<NB, 64>>>(x, Wv, bv, Wb, bb, Wg, bg);
    sim_tc_kernel<<<dim3(NR / 128, NB / 128), 256>>>();
    wa_kernel<<<NB, 1024>>>(ck, cbv);
    wt_kernel<<<dim3(NR / 32, ND / 32), dim3(32, 8)>>>(Wp);
    pl_mma_kernel<<<dim3(NR / 128, NB / 128), 256, PL_SMEM>>>(bp);
    pcomb_kernel<<<NB, 128>>>();
    addm2_kernel<<<NR / 64, 128>>>(mem);
    out_tc_kernel<<<dim3(NSPLIT, NB / 128), 256, O_SMEM>>>();
    out_reduce<<<NB * NW / 256, 256>>>(out);
}

// round 17
// speedup vs baseline: 1.7940x; 1.0416x over previous
#include <cuda_runtime.h>
#include <cuda_bf16.h>
#include <cuda_fp16.h>
#include <math.h>
#include <cstdint>

#define NB 1024
#define ND 256
#define NR 16384
#define NW 64
#define NSPLIT 32
#define EPSF 1e-16f

// ---------------- scratch (no allocations allowed) ----------------
__device__ __nv_bfloat16 g_simh[(size_t)NB * NR]; // sim logits (bf16), then a (in place)
__device__ __half g_plh[(size_t)NB * NR];         // exp(p logits) (fp16, unnormalized)
__device__ float g_gamma[NB];
__device__ float g_bvn[NB];                       // beta / ||v||
__device__ float g_imn[NR];                       // 1 / ||mem_r||
__device__ float g_part[(size_t)NSPLIT * NB * NW];
__device__ float g_pinv[NB];
__device__ float g_pss[(size_t)NB * 128];         // per (row, n-tile) sumexp
__device__ __half g_xh[(size_t)NB * ND];          // x in fp16
__device__ __half g_wt[(size_t)NR * ND];          // Wp^T in fp16 [r][k]
__device__ __nv_bfloat16 g_vh  [NB * NW];
__device__ __nv_bfloat16 g_memh[NR * NW];
__device__ __half g_m2h[(size_t)NW * NR];         // mem2^T (fp16) [w][r]

__device__ __forceinline__ float softplus_f(float z) {
    return z > 0.f ? z + log1pf(expf(-z)) : log1pf(expf(z));
}
__device__ __forceinline__ uint32_t smem_u32(const void* p) {
    uint32_t a;
    asm("{ .reg .u64 t; cvta.to.shared.u64 t, %1; cvt.u32.u64 %0, t; }" : "=r"(a) : "l"(p));
    return a;
}
__device__ __forceinline__ void ldsm_x4(uint32_t& r0, uint32_t& r1, uint32_t& r2, uint32_t& r3,
                                        uint32_t addr) {
    asm volatile("ldmatrix.sync.aligned.m8n8.x4.shared.b16 {%0, %1, %2, %3}, [%4];"
                 : "=r"(r0), "=r"(r1), "=r"(r2), "=r"(r3) : "r"(addr));
}
__device__ __forceinline__ void ldsm_x4t(uint32_t& r0, uint32_t& r1, uint32_t& r2, uint32_t& r3,
                                         uint32_t addr) {
    asm volatile("ldmatrix.sync.aligned.m8n8.x4.trans.shared.b16 {%0, %1, %2, %3}, [%4];"
                 : "=r"(r0), "=r"(r1), "=r"(r2), "=r"(r3) : "r"(addr));
}
__device__ __forceinline__ void mma16816(float* d, const uint32_t* a, const uint32_t* b) {
    asm volatile(
        "mma.sync.aligned.m16n8k16.row.col.f32.bf16.bf16.f32 "
        "{%0, %1, %2, %3}, {%4, %5, %6, %7}, {%8, %9}, {%0, %1, %2, %3};"
        : "+f"(d[0]), "+f"(d[1]), "+f"(d[2]), "+f"(d[3])
        : "r"(a[0]), "r"(a[1]), "r"(a[2]), "r"(a[3]), "r"(b[0]), "r"(b[1]));
}
__device__ __forceinline__ void mma16816h(float* d, const uint32_t* a, const uint32_t* b) {
    asm volatile(
        "mma.sync.aligned.m16n8k16.row.col.f32.f16.f16.f32 "
        "{%0, %1, %2, %3}, {%4, %5, %6, %7}, {%8, %9}, {%0, %1, %2, %3};"
        : "+f"(d[0]), "+f"(d[1]), "+f"(d[2]), "+f"(d[3])
        : "r"(a[0]), "r"(a[1]), "r"(a[2]), "r"(a[3]), "r"(b[0]), "r"(b[1]));
}
__device__ __forceinline__ void cp_async16(uint32_t saddr, const void* g) {
    asm volatile("cp.async.cg.shared.global [%0], [%1], 16;" :: "r"(saddr), "l"(g));
}
#define CP_COMMIT() asm volatile("cp.async.commit_group;" ::: "memory")
#define CP_WAIT(n)  asm volatile("cp.async.wait_group %0;" :: "n"(n) : "memory")

// block sum for 1024 threads (32 warps)
__device__ __forceinline__ float blk_sum(float v, float* red) {
    int lane = threadIdx.x & 31, w = threadIdx.x >> 5;
    #pragma unroll
    for (int o = 16; o; o >>= 1) v += __shfl_xor_sync(0xffffffffu, v, o);
    if (!lane) red[w] = v;
    __syncthreads();
    if (w == 0) {
        v = red[lane];
        #pragma unroll
        for (int o = 16; o; o >>= 1) v += __shfl_xor_sync(0xffffffffu, v, o);
        if (!lane) red[0] = v;
    }
    __syncthreads();
    v = red[0];
    __syncthreads();
    return v;
}

// ---------------- K1: controller heads (+ fused x->fp16) ----------------
__global__ void heads_kernel(const float* __restrict__ x,
                             const float* __restrict__ Wv, const float* __restrict__ bv,
                             const float* __restrict__ Wb, const float* __restrict__ bb,
                             const float* __restrict__ Wg, const float* __restrict__ bg) {
    int b = blockIdx.x, t = threadIdx.x;        // 64 threads
    __shared__ float xs[ND];
    __shared__ float red[64];
    for (int i = t; i < ND; i += 64) xs[i] = x[b * ND + i];
    __syncthreads();

    #pragma unroll
    for (int i = 0; i < ND / 64; ++i)
        g_xh[(size_t)b * ND + t + i * 64] = __float2half(xs[t + i * 64]);

    float acc = 0.f;
    #pragma unroll 8
    for (int d = 0; d < ND; ++d) acc = fmaf(xs[d], Wv[d * NW + t], acc);
    float pb = 0.f, pg = 0.f;
    for (int d = t; d < ND; d += 64) {
        pb = fmaf(xs[d], Wb[d], pb);
        pg = fmaf(xs[d], Wg[d], pg);
    }
    float v = acc + bv[t];
    g_vh[b * NW + t] = __float2bfloat16(v);

    red[t] = v * v; __syncthreads();
    for (int s = 32; s > 0; s >>= 1) { if (t < s) red[t] += red[t + s]; __syncthreads(); }
    float vn = sqrtf(red[0]);
    __syncthreads();

    red[t] = pb; __syncthreads();
    for (int s = 32; s > 0; s >>= 1) { if (t < s) red[t] += red[t + s]; __syncthreads(); }
    if (t == 0) g_bvn[b] = softplus_f(red[0] + bb[0]) / (vn + EPSF);
    __syncthreads();

    red[t] = pg; __syncthreads();
    for (int s = 32; s > 0; s >>= 1) { if (t < s) red[t] += red[t + s]; __syncthreads(); }
    if (t == 0) g_gamma[b] = 1.f + softplus_f(red[0] + bg[0]);
}

// ---------------- K0: memory row inverse norms + bf16 convert (fused) --------
__global__ void mnh_kernel(const float* __restrict__ mem) {
    int r = blockIdx.x * blockDim.x + threadIdx.x;
    if (r >= NR) return;
    const float4* m4 = (const float4*)(mem + (size_t)r * NW);
    __nv_bfloat162* h2 = (__nv_bfloat162*)(g_memh + (size_t)r * NW);
    float s = 0.f;
    #pragma unroll
    for (int i = 0; i < NW / 4; ++i) {
        float4 t4 = m4[i];
        s += t4.x * t4.x + t4.y * t4.y + t4.z * t4.z + t4.w * t4.w;
        h2[i * 2]     = __float22bfloat162_rn(make_float2(t4.x, t4.y));
        h2[i * 2 + 1] = __float22bfloat162_rn(make_float2(t4.z, t4.w));
    }
    g_imn[r] = 1.f / (sqrtf(s) + EPSF);
}

// ---------------- K2: sim via HMMA bf16 (multiply-only epilogue) ----------------
#define SLS 72
__global__ void __launch_bounds__(256, 2)
sim_tc_kernel() {
    __shared__ __nv_bfloat16 As[128][SLS];
    __shared__ __nv_bfloat16 Bs[128][SLS];
    int tid = threadIdx.x;
    int lane = tid & 31, wid = tid >> 5;
    int n0 = blockIdx.x * 128;    // r
    int b0 = blockIdx.y * 128;    // b
    int wm0 = (wid & 1) * 64;
    int wn0 = (wid >> 1) * 32;

    #pragma unroll
    for (int i = 0; i < 4; ++i) {
        int q = tid + i * 256;
        int row = q >> 3, seg = (q & 7) * 8;
        *(uint4*)&As[row][seg] = *(const uint4*)&g_vh[(size_t)(b0 + row) * NW + seg];
        *(uint4*)&Bs[row][seg] = *(const uint4*)&g_memh[(size_t)(n0 + row) * NW + seg];
    }
    __syncthreads();

    float d[4][4][4] = {};
    uint32_t as_base = smem_u32(&As[0][0]);
    uint32_t bs_base = smem_u32(&Bs[0][0]);
    int a_row = wm0 + (lane & 15);
    int a_kof = (lane >> 4) * 8;
    int b_rof = ((lane >> 4) * 8) + (lane & 7);
    int b_kof = ((lane >> 3) & 1) * 8;

    #pragma unroll
    for (int ks = 0; ks < 4; ++ks) {
        int k0 = ks * 16;
        uint32_t a[4][4];
        #pragma unroll
        for (int mi = 0; mi < 4; ++mi) {
            uint32_t addr = as_base + ((a_row + mi * 16) * SLS + k0 + a_kof) * 2;
            ldsm_x4(a[mi][0], a[mi][1], a[mi][2], a[mi][3], addr);
        }
        uint32_t bfr[2][4];
        #pragma unroll
        for (int nj = 0; nj < 2; ++nj) {
            uint32_t addr = bs_base + ((wn0 + nj * 16 + b_rof) * SLS + k0 + b_kof) * 2;
            ldsm_x4(bfr[nj][0], bfr[nj][1], bfr[nj][2], bfr[nj][3], addr);
        }
        #pragma unroll
        for (int mi = 0; mi < 4; ++mi)
            #pragma unroll
            for (int ni = 0; ni < 4; ++ni)
                mma16816(d[mi][ni], a[mi], &bfr[ni >> 1][(ni & 1) * 2]);
    }

    int gr = lane >> 2, gc = (lane & 3) * 2;
    #pragma unroll
    for (int mi = 0; mi < 4; ++mi) {
        int bi0 = b0 + wm0 + mi * 16 + gr;
        float s0 = g_bvn[bi0];
        float s1 = g_bvn[bi0 + 8];
        #pragma unroll
        for (int ni = 0; ni < 4; ++ni) {
            int c = n0 + wn0 + ni * 8 + gc;
            float im0 = g_imn[c], im1 = g_imn[c + 1];
            *(__nv_bfloat162*)&g_simh[(size_t)bi0 * NR + c] =
                __float22bfloat162_rn(make_float2(
                    s0 * d[mi][ni][0] * im0, s0 * d[mi][ni][1] * im1));
            *(__nv_bfloat162*)&g_simh[(size_t)(bi0 + 8) * NR + c] =
                __float22bfloat162_rn(make_float2(
                    s1 * d[mi][ni][2] * im0, s1 * d[mi][ni][3] * im1));
        }
    }
}

// ---------------- K3: softmax -> conv -> pow -> renorm (rolling regs) ----
__global__ void __launch_bounds__(1024, 2)
wa_kernel(const float* __restrict__ conv_k, const float* __restrict__ conv_b) {
    __shared__ float eL[2][1024];
    __shared__ float eR[2][1024];
    __shared__ float red[32];
    int b = blockIdx.x, t = threadIdx.x;   // 1024 threads, 2x8 contiguous elems each
    __nv_bfloat16* row = g_simh + (size_t)b * NR;

    float e[16];
    float sum = 0.f;
    #pragma unroll
    for (int i = 0; i < 2; ++i) {
        uint4 raw = *(const uint4*)&row[i * 8192 + t * 8];
        const __nv_bfloat162* p2 = (const __nv_bfloat162*)&raw;
        #pragma unroll
        for (int k = 0; k < 4; ++k) {
            float2 f = __bfloat1622float2(p2[k]);
            float e0 = __expf(f.x);
            float e1 = __expf(f.y);
            e[i * 8 + 2 * k]     = e0;
            e[i * 8 + 2 * k + 1] = e1;
            sum += e0 + e1;
        }
    }
    eL[0][t] = e[0]; eR[0][t] = e[7];
    eL[1][t] = e[8]; eR[1][t] = e[15];
    sum = blk_sum(sum, red);   // contains __syncthreads -> edges visible
    float inv = 1.f / sum;

    float c0 = conv_k[0], c1 = conv_k[1], c2 = conv_k[2], cb = conv_b[0];
    float gam = g_gamma[b];
    float asum = 0.f;
    #pragma unroll
    for (int i = 0; i < 2; ++i) {
        float prev;
        if (i == 0) prev = (t > 0) ? eR[0][t - 1] : 0.f;
        else        prev = (t > 0) ? eR[1][t - 1] : eR[0][1023];
        #pragma unroll
        for (int k = 0; k < 8; ++k) {
            int idx = i * 8 + k;
            float cur = e[idx];
            float wr;
            if (k < 7) wr = e[idx + 1];
            else if (i == 0) wr = (t < 1023) ? eL[0][t + 1] : eL[1][0];
            else             wr = (t < 1023) ? eL[1][t + 1] : 0.f;
            float wc = fmaf(prev, c0, fmaf(cur, c1, wr * c2)) * inv + cb;
            float a = __powf(wc, gam);
            e[idx] = a; asum += a;
            prev = cur;
        }
    }
    asum = blk_sum(asum, red);
    float invd = 1.f / (asum + (float)NR * EPSF);

    #pragma unroll
    for (int i = 0; i < 2; ++i) {
        uint4 raw;
        __nv_bfloat162* p2 = (__nv_bfloat162*)&raw;
        #pragma unroll
        for (int k = 0; k < 4; ++k)
            p2[k] = __float22bfloat162_rn(make_float2(
                e[i * 8 + 2 * k] * invd, e[i * 8 + 2 * k + 1] * invd));
        *(uint4*)&row[i * 8192 + t * 8] = raw;
    }
}

// ---------------- K4: add/erase HMMA + fused mem2 build, 2-stage cp.async ------
#define ATS 72
#define AM2_MAT (128 * ATS)                  // elements per matrix per stage
#define AM2_SMEM (2 * 2 * AM2_MAT * 2)       // 2 stages x (As+Vs) x 2B

__global__ void __launch_bounds__(128, 3)
addm2_kernel(const float* __restrict__ mem) {
    extern __shared__ __nv_bfloat16 amsm[];
    int tid = threadIdx.x, lane = tid & 31, wid = tid >> 5;   // 4 warps
    int r0 = blockIdx.x * 64;
    float acc[8][4] = {};
    float acce[4] = {};
    uint32_t onesf[2] = {0x3F803F80u, 0x3F803F80u};
    uint32_t base = smem_u32(amsm);
    const uint32_t stageB = 2 * AM2_MAT * 2;           // bytes per stage
    int m0 = wid * 16;
    int lrow = (lane & 7) + ((lane & 16) >> 1);
    int lcol = lane & 8;

    // per-thread load slots: 8 (row, seg) pairs
    int lkk[8], lc[8];
    #pragma unroll
    for (int i = 0; i < 8; ++i) { int q = tid + i * 128; lkk[i] = q >> 3; lc[i] = (q & 7) * 8; }

    // prologue: chunk 0 -> stage 0
    #pragma unroll
    for (int i = 0; i < 8; ++i) {
        cp_async16(base + (lkk[i] * ATS + lc[i]) * 2,
                   &g_simh[(size_t)lkk[i] * NR + r0 + lc[i]]);
        cp_async16(base + AM2_MAT * 2 + (lkk[i] * ATS + lc[i]) * 2,
                   &g_vh[lkk[i] * NW + lc[i]]);
    }
    CP_COMMIT();

    for (int kc = 0; kc < NB / 128; ++kc) {
        if (kc + 1 < NB / 128) {
            uint32_t nb = base + ((kc + 1) & 1) * stageB;
            int kb = (kc + 1) * 128;
            #pragma unroll
            for (int i = 0; i < 8; ++i) {
                cp_async16(nb + (lkk[i] * ATS + lc[i]) * 2,
                           &g_simh[(size_t)(kb + lkk[i]) * NR + r0 + lc[i]]);
                cp_async16(nb + AM2_MAT * 2 + (lkk[i] * ATS + lc[i]) * 2,
                           &g_vh[(kb + lkk[i]) * NW + lc[i]]);
            }
            CP_COMMIT();
            CP_WAIT(1);
        } else {
            CP_WAIT(0);
        }
        __syncthreads();

        uint32_t asb = base + (kc & 1) * stageB;
        uint32_t vsb = asb + AM2_MAT * 2;
        #pragma unroll
        for (int ks = 0; ks < 8; ++ks) {
            int k0 = ks * 16;
            uint32_t a[4];
            ldsm_x4t(a[0], a[1], a[2], a[3],
                     asb + ((k0 + lrow) * ATS + m0 + lcol) * 2);
            uint32_t bfr[4][4];
            #pragma unroll
            for (int nj = 0; nj < 4; ++nj)
                ldsm_x4t(bfr[nj][0], bfr[nj][1], bfr[nj][2], bfr[nj][3],
                         vsb + ((k0 + lrow) * ATS + nj * 16 + lcol) * 2);
            #pragma unroll
            for (int nj = 0; nj < 4; ++nj) {
                uint32_t f1[2] = {bfr[nj][0], bfr[nj][2]};
                uint32_t f2[2] = {bfr[nj][1], bfr[nj][3]};
                mma16816(acc[nj * 2],     a, f1);
                mma16816(acc[nj * 2 + 1], a, f2);
            }
            mma16816(acce, a, onesf);
        }
        __syncthreads();
    }

    const float invB = 1.f / (float)NB;
    float ev0 = 1.f - acce[0] * invB;
    float ev1 = 1.f - acce[2] * invB;
    int gr = lane >> 2, gc = (lane & 3) * 2;
    int rA = m0 + gr, rB = m0 + gr + 8;

    float (*tbuf)[65] = (float(*)[65])amsm;   // 64x65 fp32 = 16.6KB < stage0 As region
    #pragma unroll
    for (int nj = 0; nj < 8; ++nj) {
        int w = nj * 8 + gc;
        float2 ma = *(const float2*)&mem[(size_t)(r0 + rA) * NW + w];
        float2 mb = *(const float2*)&mem[(size_t)(r0 + rB) * NW + w];
        tbuf[rA][w]     = ma.x * ev0 + acc[nj][0] * invB;
        tbuf[rA][w + 1] = ma.y * ev0 + acc[nj][1] * invB;
        tbuf[rB][w]     = mb.x * ev1 + acc[nj][2] * invB;
        tbuf[rB][w + 1] = mb.y * ev1 + acc[nj][3] * invB;
    }
    __syncthreads();

    #pragma unroll
    for (int i = 0; i < 32; ++i) {
        int q = tid + i * 128;
        int w = q >> 6, r = q & 63;
        g_m2h[(size_t)w * NR + r0 + r] = __float2half(tbuf[r][w]);
    }
}

// ---------------- prep: Wp^T -> fp16 [r][k] ----------------
__global__ void wt_kernel(const float* __restrict__ Wp) {
    __shared__ float t[32][33];
    int n0 = blockIdx.x * 32, k0 = blockIdx.y * 32;
    int tx = threadIdx.x, ty = threadIdx.y;   // (32, 8)
    #pragma unroll
    for (int i = 0; i < 4; ++i)
        t[ty + 8 * i][tx] = Wp[(size_t)(k0 + ty + 8 * i) * NR + n0 + tx];
    __syncthreads();
    #pragma unroll
    for (int i = 0; i < 4; ++i) {
        int row = ty + 8 * i;
        g_wt[(size_t)(n0 + row) * ND + k0 + tx] = __float2half(t[tx][row]);
    }
}

// ---------------- K5: exp(p logits) (fp16 HMMA K=256) + per-tile sumexp --------------
#define PLS 40
#define PLK (ND / 32)
#define PSTG 3
#define PL_BUF (128 * PLS)
#define PL_SMEM (2 * PSTG * PL_BUF * 2)

__global__ void __launch_bounds__(256, 2)
pl_mma_kernel(const float* __restrict__ bp) {
    extern __shared__ __half plsm[];
    __half* As = plsm;                    // [PSTG][128][PLS]
    __half* Bs = plsm + PSTG * PL_BUF;    // [PSTG][128][PLS]
    __shared__ float s_sm[128][2];
    int tid = threadIdx.x;
    int lane = tid & 31, wid = tid >> 5;          // 8 warps
    int n0 = blockIdx.x * 128;
    int b0 = blockIdx.y * 128;
    int wm0 = (wid & 3) * 32;
    int wn0 = (wid >> 2) * 64;
    int half_id = wid >> 2;

    uint32_t asb = smem_u32(As), bsb = smem_u32(Bs);
    const uint32_t bufB = PL_BUF * 2;

    int row0 = tid >> 2, seg0 = (tid & 3) * 8;
    int row1 = (tid + 256) >> 2, seg1 = (tid & 3) * 8;

    uint32_t a_sa0 = asb + (row0 * PLS + seg0) * 2;
    uint32_t a_sa1 = asb + (row1 * PLS + seg1) * 2;
    uint32_t b_sa0 = bsb + (row0 * PLS + seg0) * 2;
    uint32_t b_sa1 = bsb + (row1 * PLS + seg1) * 2;
    const __half* a_g0 = &g_xh[(size_t)(b0 + row0) * ND + seg0];
    const __half* a_g1 = &g_xh[(size_t)(b0 + row1) * ND + seg1];
    const __half* b_g0 = &g_wt[(size_t)(n0 + row0) * ND + seg0];
    const __half* b_g1 = &g_wt[(size_t)(n0 + row1) * ND + seg1];

    #pragma unroll
    for (int s = 0; s < 2; ++s) {
        cp_async16(a_sa0 + s * bufB, a_g0 + s * 32);
        cp_async16(a_sa1 + s * bufB, a_g1 + s * 32);
        cp_async16(b_sa0 + s * bufB, b_g0 + s * 32);
        cp_async16(b_sa1 + s * bufB, b_g1 + s * 32);
        CP_COMMIT();
    }

    float acc[2][8][4] = {};
    int a_row = wm0 + (lane & 15);
    int a_kof = (lane >> 4) * 8;
    int b_rof = ((lane >> 4) * 8) + (lane & 7);
    int b_kof = ((lane >> 3) & 1) * 8;

    for (int kc = 0; kc < PLK; ++kc) {
        int cur = kc % PSTG;
        if (kc + 1 < PLK) CP_WAIT(1); else CP_WAIT(0);
        __syncthreads();

        if (kc + 2 < PLK) {
            int nxt = (kc + 2) % PSTG;
            int ko = (kc + 2) * 32;
            cp_async16(a_sa0 + nxt * bufB, a_g0 + ko);
            cp_async16(a_sa1 + nxt * bufB, a_g1 + ko);
            cp_async16(b_sa0 + nxt * bufB, b_g0 + ko);
            cp_async16(b_sa1 + nxt * bufB, b_g1 + ko);
            CP_COMMIT();
        }

        uint32_t abase = asb + cur * bufB;
        uint32_t bbase = bsb + cur * bufB;

        uint32_t a[2][2][4], bfr[2][4][4];
        #pragma unroll
        for (int mi = 0; mi < 2; ++mi)
            ldsm_x4(a[0][mi][0], a[0][mi][1], a[0][mi][2], a[0][mi][3],
                    abase + ((a_row + mi * 16) * PLS + a_kof) * 2);
        #pragma unroll
        for (int nj = 0; nj < 4; ++nj)
            ldsm_x4(bfr[0][nj][0], bfr[0][nj][1], bfr[0][nj][2], bfr[0][nj][3],
                    bbase + ((wn0 + nj * 16 + b_rof) * PLS + b_kof) * 2);

        #pragma unroll
        for (int ks = 0; ks < 2; ++ks) {
            int c = ks & 1, n = c ^ 1;
            if (ks + 1 < 2) {
                int k0 = (ks + 1) * 16;
                #pragma unroll
                for (int mi = 0; mi < 2; ++mi)
                    ldsm_x4(a[n][mi][0], a[n][mi][1], a[n][mi][2], a[n][mi][3],
                            abase + ((a_row + mi * 16) * PLS + k0 + a_kof) * 2);
                #pragma unroll
                for (int nj = 0; nj < 4; ++nj)
                    ldsm_x4(bfr[n][nj][0], bfr[n][nj][1], bfr[n][nj][2], bfr[n][nj][3],
                            bbase + ((wn0 + nj * 16 + b_rof) * PLS + k0 + b_kof) * 2);
            }
            #pragma unroll
            for (int mi = 0; mi < 2; ++mi)
                #pragma unroll
                for (int nj = 0; nj < 4; ++nj) {
                    mma16816h(acc[mi][nj * 2],     a[c][mi], &bfr[c][nj][0]);
                    mma16816h(acc[mi][nj * 2 + 1], a[c][mi], &bfr[c][nj][2]);
                }
        }
    }

    // epilogue: bias, exp, fp16 store, per-tile sumexp partials
    int gr = lane >> 2, gc = (lane & 3) * 2;
    float bpv[8][2];
    #pragma unroll
    for (int j = 0; j < 8; ++j) {
        int c = n0 + wn0 + j * 8 + gc;
        bpv[j][0] = bp[c]; bpv[j][1] = bp[c + 1];
    }
    #pragma unroll
    for (int mi = 0; mi < 2; ++mi) {
        int rl = wm0 + mi * 16 + gr;
        int r1 = b0 + rl;
        float s0 = 0.f, s1 = 0.f;
        #pragma unroll
        for (int j = 0; j < 8; ++j) {
            float e0 = __expf(acc[mi][j][0] + bpv[j][0]);
            float e1 = __expf(acc[mi][j][1] + bpv[j][1]);
            float e2 = __expf(acc[mi][j][2] + bpv[j][0]);
            float e3 = __expf(acc[mi][j][3] + bpv[j][1]);
            int c = n0 + wn0 + j * 8 + gc;
            *(__half2*)&g_plh[(size_t)r1 * NR + c]       = __floats2half2_rn(e0, e1);
            *(__half2*)&g_plh[(size_t)(r1 + 8) * NR + c] = __floats2half2_rn(e2, e3);
            s0 += e0 + e1;
            s1 += e2 + e3;
        }
        #pragma unroll
        for (int o = 1; o <= 2; o <<= 1) {
            s0 += __shfl_xor_sync(0xffffffffu, s0, o);
            s1 += __shfl_xor_sync(0xffffffffu, s1, o);
        }
        if ((lane & 3) == 0) {
            s_sm[rl][half_id] = s0;
            s_sm[rl + 8][half_id] = s1;
        }
    }
    __syncthreads();
    if (tid < 128)
        g_pss[(size_t)(b0 + tid) * 128 + blockIdx.x] = s_sm[tid][0] + s_sm[tid][1];
}

// ---------------- K6: combine per-tile sumexp partials ----------------
__global__ void pcomb_kernel() {
    __shared__ float rs[4];
    int b = blockIdx.x, t = threadIdx.x;   // 128 threads
    int lane = t & 31, w = t >> 5;
    float s = g_pss[(size_t)b * 128 + t];
    #pragma unroll
    for (int o = 16; o; o >>= 1) s += __shfl_xor_sync(0xffffffffu, s, o);
    if (!lane) rs[w] = s;
    __syncthreads();
    if (t == 0) g_pinv[b] = 1.f / (rs[0] + rs[1] + rs[2] + rs[3]);
}

// ---------------- K7: out = E @ m2, 2-stage cp.async pipeline ----------------
#define OLS 72
#define O_E  0
#define O_MH (128 * OLS)
#define O_STAGE (192 * OLS)                 // elements per stage
#define O_SMEM (2 * O_STAGE * 2)            // bytes

__global__ void __launch_bounds__(256, 2)
out_tc_kernel() {
    extern __shared__ __half osm[];
    int tid = threadIdx.x;
    int lane = tid & 31, wid = tid >> 5;
    int split = blockIdx.x;
    int b0 = blockIdx.y * 128;
    int kbase = split * (NR / NSPLIT);

    uint32_t base = smem_u32(osm);
    const uint32_t stageB = O_STAGE * 2;

    // load slots: E 4/thread (128 rows x 8 segs), MH 2/thread (64 rows x 8 segs)
    int e_row[4], e_seg[4];
    #pragma unroll
    for (int i = 0; i < 4; ++i) { int q = tid + i * 256; e_row[i] = q >> 3; e_seg[i] = (q & 7) * 8; }
    int m_row0 = tid >> 3, m_seg0 = (tid & 7) * 8;
    int m_row1 = (tid + 256) >> 3, m_seg1 = (tid & 7) * 8;

    // prologue: chunk 0 -> stage 0
    #pragma unroll
    for (int i = 0; i < 4; ++i)
        cp_async16(base + (e_row[i] * OLS + e_seg[i]) * 2,
                   &g_plh[(size_t)(b0 + e_row[i]) * NR + kbase + e_seg[i]]);
    cp_async16(base + (O_MH + m_row0 * OLS + m_seg0) * 2,
               &g_m2h[(size_t)m_row0 * NR + kbase + m_seg0]);
    cp_async16(base + (O_MH + m_row1 * OLS + m_seg1) * 2,
               &g_m2h[(size_t)m_row1 * NR + kbase + m_seg1]);
    CP_COMMIT();

    float acc[8][4] = {};
    int a_row = wid * 16 + (lane & 15);
    int a_kof = (lane >> 4) * 8;
    int b_rof = ((lane >> 4) * 8) + (lane & 7);
    int b_kof = ((lane >> 3) & 1) * 8;
    const int NCH = NR / NSPLIT / 64;       // 8 chunks

    for (int kc = 0; kc < NCH; ++kc) {
        if (kc + 1 < NCH) {
            int kg = kbase + (kc + 1) * 64;
            uint32_t nb = base + ((kc + 1) & 1) * stageB;
            #pragma unroll
            for (int i = 0; i < 4; ++i)
                cp_async16(nb + (e_row[i] * OLS + e_seg[i]) * 2,
                           &g_plh[(size_t)(b0 + e_row[i]) * NR + kg + e_seg[i]]);
            cp_async16(nb + (O_MH + m_row0 * OLS + m_seg0) * 2,
                       &g_m2h[(size_t)m_row0 * NR + kg + m_seg0]);
            cp_async16(nb + (O_MH + m_row1 * OLS + m_seg1) * 2,
                       &g_m2h[(size_t)m_row1 * NR + kg + m_seg1]);
            CP_COMMIT();
            CP_WAIT(1);
        } else {
            CP_WAIT(0);
        }
        __syncthreads();

        uint32_t eb = base + (kc & 1) * stageB;
        uint32_t mhb = eb + O_MH * 2;
        #pragma unroll
        for (int ks = 0; ks < 4; ++ks) {
            int k0 = ks * 16;
            uint32_t a[4];
            ldsm_x4(a[0], a[1], a[2], a[3], eb + (a_row * OLS + k0 + a_kof) * 2);
            uint32_t bh[4][4];
            #pragma unroll
            for (int g = 0; g < 4; ++g) {
                uint32_t addr = mhb + ((g * 16 + b_rof) * OLS + k0 + b_kof) * 2;
                ldsm_x4(bh[g][0], bh[g][1], bh[g][2], bh[g][3], addr);
            }
            #pragma unroll
            for (int g = 0; g < 4; ++g) {
                mma16816h(acc[g * 2],     a, &bh[g][0]);
                mma16816h(acc[g * 2 + 1], a, &bh[g][2]);
            }
        }
        __syncthreads();
    }

    int gr = lane >> 2, gc = (lane & 3) * 2;
    int r1 = b0 + wid * 16 + gr;
    #pragma unroll
    for (int j = 0; j < 8; ++j) {
        int c = j * 8 + gc;
        *(float2*)&g_part[(size_t)split * (NB * NW) + (size_t)r1 * NW + c] =
            make_float2(acc[j][0], acc[j][1]);
        *(float2*)&g_part[(size_t)split * (NB * NW) + (size_t)(r1 + 8) * NW + c] =
            make_float2(acc[j][2], acc[j][3]);
    }
}

__global__ void out_reduce(float* __restrict__ out) {
    int i = blockIdx.x * blockDim.x + threadIdx.x;
    float s = 0.f;
    #pragma unroll
    for (int p = 0; p < NSPLIT; ++p) s += g_part[(size_t)p * (NB * NW) + i];
    out[i] = s * g_pinv[i >> 6];
}

// ---------------- launch ----------------
extern "C" void kernel_launch(void* const* d_in, const int* in_sizes, int n_in,
                              void* d_out, int out_size) {
    const float* x   = (const float*)d_in[0];
    const float* Wv  = (const float*)d_in[1];
    const float* bv  = (const float*)d_in[2];
    const float* Wb  = (const float*)d_in[3];
    const float* bb  = (const float*)d_in[4];
    const float* Wg  = (const float*)d_in[5];
    const float* bg  = (const float*)d_in[6];
    const float* Wp  = (const float*)d_in[7];
    const float* bp  = (const float*)d_in[8];
    const float* ck  = (const float*)d_in[9];
    const float* cbv = (const float*)d_in[10];
    const float* mem = (const float*)d_in[11];
    float* out = (float*)d_out;
    (void)in_sizes; (void)n_in; (void)out_size;

    cudaFuncSetAttribute(pl_mma_kernel, cudaFuncAttributeMaxDynamicSharedMemorySize, PL_SMEM);
    cudaFuncSetAttribute(out_tc_kernel, cudaFuncAttributeMaxDynamicSharedMemorySize, O_SMEM);
    cudaFuncSetAttribute(addm2_kernel, cudaFuncAttributeMaxDynamicSharedMemorySize, AM2_SMEM);

    // order chosen so pl_mma_kernel is launch index 3 (ncu capture slot)
    wt_kernel<<<dim3(NR / 32, ND / 32), dim3(32, 8)>>>(Wp);
    mnh_kernel<<<NR / 256, 256>>>(mem);
    heads_kernel<<<NB, 64>>>(x, Wv, bv, Wb, bb, Wg, bg);
    pl_mma_kernel<<<dim3(NR / 128, NB / 128), 256, PL_SMEM>>>(bp);
    sim_tc_kernel<<<dim3(NR / 128, NB / 128), 256>>>();
    wa_kernel<<<NB, 1024>>>(ck, cbv);
    pcomb_kernel<<<NB, 128>>>();
    addm2_kernel<<<NR / 64, 128, AM2_SMEM>>>(mem);
    out_tc_kernel<<<dim3(NSPLIT, NB / 128), 256, O_SMEM>>>();
    out_reduce<<<NB * NW / 256, 256>>>(out);
}